// round 1
// baseline (speedup 1.0000x reference)
#include <cuda_runtime.h>
#include <math.h>

// Problem constants
#define B_   8
#define C_   256
#define H_   56
#define W_   56
#define HW_  3136        // 56*56
#define KHW_ 784         // 28*28
#define HEADS_ 8
#define DK_  32
#define DV_  32
#define HD_  256         // HEADS*DK
#define NTOT_ 6422528    // B*C*HW
#define EPS_ 1e-5

// Scratch (static device arrays — allocation-free)
__device__ float g_q[B_ * HW_ * HD_];     // [b][i][hd]
__device__ float g_k[B_ * KHW_ * HD_];    // [b][j][hd]
__device__ float g_v[B_ * KHW_ * HD_];
__device__ float g_ck[B_ * C_ * KHW_];    // conv-K out [b][c][j]
__device__ float g_cv[B_ * C_ * KHW_];
__device__ float g_res[B_ * HW_ * HD_];   // attention output [b][i][hd]
__device__ float g_part[2048];            // 1024 sums + 1024 sumsq
__device__ float g_stats[2];              // mu, rstd
__device__ float g_cq[256];               // folded Q bias

// ---------------------------------------------------------------------------
// Stage 1: partial sums for global layernorm stats
// ---------------------------------------------------------------------------
__global__ void stats_partial(const float* __restrict__ x) {
    int tid = threadIdx.x;
    int gid = blockIdx.x * 256 + tid;
    const float4* x4 = (const float4*)x;
    float s = 0.f, ss = 0.f;
    for (int i = gid; i < NTOT_ / 4; i += 1024 * 256) {
        float4 v = x4[i];
        s  += v.x + v.y + v.z + v.w;
        ss += v.x * v.x + v.y * v.y + v.z * v.z + v.w * v.w;
    }
    #pragma unroll
    for (int o = 16; o; o >>= 1) {
        s  += __shfl_xor_sync(0xffffffffu, s, o);
        ss += __shfl_xor_sync(0xffffffffu, ss, o);
    }
    __shared__ float sh[16];
    int w = tid >> 5, lane = tid & 31;
    if (lane == 0) { sh[w] = s; sh[8 + w] = ss; }
    __syncthreads();
    if (tid == 0) {
        float a = 0.f, b = 0.f;
        #pragma unroll
        for (int i = 0; i < 8; i++) { a += sh[i]; b += sh[8 + i]; }
        g_part[blockIdx.x] = a;
        g_part[1024 + blockIdx.x] = b;
    }
}

// ---------------------------------------------------------------------------
// Stage 2: finalize mu/rstd, and fold LN into Q bias:
//   cq[n] = bq[n] - rstd*mu*sum_k Wq[n,k]
// ---------------------------------------------------------------------------
__global__ void stats_final(const float* __restrict__ Wq, const float* __restrict__ bq) {
    int tid = threadIdx.x;
    double s = 0.0, ss = 0.0;
    for (int i = tid; i < 1024; i += 256) {
        s  += (double)g_part[i];
        ss += (double)g_part[1024 + i];
    }
    __shared__ double shs[256], shss[256];
    shs[tid] = s; shss[tid] = ss;
    __syncthreads();
    for (int o = 128; o; o >>= 1) {
        if (tid < o) { shs[tid] += shs[tid + o]; shss[tid] += shss[tid + o]; }
        __syncthreads();
    }
    __shared__ float mu_s, rstd_s;
    if (tid == 0) {
        double N = (double)NTOT_;
        double mu = shs[0] / N;
        double var = shss[0] / N - mu * mu;
        float rstd = (float)(1.0 / sqrt(var + EPS_));
        g_stats[0] = (float)mu;
        g_stats[1] = rstd;
        mu_s = (float)mu; rstd_s = rstd;
    }
    __syncthreads();
    float rs = 0.f;
    const float* wrow = Wq + (size_t)tid * 256;
    for (int k = 0; k < 256; k++) rs += wrow[k];
    g_cq[tid] = bq[tid] - rstd_s * mu_s * rs;
}

// ---------------------------------------------------------------------------
// Depthwise 3x3 stride-2 conv (K and V paths fused, x read once)
// out layout [b][c][j] (transposed-A layout for the projection GEMM)
// ---------------------------------------------------------------------------
__global__ void dwconv_kernel(const float* __restrict__ x,
                              const float* __restrict__ wk, const float* __restrict__ bkd,
                              const float* __restrict__ wv, const float* __restrict__ bvd) {
    int idx = blockIdx.x * blockDim.x + threadIdx.x;
    if (idx >= B_ * C_ * KHW_) return;
    int ox = idx % 28;
    int oy = (idx / 28) % 28;
    int c  = (idx / KHW_) % C_;
    int b  = idx / (KHW_ * C_);
    const float* xp = x + ((size_t)(b * C_ + c)) * HW_;
    float ak = 0.f, av = 0.f;
    #pragma unroll
    for (int ky = 0; ky < 3; ky++) {
        int iy = oy * 2 + ky - 1;
        if (iy < 0 || iy >= H_) continue;
        #pragma unroll
        for (int kx = 0; kx < 3; kx++) {
            int ix = ox * 2 + kx - 1;
            if (ix < 0 || ix >= W_) continue;
            float xv = xp[iy * W_ + ix];
            ak += xv * wk[c * 9 + ky * 3 + kx];
            av += xv * wv[c * 9 + ky * 3 + kx];
        }
    }
    g_ck[idx] = ak + bkd[c];
    g_cv[idx] = av + bvd[c];
}

// ---------------------------------------------------------------------------
// GEMM (transposed A): out[b][i][n] = alpha * sum_k A[b][k][i]*Wt[n][k] + cvec[n]
// A layout [b][256][M]. Used for Q (alpha=rstd), K, V projections.
// BM=BN=64, BK=16, 256 threads, 4x4 micro-tile.
// ---------------------------------------------------------------------------
#define PADL 68
__global__ void gemm_T_kernel(const float* __restrict__ A,
                              const float* __restrict__ Wt,
                              const float* __restrict__ cvec,
                              int useAlpha, int M,
                              float* __restrict__ out) {
    __shared__ float As[16][PADL];
    __shared__ float Bs[16][PADL];
    int b  = blockIdx.z;
    int i0 = blockIdx.x * 64;
    int n0 = blockIdx.y * 64;
    const float* Ab = A + (size_t)b * 256 * M;
    float alpha = useAlpha ? g_stats[1] : 1.0f;
    int tid = threadIdx.x;
    int tx = tid & 15, ty = tid >> 4;
    float acc[4][4] = {};

    for (int k0 = 0; k0 < 256; k0 += 16) {
        {
            int i   = tid & 63;
            int kk0 = tid >> 6;
            #pragma unroll
            for (int r = 0; r < 4; r++) {
                int kk = kk0 + r * 4;
                int gi = i0 + i;
                As[kk][i] = (gi < M) ? Ab[(size_t)(k0 + kk) * M + gi] : 0.f;
            }
        }
        {
            int kk = tid & 15;
            int n  = tid >> 4;
            #pragma unroll
            for (int r = 0; r < 4; r++)
                Bs[kk][n + r * 16] = Wt[(size_t)(n0 + n + r * 16) * 256 + k0 + kk];
        }
        __syncthreads();
        #pragma unroll
        for (int k = 0; k < 16; k++) {
            float av[4], bv[4];
            #pragma unroll
            for (int m = 0; m < 4; m++) av[m] = As[k][ty * 4 + m];
            #pragma unroll
            for (int n = 0; n < 4; n++) bv[n] = Bs[k][tx * 4 + n];
            #pragma unroll
            for (int m = 0; m < 4; m++)
                #pragma unroll
                for (int n = 0; n < 4; n++) acc[m][n] += av[m] * bv[n];
        }
        __syncthreads();
    }
    #pragma unroll
    for (int m = 0; m < 4; m++) {
        int gi = i0 + ty * 4 + m;
        if (gi >= M) continue;
        float* orow = out + ((size_t)b * M + gi) * 256 + n0 + tx * 4;
        #pragma unroll
        for (int n = 0; n < 4; n++)
            orow[n] = alpha * acc[m][n] + cvec[n0 + tx * 4 + n];
    }
}

// ---------------------------------------------------------------------------
// O projection GEMM (row-major A = g_res) with fused flat residual add:
//   out.flat[b, i*256+n] = res[b,i,:]@Wo[n,:] + bo[n] + x.flat[b, i*256+n]
// ---------------------------------------------------------------------------
__global__ void gemm_O_kernel(const float* __restrict__ A,
                              const float* __restrict__ Wt,
                              const float* __restrict__ bo,
                              const float* __restrict__ x,
                              float* __restrict__ out) {
    __shared__ float As[16][PADL];
    __shared__ float Bs[16][PADL];
    int b  = blockIdx.z;
    int i0 = blockIdx.x * 64;
    int n0 = blockIdx.y * 64;
    int tid = threadIdx.x;
    int tx = tid & 15, ty = tid >> 4;
    float acc[4][4] = {};

    for (int k0 = 0; k0 < 256; k0 += 16) {
        {
            int i  = tid >> 4;
            int kk = tid & 15;
            #pragma unroll
            for (int r = 0; r < 4; r++)
                As[kk][i + r * 16] =
                    A[((size_t)(b * HW_) + i0 + i + r * 16) * 256 + k0 + kk];
        }
        {
            int kk = tid & 15;
            int n  = tid >> 4;
            #pragma unroll
            for (int r = 0; r < 4; r++)
                Bs[kk][n + r * 16] = Wt[(size_t)(n0 + n + r * 16) * 256 + k0 + kk];
        }
        __syncthreads();
        #pragma unroll
        for (int k = 0; k < 16; k++) {
            float av[4], bv[4];
            #pragma unroll
            for (int m = 0; m < 4; m++) av[m] = As[k][ty * 4 + m];
            #pragma unroll
            for (int n = 0; n < 4; n++) bv[n] = Bs[k][tx * 4 + n];
            #pragma unroll
            for (int m = 0; m < 4; m++)
                #pragma unroll
                for (int n = 0; n < 4; n++) acc[m][n] += av[m] * bv[n];
        }
        __syncthreads();
    }
    #pragma unroll
    for (int m = 0; m < 4; m++) {
        int gi = i0 + ty * 4 + m;
        size_t flat = (size_t)b * (C_ * HW_) + (size_t)gi * 256 + n0 + tx * 4;
        #pragma unroll
        for (int n = 0; n < 4; n++)
            out[flat + n] = acc[m][n] + bo[n0 + tx * 4 + n] + x[flat + n];
    }
}

// ---------------------------------------------------------------------------
// Fused attention: one block per (b, h, 64 q-rows).
// K^T,V^T (fp32) in smem [32][785] (pad 785 -> conflict-free), q in smem.
// Each warp processes 8 q rows (2 at a time to amortize K/V smem reads).
// Scores in registers (25 slots/lane over j), softmax in-warp, PV via
// per-d warp reductions. No global attn matrix.
// ---------------------------------------------------------------------------
#define KVP 785
#define ATT_SMEM ((2 * 32 * KVP + 64 * 32) * 4)

__global__ void attn_kernel(const float* __restrict__ qb,
                            const float* __restrict__ kb,
                            const float* __restrict__ vb,
                            const float* __restrict__ bias,
                            float* __restrict__ res) {
    extern __shared__ float sm[];
    float* Ksm = sm;                  // [32][KVP]
    float* Vsm = sm + 32 * KVP;       // [32][KVP]
    float* qsm = sm + 64 * KVP;       // [64][32]

    int b = blockIdx.z, h = blockIdx.y;
    int i0 = blockIdx.x * 64;
    int tid = threadIdx.x, lane = tid & 31, w = tid >> 5;

    for (int idx = tid; idx < KHW_ * 32; idx += 256) {
        int j = idx >> 5, d = idx & 31;
        size_t g = ((size_t)(b * KHW_ + j)) * 256 + h * 32 + d;
        Ksm[d * KVP + j] = kb[g];
        Vsm[d * KVP + j] = vb[g];
    }
    for (int idx = tid; idx < 64 * 32; idx += 256) {
        int r = idx >> 5, d = idx & 31;
        qsm[idx] = qb[((size_t)(b * HW_ + i0 + r)) * 256 + h * 32 + d];
    }
    __syncthreads();

    const float scale = 0.17677669529663687f;  // 1/sqrt(32)

    #pragma unroll 1
    for (int t = 0; t < 4; t++) {
        int r0 = w * 8 + t * 2, r1 = r0 + 1;
        int gi0 = i0 + r0, gi1 = i0 + r1;

        float q0[32], q1[32];
        #pragma unroll
        for (int d = 0; d < 32; d++) {
            q0[d] = qsm[r0 * 32 + d];
            q1[d] = qsm[r1 * 32 + d];
        }
        const float* bias0 = bias + ((size_t)h * HW_ + gi0) * KHW_;
        const float* bias1 = bias + ((size_t)h * HW_ + gi1) * KHW_;

        float s0[25], s1[25];
        float m0 = -1e30f, m1 = -1e30f;
        #pragma unroll
        for (int s = 0; s < 25; s++) {
            int j = s * 32 + lane;
            bool valid = (j < KHW_);
            int jc = valid ? j : (KHW_ - 1);
            float a0 = 0.f, a1 = 0.f, c0 = 0.f, c1 = 0.f;
            #pragma unroll
            for (int d = 0; d < 32; d += 2) {
                float kv0 = Ksm[d * KVP + jc];
                float kv1 = Ksm[(d + 1) * KVP + jc];
                a0 += q0[d] * kv0; c0 += q0[d + 1] * kv1;
                a1 += q1[d] * kv0; c1 += q1[d + 1] * kv1;
            }
            float sc0 = valid ? ((a0 + c0) * scale + bias0[jc]) : -1e30f;
            float sc1 = valid ? ((a1 + c1) * scale + bias1[jc]) : -1e30f;
            s0[s] = sc0; s1[s] = sc1;
            m0 = fmaxf(m0, sc0); m1 = fmaxf(m1, sc1);
        }
        #pragma unroll
        for (int o = 16; o; o >>= 1) {
            m0 = fmaxf(m0, __shfl_xor_sync(0xffffffffu, m0, o));
            m1 = fmaxf(m1, __shfl_xor_sync(0xffffffffu, m1, o));
        }
        float sum0 = 0.f, sum1 = 0.f;
        #pragma unroll
        for (int s = 0; s < 25; s++) {
            float p0 = __expf(s0[s] - m0);
            float p1 = __expf(s1[s] - m1);
            s0[s] = p0; s1[s] = p1;
            sum0 += p0; sum1 += p1;
        }
        #pragma unroll
        for (int o = 16; o; o >>= 1) {
            sum0 += __shfl_xor_sync(0xffffffffu, sum0, o);
            sum1 += __shfl_xor_sync(0xffffffffu, sum1, o);
        }
        float inv0 = 1.f / sum0, inv1 = 1.f / sum1;

        float o0 = 0.f, o1 = 0.f;
        #pragma unroll 1
        for (int d = 0; d < 32; d++) {
            float pa0 = 0.f, pa1 = 0.f, pb0 = 0.f, pb1 = 0.f;
            #pragma unroll
            for (int s = 0; s < 25; s++) {
                int j = s * 32 + lane;
                int jc = (j < KHW_) ? j : (KHW_ - 1);   // masked slots have p==0
                float vv = Vsm[d * KVP + jc];
                if (s & 1) { pb0 += s0[s] * vv; pb1 += s1[s] * vv; }
                else       { pa0 += s0[s] * vv; pa1 += s1[s] * vv; }
            }
            float p0 = pa0 + pb0, p1 = pa1 + pb1;
            #pragma unroll
            for (int o = 16; o; o >>= 1) {
                p0 += __shfl_xor_sync(0xffffffffu, p0, o);
                p1 += __shfl_xor_sync(0xffffffffu, p1, o);
            }
            if (lane == d) { o0 = p0; o1 = p1; }
        }
        res[((size_t)(b * HW_) + gi0) * 256 + h * 32 + lane] = o0 * inv0;
        res[((size_t)(b * HW_) + gi1) * 256 + h * 32 + lane] = o1 * inv1;
    }
}

// ---------------------------------------------------------------------------
extern "C" void kernel_launch(void* const* d_in, const int* in_sizes, int n_in,
                              void* d_out, int out_size) {
    const float* x     = (const float*)d_in[0];
    const float* Wk_dw = (const float*)d_in[1];
    const float* bk_dw = (const float*)d_in[2];
    const float* Wv_dw = (const float*)d_in[3];
    const float* bv_dw = (const float*)d_in[4];
    const float* Wq    = (const float*)d_in[5];
    const float* bq    = (const float*)d_in[6];
    const float* Wk    = (const float*)d_in[7];
    const float* bk    = (const float*)d_in[8];
    const float* Wv    = (const float*)d_in[9];
    const float* bv    = (const float*)d_in[10];
    const float* Wo    = (const float*)d_in[11];
    const float* bo    = (const float*)d_in[12];
    const float* Bb    = (const float*)d_in[13];
    float* out = (float*)d_out;

    float *qp, *kp, *vp, *ckp, *cvp, *resp, *cqp;
    cudaGetSymbolAddress((void**)&qp,  g_q);
    cudaGetSymbolAddress((void**)&kp,  g_k);
    cudaGetSymbolAddress((void**)&vp,  g_v);
    cudaGetSymbolAddress((void**)&ckp, g_ck);
    cudaGetSymbolAddress((void**)&cvp, g_cv);
    cudaGetSymbolAddress((void**)&resp, g_res);
    cudaGetSymbolAddress((void**)&cqp, g_cq);

    cudaFuncSetAttribute(attn_kernel,
                         cudaFuncAttributeMaxDynamicSharedMemorySize, ATT_SMEM);

    stats_partial<<<1024, 256>>>(x);
    stats_final<<<1, 256>>>(Wq, bq);
    dwconv_kernel<<<(B_ * C_ * KHW_ + 255) / 256, 256>>>(x, Wk_dw, bk_dw, Wv_dw, bv_dw);

    gemm_T_kernel<<<dim3(49, 4, B_), 256>>>(x,   Wq, cqp, 1, HW_,  qp);
    gemm_T_kernel<<<dim3(13, 4, B_), 256>>>(ckp, Wk, bk,  0, KHW_, kp);
    gemm_T_kernel<<<dim3(13, 4, B_), 256>>>(cvp, Wv, bv,  0, KHW_, vp);

    attn_kernel<<<dim3(49, HEADS_, B_), 256, ATT_SMEM>>>(qp, kp, vp, Bb, resp);

    gemm_O_kernel<<<dim3(49, 4, B_), 256>>>(resp, Wo, bo, x, out);
}

// round 2
// speedup vs baseline: 6.7371x; 6.7371x over previous
#include <cuda_runtime.h>
#include <cuda_bf16.h>
#include <math.h>
#include <stdint.h>

// Problem constants
#define B_   8
#define C_   256
#define H_   56
#define W_   56
#define HW_  3136        // 56*56
#define KHW_ 784         // 28*28
#define HEADS_ 8
#define DK_  32
#define DV_  32
#define HD_  256         // HEADS*DK
#define NTOT_ 6422528    // B*C*HW
#define EPS_ 1e-5

// Scratch (static device arrays — allocation-free)
__device__ float g_q[B_ * HW_ * HD_];     // [b][i][hd]
__device__ float g_k[B_ * KHW_ * HD_];    // [b][j][hd]
__device__ float g_v[B_ * KHW_ * HD_];
__device__ float g_ck[B_ * C_ * KHW_];    // conv-K out [b][c][j]
__device__ float g_cv[B_ * C_ * KHW_];
__device__ float g_res[B_ * HW_ * HD_];   // attention output [b][i][hd]
__device__ float g_part[2048];            // 1024 sums + 1024 sumsq
__device__ float g_stats[2];              // mu, rstd
__device__ float g_cq[256];               // folded Q bias

// ---------------------------------------------------------------------------
// Stage 1: partial sums for global layernorm stats
// ---------------------------------------------------------------------------
__global__ void stats_partial(const float* __restrict__ x) {
    int tid = threadIdx.x;
    int gid = blockIdx.x * 256 + tid;
    const float4* x4 = (const float4*)x;
    float s = 0.f, ss = 0.f;
    for (int i = gid; i < NTOT_ / 4; i += 1024 * 256) {
        float4 v = x4[i];
        s  += v.x + v.y + v.z + v.w;
        ss += v.x * v.x + v.y * v.y + v.z * v.z + v.w * v.w;
    }
    #pragma unroll
    for (int o = 16; o; o >>= 1) {
        s  += __shfl_xor_sync(0xffffffffu, s, o);
        ss += __shfl_xor_sync(0xffffffffu, ss, o);
    }
    __shared__ float sh[16];
    int w = tid >> 5, lane = tid & 31;
    if (lane == 0) { sh[w] = s; sh[8 + w] = ss; }
    __syncthreads();
    if (tid == 0) {
        float a = 0.f, b = 0.f;
        #pragma unroll
        for (int i = 0; i < 8; i++) { a += sh[i]; b += sh[8 + i]; }
        g_part[blockIdx.x] = a;
        g_part[1024 + blockIdx.x] = b;
    }
}

// ---------------------------------------------------------------------------
// Stage 2: finalize mu/rstd, and fold LN into Q bias
// ---------------------------------------------------------------------------
__global__ void stats_final(const float* __restrict__ Wq, const float* __restrict__ bq) {
    int tid = threadIdx.x;
    double s = 0.0, ss = 0.0;
    for (int i = tid; i < 1024; i += 256) {
        s  += (double)g_part[i];
        ss += (double)g_part[1024 + i];
    }
    __shared__ double shs[256], shss[256];
    shs[tid] = s; shss[tid] = ss;
    __syncthreads();
    for (int o = 128; o; o >>= 1) {
        if (tid < o) { shs[tid] += shs[tid + o]; shss[tid] += shss[tid + o]; }
        __syncthreads();
    }
    __shared__ float mu_s, rstd_s;
    if (tid == 0) {
        double N = (double)NTOT_;
        double mu = shs[0] / N;
        double var = shss[0] / N - mu * mu;
        float rstd = (float)(1.0 / sqrt(var + EPS_));
        g_stats[0] = (float)mu;
        g_stats[1] = rstd;
        mu_s = (float)mu; rstd_s = rstd;
    }
    __syncthreads();
    float rs = 0.f;
    const float* wrow = Wq + (size_t)tid * 256;
    for (int k = 0; k < 256; k++) rs += wrow[k];
    g_cq[tid] = bq[tid] - rstd_s * mu_s * rs;
}

// ---------------------------------------------------------------------------
// Depthwise 3x3 stride-2 conv (K and V paths fused)
// ---------------------------------------------------------------------------
__global__ void dwconv_kernel(const float* __restrict__ x,
                              const float* __restrict__ wk, const float* __restrict__ bkd,
                              const float* __restrict__ wv, const float* __restrict__ bvd) {
    int idx = blockIdx.x * blockDim.x + threadIdx.x;
    if (idx >= B_ * C_ * KHW_) return;
    int ox = idx % 28;
    int oy = (idx / 28) % 28;
    int c  = (idx / KHW_) % C_;
    int b  = idx / (KHW_ * C_);
    const float* xp = x + ((size_t)(b * C_ + c)) * HW_;
    float ak = 0.f, av = 0.f;
    #pragma unroll
    for (int ky = 0; ky < 3; ky++) {
        int iy = oy * 2 + ky - 1;
        if (iy < 0 || iy >= H_) continue;
        #pragma unroll
        for (int kx = 0; kx < 3; kx++) {
            int ix = ox * 2 + kx - 1;
            if (ix < 0 || ix >= W_) continue;
            float xv = xp[iy * W_ + ix];
            ak += xv * wk[c * 9 + ky * 3 + kx];
            av += xv * wv[c * 9 + ky * 3 + kx];
        }
    }
    g_ck[idx] = ak + bkd[c];
    g_cv[idx] = av + bvd[c];
}

// ---------------------------------------------------------------------------
// GEMM (transposed A): used for Q (alpha=rstd), K, V projections
// ---------------------------------------------------------------------------
#define PADL 68
__global__ void gemm_T_kernel(const float* __restrict__ A,
                              const float* __restrict__ Wt,
                              const float* __restrict__ cvec,
                              int useAlpha, int M,
                              float* __restrict__ out) {
    __shared__ float As[16][PADL];
    __shared__ float Bs[16][PADL];
    int b  = blockIdx.z;
    int i0 = blockIdx.x * 64;
    int n0 = blockIdx.y * 64;
    const float* Ab = A + (size_t)b * 256 * M;
    float alpha = useAlpha ? g_stats[1] : 1.0f;
    int tid = threadIdx.x;
    int tx = tid & 15, ty = tid >> 4;
    float acc[4][4] = {};

    for (int k0 = 0; k0 < 256; k0 += 16) {
        {
            int i   = tid & 63;
            int kk0 = tid >> 6;
            #pragma unroll
            for (int r = 0; r < 4; r++) {
                int kk = kk0 + r * 4;
                int gi = i0 + i;
                As[kk][i] = (gi < M) ? Ab[(size_t)(k0 + kk) * M + gi] : 0.f;
            }
        }
        {
            int kk = tid & 15;
            int n  = tid >> 4;
            #pragma unroll
            for (int r = 0; r < 4; r++)
                Bs[kk][n + r * 16] = Wt[(size_t)(n0 + n + r * 16) * 256 + k0 + kk];
        }
        __syncthreads();
        #pragma unroll
        for (int k = 0; k < 16; k++) {
            float av[4], bv[4];
            #pragma unroll
            for (int m = 0; m < 4; m++) av[m] = As[k][ty * 4 + m];
            #pragma unroll
            for (int n = 0; n < 4; n++) bv[n] = Bs[k][tx * 4 + n];
            #pragma unroll
            for (int m = 0; m < 4; m++)
                #pragma unroll
                for (int n = 0; n < 4; n++) acc[m][n] += av[m] * bv[n];
        }
        __syncthreads();
    }
    #pragma unroll
    for (int m = 0; m < 4; m++) {
        int gi = i0 + ty * 4 + m;
        if (gi >= M) continue;
        float* orow = out + ((size_t)b * M + gi) * 256 + n0 + tx * 4;
        #pragma unroll
        for (int n = 0; n < 4; n++)
            orow[n] = alpha * acc[m][n] + cvec[n0 + tx * 4 + n];
    }
}

// ---------------------------------------------------------------------------
// O projection GEMM with fused flat residual add
// ---------------------------------------------------------------------------
__global__ void gemm_O_kernel(const float* __restrict__ A,
                              const float* __restrict__ Wt,
                              const float* __restrict__ bo,
                              const float* __restrict__ x,
                              float* __restrict__ out) {
    __shared__ float As[16][PADL];
    __shared__ float Bs[16][PADL];
    int b  = blockIdx.z;
    int i0 = blockIdx.x * 64;
    int n0 = blockIdx.y * 64;
    int tid = threadIdx.x;
    int tx = tid & 15, ty = tid >> 4;
    float acc[4][4] = {};

    for (int k0 = 0; k0 < 256; k0 += 16) {
        {
            int i  = tid >> 4;
            int kk = tid & 15;
            #pragma unroll
            for (int r = 0; r < 4; r++)
                As[kk][i + r * 16] =
                    A[((size_t)(b * HW_) + i0 + i + r * 16) * 256 + k0 + kk];
        }
        {
            int kk = tid & 15;
            int n  = tid >> 4;
            #pragma unroll
            for (int r = 0; r < 4; r++)
                Bs[kk][n + r * 16] = Wt[(size_t)(n0 + n + r * 16) * 256 + k0 + kk];
        }
        __syncthreads();
        #pragma unroll
        for (int k = 0; k < 16; k++) {
            float av[4], bv[4];
            #pragma unroll
            for (int m = 0; m < 4; m++) av[m] = As[k][ty * 4 + m];
            #pragma unroll
            for (int n = 0; n < 4; n++) bv[n] = Bs[k][tx * 4 + n];
            #pragma unroll
            for (int m = 0; m < 4; m++)
                #pragma unroll
                for (int n = 0; n < 4; n++) acc[m][n] += av[m] * bv[n];
        }
        __syncthreads();
    }
    #pragma unroll
    for (int m = 0; m < 4; m++) {
        int gi = i0 + ty * 4 + m;
        size_t flat = (size_t)b * (C_ * HW_) + (size_t)gi * 256 + n0 + tx * 4;
        #pragma unroll
        for (int n = 0; n < 4; n++)
            out[flat + n] = acc[m][n] + bo[n0 + tx * 4 + n] + x[flat + n];
    }
}

// ---------------------------------------------------------------------------
// bf16 tensor-core flash attention.
// Block = 128 q-rows x (b,h). 8 warps, each owns a 16-row stripe -> all
// softmax row stats are warp-local. KV tiles of 64 in smem (bf16, 40-elem
// row stride = conflict-free ldmatrix). S accum (16x64 per warp) converts
// in-registers into PV A-fragments. fp32 accumulation throughout.
// ---------------------------------------------------------------------------
__device__ __forceinline__ uint32_t smem_u32(const void* p) {
    return (uint32_t)__cvta_generic_to_shared(p);
}
__device__ __forceinline__ void ldm_x4(uint32_t* r, uint32_t addr) {
    asm volatile("ldmatrix.sync.aligned.m8n8.x4.shared.b16 {%0,%1,%2,%3}, [%4];"
        : "=r"(r[0]), "=r"(r[1]), "=r"(r[2]), "=r"(r[3]) : "r"(addr));
}
__device__ __forceinline__ void ldm_x4_t(uint32_t* r, uint32_t addr) {
    asm volatile("ldmatrix.sync.aligned.m8n8.x4.trans.shared.b16 {%0,%1,%2,%3}, [%4];"
        : "=r"(r[0]), "=r"(r[1]), "=r"(r[2]), "=r"(r[3]) : "r"(addr));
}
__device__ __forceinline__ void mma_bf16(float* d, const uint32_t* a, const uint32_t* b) {
    asm volatile(
        "mma.sync.aligned.m16n8k16.row.col.f32.bf16.bf16.f32 "
        "{%0,%1,%2,%3}, {%4,%5,%6,%7}, {%8,%9}, {%0,%1,%2,%3};"
        : "+f"(d[0]), "+f"(d[1]), "+f"(d[2]), "+f"(d[3])
        : "r"(a[0]), "r"(a[1]), "r"(a[2]), "r"(a[3]), "r"(b[0]), "r"(b[1]));
}
__device__ __forceinline__ uint32_t pack_bf16x2(float lo, float hi) {
    uint32_t r;
    asm("cvt.rn.bf16x2.f32 %0, %1, %2;" : "=r"(r) : "f"(hi), "f"(lo));
    return r;
}

#define QROWS 128
#define JTILE 64
#define KVSTRIDE 40   // bf16 elems per smem row (80B: conflict-free for ldmatrix)

__global__ void __launch_bounds__(256, 2) attn_mma_kernel(
    const float* __restrict__ qb, const float* __restrict__ kb,
    const float* __restrict__ vb, const float* __restrict__ bias,
    float* __restrict__ res)
{
    __shared__ __align__(16) __nv_bfloat16 Qs[QROWS * KVSTRIDE];
    __shared__ __align__(16) __nv_bfloat16 Ks[JTILE * KVSTRIDE];
    __shared__ __align__(16) __nv_bfloat16 Vs[JTILE * KVSTRIDE];

    const int b = blockIdx.z, h = blockIdx.y;
    const int i0 = blockIdx.x * QROWS;
    const int tid = threadIdx.x, lane = tid & 31, w = tid >> 5;
    const float scale = 0.17677669529663687f;  // 1/sqrt(32)

    // --- Load Q tile (fp32 -> bf16, scale folded in) ---
    #pragma unroll
    for (int f = tid; f < QROWS * 8; f += 256) {
        int r = f >> 3, seg = f & 7;
        int gi = i0 + r; if (gi > HW_ - 1) gi = HW_ - 1;
        float4 v = *(const float4*)(qb + ((size_t)(b * HW_ + gi)) * 256 + h * 32 + seg * 4);
        __nv_bfloat162 p0 = __floats2bfloat162_rn(v.x * scale, v.y * scale);
        __nv_bfloat162 p1 = __floats2bfloat162_rn(v.z * scale, v.w * scale);
        *(__nv_bfloat162*)(&Qs[r * KVSTRIDE + seg * 4])     = p0;
        *(__nv_bfloat162*)(&Qs[r * KVSTRIDE + seg * 4 + 2]) = p1;
    }
    __syncthreads();

    // --- Q A-fragments (held for whole kernel) ---
    uint32_t qa[2][4];
    {
        uint32_t qbase = smem_u32(Qs);
        int rr = w * 16 + ((lane >> 3) & 1) * 8 + (lane & 7);
        int ch = (lane >> 4) & 1;
        #pragma unroll
        for (int kk = 0; kk < 2; kk++)
            ldm_x4(qa[kk], qbase + (uint32_t)(rr * (KVSTRIDE * 2) + kk * 32 + ch * 16));
    }

    float m0 = -1e30f, m1 = -1e30f;      // running max (rows lane/4, lane/4+8)
    float l0 = 0.f, l1 = 0.f;            // running denom
    float oacc[4][4];
    #pragma unroll
    for (int nf = 0; nf < 4; nf++)
        #pragma unroll
        for (int r = 0; r < 4; r++) oacc[nf][r] = 0.f;

    const uint32_t kbase = smem_u32(Ks);
    const uint32_t vbase = smem_u32(Vs);
    const int browA = i0 + w * 16 + (lane >> 2);
    const int biasRowA = (browA < HW_) ? browA : HW_ - 1;
    const int biasRowB = (browA + 8 < HW_) ? browA + 8 : HW_ - 1;
    const float* biasA = bias + ((size_t)h * HW_ + biasRowA) * KHW_;
    const float* biasB = bias + ((size_t)h * HW_ + biasRowB) * KHW_;

    for (int jt = 0; jt < 13; jt++) {
        const int j0 = jt * JTILE;
        __syncthreads();
        // --- Load K,V tile (fp32 -> bf16) ---
        #pragma unroll
        for (int f = tid; f < JTILE * 8; f += 256) {
            int r = f >> 3, seg = f & 7;
            int gj = j0 + r; if (gj > KHW_ - 1) gj = KHW_ - 1;
            size_t gofs = ((size_t)(b * KHW_ + gj)) * 256 + h * 32 + seg * 4;
            float4 kv = *(const float4*)(kb + gofs);
            float4 vv = *(const float4*)(vb + gofs);
            *(__nv_bfloat162*)(&Ks[r * KVSTRIDE + seg * 4])     = __floats2bfloat162_rn(kv.x, kv.y);
            *(__nv_bfloat162*)(&Ks[r * KVSTRIDE + seg * 4 + 2]) = __floats2bfloat162_rn(kv.z, kv.w);
            *(__nv_bfloat162*)(&Vs[r * KVSTRIDE + seg * 4])     = __floats2bfloat162_rn(vv.x, vv.y);
            *(__nv_bfloat162*)(&Vs[r * KVSTRIDE + seg * 4 + 2]) = __floats2bfloat162_rn(vv.z, vv.w);
        }
        __syncthreads();

        // --- S = Q @ K^T ---
        float s[8][4];
        #pragma unroll
        for (int nf = 0; nf < 8; nf++)
            #pragma unroll
            for (int r = 0; r < 4; r++) s[nf][r] = 0.f;

        #pragma unroll
        for (int kk = 0; kk < 2; kk++) {
            uint32_t kbf[8][2];
            int rr = ((lane >> 3) & 1) * 8 + (lane & 7);
            int ch = (lane >> 4) & 1;
            #pragma unroll
            for (int ng = 0; ng < 4; ng++) {
                uint32_t r4[4];
                ldm_x4(r4, kbase + (uint32_t)((ng * 16 + rr) * (KVSTRIDE * 2) + kk * 32 + ch * 16));
                kbf[2 * ng][0] = r4[0]; kbf[2 * ng][1] = r4[2];
                kbf[2 * ng + 1][0] = r4[1]; kbf[2 * ng + 1][1] = r4[3];
            }
            #pragma unroll
            for (int nf = 0; nf < 8; nf++) mma_bf16(s[nf], qa[kk], kbf[nf]);
        }

        // --- bias + mask + online softmax ---
        float rmax0 = -1e30f, rmax1 = -1e30f;
        #pragma unroll
        for (int nf = 0; nf < 8; nf++) {
            int gj = j0 + nf * 8 + (lane & 3) * 2;
            bool jv = (gj < KHW_);
            int gjc = jv ? gj : (KHW_ - 2);
            float2 bA = *(const float2*)(biasA + gjc);
            float2 bB = *(const float2*)(biasB + gjc);
            float v0 = s[nf][0] + bA.x, v1 = s[nf][1] + bA.y;
            float v2 = s[nf][2] + bB.x, v3 = s[nf][3] + bB.y;
            if (!jv) { v0 = v1 = v2 = v3 = -1e30f; }
            s[nf][0] = v0; s[nf][1] = v1; s[nf][2] = v2; s[nf][3] = v3;
            rmax0 = fmaxf(rmax0, fmaxf(v0, v1));
            rmax1 = fmaxf(rmax1, fmaxf(v2, v3));
        }
        #pragma unroll
        for (int o = 1; o <= 2; o <<= 1) {
            rmax0 = fmaxf(rmax0, __shfl_xor_sync(0xffffffffu, rmax0, o));
            rmax1 = fmaxf(rmax1, __shfl_xor_sync(0xffffffffu, rmax1, o));
        }
        float mn0 = fmaxf(m0, rmax0), mn1 = fmaxf(m1, rmax1);
        float al0 = __expf(m0 - mn0), al1 = __expf(m1 - mn1);
        m0 = mn0; m1 = mn1;

        float rs0 = 0.f, rs1 = 0.f;
        uint32_t pa[4][4];
        #pragma unroll
        for (int nf = 0; nf < 8; nf++) {
            float p0 = __expf(s[nf][0] - mn0);
            float p1 = __expf(s[nf][1] - mn0);
            float p2 = __expf(s[nf][2] - mn1);
            float p3 = __expf(s[nf][3] - mn1);
            rs0 += p0 + p1; rs1 += p2 + p3;
            pa[nf >> 1][(nf & 1) * 2 + 0] = pack_bf16x2(p0, p1);
            pa[nf >> 1][(nf & 1) * 2 + 1] = pack_bf16x2(p2, p3);
        }
        #pragma unroll
        for (int o = 1; o <= 2; o <<= 1) {
            rs0 += __shfl_xor_sync(0xffffffffu, rs0, o);
            rs1 += __shfl_xor_sync(0xffffffffu, rs1, o);
        }
        l0 = al0 * l0 + rs0;
        l1 = al1 * l1 + rs1;
        #pragma unroll
        for (int nf = 0; nf < 4; nf++) {
            oacc[nf][0] *= al0; oacc[nf][1] *= al0;
            oacc[nf][2] *= al1; oacc[nf][3] *= al1;
        }

        // --- O += P @ V ---
        uint32_t vbf[4][4][2];   // [n-frag d][k-frag j][2]
        {
            int rr = ((lane >> 3) & 1) * 8 + (lane & 7);
            int ch = (lane >> 4) & 1;
            #pragma unroll
            for (int kf = 0; kf < 4; kf++)
                #pragma unroll
                for (int nv = 0; nv < 2; nv++) {
                    uint32_t r4[4];
                    ldm_x4_t(r4, vbase + (uint32_t)((kf * 16 + rr) * (KVSTRIDE * 2) + (nv * 16 + ch * 8) * 2));
                    vbf[2 * nv][kf][0] = r4[0]; vbf[2 * nv][kf][1] = r4[1];
                    vbf[2 * nv + 1][kf][0] = r4[2]; vbf[2 * nv + 1][kf][1] = r4[3];
                }
        }
        #pragma unroll
        for (int kf = 0; kf < 4; kf++)
            #pragma unroll
            for (int nf = 0; nf < 4; nf++)
                mma_bf16(oacc[nf], pa[kf], vbf[nf][kf]);
    }

    // --- epilogue: normalize + store ---
    float inv0 = 1.f / l0, inv1 = 1.f / l1;
    int giA = i0 + w * 16 + (lane >> 2);
    int giB = giA + 8;
    #pragma unroll
    for (int nf = 0; nf < 4; nf++) {
        int col = h * 32 + nf * 8 + (lane & 3) * 2;
        if (giA < HW_) {
            float2 o2 = make_float2(oacc[nf][0] * inv0, oacc[nf][1] * inv0);
            *(float2*)(res + ((size_t)(b * HW_ + giA)) * 256 + col) = o2;
        }
        if (giB < HW_) {
            float2 o2 = make_float2(oacc[nf][2] * inv1, oacc[nf][3] * inv1);
            *(float2*)(res + ((size_t)(b * HW_ + giB)) * 256 + col) = o2;
        }
    }
}

// ---------------------------------------------------------------------------
extern "C" void kernel_launch(void* const* d_in, const int* in_sizes, int n_in,
                              void* d_out, int out_size) {
    const float* x     = (const float*)d_in[0];
    const float* Wk_dw = (const float*)d_in[1];
    const float* bk_dw = (const float*)d_in[2];
    const float* Wv_dw = (const float*)d_in[3];
    const float* bv_dw = (const float*)d_in[4];
    const float* Wq    = (const float*)d_in[5];
    const float* bq    = (const float*)d_in[6];
    const float* Wk    = (const float*)d_in[7];
    const float* bk    = (const float*)d_in[8];
    const float* Wv    = (const float*)d_in[9];
    const float* bv    = (const float*)d_in[10];
    const float* Wo    = (const float*)d_in[11];
    const float* bo    = (const float*)d_in[12];
    const float* Bb    = (const float*)d_in[13];
    float* out = (float*)d_out;

    float *qp, *kp, *vp, *ckp, *cvp, *resp, *cqp;
    cudaGetSymbolAddress((void**)&qp,  g_q);
    cudaGetSymbolAddress((void**)&kp,  g_k);
    cudaGetSymbolAddress((void**)&vp,  g_v);
    cudaGetSymbolAddress((void**)&ckp, g_ck);
    cudaGetSymbolAddress((void**)&cvp, g_cv);
    cudaGetSymbolAddress((void**)&resp, g_res);
    cudaGetSymbolAddress((void**)&cqp, g_cq);

    stats_partial<<<1024, 256>>>(x);
    stats_final<<<1, 256>>>(Wq, bq);
    dwconv_kernel<<<(B_ * C_ * KHW_ + 255) / 256, 256>>>(x, Wk_dw, bk_dw, Wv_dw, bv_dw);

    gemm_T_kernel<<<dim3(49, 4, B_), 256>>>(x,   Wq, cqp, 1, HW_,  qp);
    gemm_T_kernel<<<dim3(13, 4, B_), 256>>>(ckp, Wk, bk,  0, KHW_, kp);
    gemm_T_kernel<<<dim3(13, 4, B_), 256>>>(cvp, Wv, bv,  0, KHW_, vp);

    attn_mma_kernel<<<dim3((HW_ + QROWS - 1) / QROWS, HEADS_, B_), 256>>>(qp, kp, vp, Bb, resp);

    gemm_O_kernel<<<dim3(49, 4, B_), 256>>>(resp, Wo, bo, x, out);
}

// round 3
// speedup vs baseline: 11.9457x; 1.7731x over previous
#include <cuda_runtime.h>
#include <cuda_bf16.h>
#include <math.h>
#include <stdint.h>

// Problem constants
#define B_   8
#define C_   256
#define H_   56
#define W_   56
#define HW_  3136        // 56*56
#define KHW_ 784         // 28*28
#define HEADS_ 8
#define NTOT_ 6422528    // B*C*HW
#define EPS_ 1e-5
#define SCALE_ 0.17677669529663687f   // 1/sqrt(32)

// Scratch (static device arrays — allocation-free)
__device__ __nv_bfloat16 g_q[B_ * 256 * HW_];    // [b][hd][i]
__device__ __nv_bfloat16 g_k[B_ * 256 * KHW_];   // [b][hd][j]
__device__ __nv_bfloat16 g_v[B_ * 256 * KHW_];   // [b][hd][j]
__device__ __nv_bfloat16 g_res[B_ * HW_ * 256];  // [b][i][hd]
__device__ float g_ck[B_ * C_ * KHW_];           // conv-K out [b][c][j]
__device__ float g_cv[B_ * C_ * KHW_];
__device__ float g_part[2048];
__device__ float g_stats[2];                     // mu, rstd
__device__ float g_cq[256];                      // folded Q bias

// ---------------------------------------------------------------------------
// mma helpers
// ---------------------------------------------------------------------------
__device__ __forceinline__ uint32_t smem_u32(const void* p) {
    return (uint32_t)__cvta_generic_to_shared(p);
}
__device__ __forceinline__ void ldm_x4(uint32_t* r, uint32_t addr) {
    asm volatile("ldmatrix.sync.aligned.m8n8.x4.shared.b16 {%0,%1,%2,%3}, [%4];"
        : "=r"(r[0]), "=r"(r[1]), "=r"(r[2]), "=r"(r[3]) : "r"(addr));
}
__device__ __forceinline__ void ldm_x4_t(uint32_t* r, uint32_t addr) {
    asm volatile("ldmatrix.sync.aligned.m8n8.x4.trans.shared.b16 {%0,%1,%2,%3}, [%4];"
        : "=r"(r[0]), "=r"(r[1]), "=r"(r[2]), "=r"(r[3]) : "r"(addr));
}
__device__ __forceinline__ void mma_bf16(float* d, const uint32_t* a, const uint32_t* b) {
    asm volatile(
        "mma.sync.aligned.m16n8k16.row.col.f32.bf16.bf16.f32 "
        "{%0,%1,%2,%3}, {%4,%5,%6,%7}, {%8,%9}, {%0,%1,%2,%3};"
        : "+f"(d[0]), "+f"(d[1]), "+f"(d[2]), "+f"(d[3])
        : "r"(a[0]), "r"(a[1]), "r"(a[2]), "r"(a[3]), "r"(b[0]), "r"(b[1]));
}
__device__ __forceinline__ uint32_t pack_bf16x2(float lo, float hi) {
    uint32_t r;
    asm("cvt.rn.bf16x2.f32 %0, %1, %2;" : "=r"(r) : "f"(hi), "f"(lo));
    return r;
}

// ---------------------------------------------------------------------------
// Stage 1: partial sums for global layernorm stats
// ---------------------------------------------------------------------------
__global__ void stats_partial(const float* __restrict__ x) {
    int tid = threadIdx.x;
    int gid = blockIdx.x * 256 + tid;
    const float4* x4 = (const float4*)x;
    float s = 0.f, ss = 0.f;
    for (int i = gid; i < NTOT_ / 4; i += 1024 * 256) {
        float4 v = x4[i];
        s  += v.x + v.y + v.z + v.w;
        ss += v.x * v.x + v.y * v.y + v.z * v.z + v.w * v.w;
    }
    #pragma unroll
    for (int o = 16; o; o >>= 1) {
        s  += __shfl_xor_sync(0xffffffffu, s, o);
        ss += __shfl_xor_sync(0xffffffffu, ss, o);
    }
    __shared__ float sh[16];
    int w = tid >> 5, lane = tid & 31;
    if (lane == 0) { sh[w] = s; sh[8 + w] = ss; }
    __syncthreads();
    if (tid == 0) {
        float a = 0.f, b = 0.f;
        #pragma unroll
        for (int i = 0; i < 8; i++) { a += sh[i]; b += sh[8 + i]; }
        g_part[blockIdx.x] = a;
        g_part[1024 + blockIdx.x] = b;
    }
}

// ---------------------------------------------------------------------------
// Stage 2: finalize mu/rstd, fold LN into Q bias: cq = bq - rstd*mu*rowsum(Wq)
// ---------------------------------------------------------------------------
__global__ void stats_final(const float* __restrict__ Wq, const float* __restrict__ bq) {
    int tid = threadIdx.x;
    double s = 0.0, ss = 0.0;
    for (int i = tid; i < 1024; i += 256) {
        s  += (double)g_part[i];
        ss += (double)g_part[1024 + i];
    }
    __shared__ double shs[256], shss[256];
    shs[tid] = s; shss[tid] = ss;
    __syncthreads();
    for (int o = 128; o; o >>= 1) {
        if (tid < o) { shs[tid] += shs[tid + o]; shss[tid] += shss[tid + o]; }
        __syncthreads();
    }
    __shared__ float mu_s, rstd_s;
    if (tid == 0) {
        double N = (double)NTOT_;
        double mu = shs[0] / N;
        double var = shss[0] / N - mu * mu;
        float rstd = (float)(1.0 / sqrt(var + EPS_));
        g_stats[0] = (float)mu;
        g_stats[1] = rstd;
        mu_s = (float)mu; rstd_s = rstd;
    }
    __syncthreads();
    float rs = 0.f;
    const float* wrow = Wq + (size_t)tid * 256;
    for (int k = 0; k < 256; k++) rs += wrow[k];
    g_cq[tid] = bq[tid] - rstd_s * mu_s * rs;
}

// ---------------------------------------------------------------------------
// Depthwise 3x3 stride-2 conv (K and V paths fused)
// ---------------------------------------------------------------------------
__global__ void dwconv_kernel(const float* __restrict__ x,
                              const float* __restrict__ wk, const float* __restrict__ bkd,
                              const float* __restrict__ wv, const float* __restrict__ bvd) {
    int idx = blockIdx.x * blockDim.x + threadIdx.x;
    if (idx >= B_ * C_ * KHW_) return;
    int ox = idx % 28;
    int oy = (idx / 28) % 28;
    int c  = (idx / KHW_) % C_;
    int b  = idx / (KHW_ * C_);
    const float* xp = x + ((size_t)(b * C_ + c)) * HW_;
    float ak = 0.f, av = 0.f;
    #pragma unroll
    for (int ky = 0; ky < 3; ky++) {
        int iy = oy * 2 + ky - 1;
        if (iy < 0 || iy >= H_) continue;
        #pragma unroll
        for (int kx = 0; kx < 3; kx++) {
            int ix = ox * 2 + kx - 1;
            if (ix < 0 || ix >= W_) continue;
            float xv = xp[iy * W_ + ix];
            ak += xv * wk[c * 9 + ky * 3 + kx];
            av += xv * wv[c * 9 + ky * 3 + kx];
        }
    }
    g_ck[idx] = ak + bkd[c];
    g_cv[idx] = av + bvd[c];
}

// ---------------------------------------------------------------------------
// bf16 mma GEMM: out[b][R][P] = a1 * sum_k W[R][k] * X[b][k][P] + a2*cvec[R]
// W fp32 [256][256] row-major, X fp32 [b][256][Mt], out bf16 [b][256][Mt].
// Block tile R128 x P128, BK=32; 8 warps (2 R x 4 P), warp tile 64x32.
// isQ: a1 = rstd*SCALE, a2 = SCALE (LN + softmax scale folded).
// ---------------------------------------------------------------------------
#define WST 40
#define XST 136
__global__ void __launch_bounds__(256, 2) gemm_wx(
    const float* __restrict__ W, const float* __restrict__ X,
    const float* __restrict__ cvec, int isQ, int Mt,
    __nv_bfloat16* __restrict__ out)
{
    __shared__ __align__(16) __nv_bfloat16 Ws[128 * WST];
    __shared__ __align__(16) __nv_bfloat16 Xs[32 * XST];
    const int P0 = blockIdx.x * 128;
    const int R0 = blockIdx.y * 128;
    const int b  = blockIdx.z;
    const float* Xb = X + (size_t)b * 256 * Mt;
    const int tid = threadIdx.x, lane = tid & 31, w = tid >> 5;
    const int wR = (w >> 2) * 64, wP = (w & 3) * 32;

    float c[4][4][4];
    #pragma unroll
    for (int i = 0; i < 4; i++)
        #pragma unroll
        for (int j = 0; j < 4; j++)
            #pragma unroll
            for (int r = 0; r < 4; r++) c[i][j][r] = 0.f;

    const uint32_t wsb = smem_u32(Ws), xsb = smem_u32(Xs);

    for (int k0 = 0; k0 < 256; k0 += 32) {
        __syncthreads();
        #pragma unroll
        for (int f = tid; f < 1024; f += 256) {
            int r = f >> 3, kq = (f & 7) * 4;
            float4 v = *(const float4*)(W + (size_t)(R0 + r) * 256 + k0 + kq);
            *(__nv_bfloat162*)&Ws[r * WST + kq]     = __floats2bfloat162_rn(v.x, v.y);
            *(__nv_bfloat162*)&Ws[r * WST + kq + 2] = __floats2bfloat162_rn(v.z, v.w);
        }
        #pragma unroll
        for (int f = tid; f < 1024; f += 256) {
            int kk = f >> 5, p = (f & 31) * 4;
            int gp = P0 + p; if (gp > Mt - 4) gp = Mt - 4;
            float4 v = *(const float4*)(Xb + (size_t)(k0 + kk) * Mt + gp);
            *(__nv_bfloat162*)&Xs[kk * XST + p]     = __floats2bfloat162_rn(v.x, v.y);
            *(__nv_bfloat162*)&Xs[kk * XST + p + 2] = __floats2bfloat162_rn(v.z, v.w);
        }
        __syncthreads();

        #pragma unroll
        for (int kk = 0; kk < 2; kk++) {
            uint32_t af[4][4], bf[4][2];
            {
                int rr = ((lane >> 3) & 1) * 8 + (lane & 7);
                int ch = (lane >> 4) & 1;
                #pragma unroll
                for (int rf = 0; rf < 4; rf++)
                    ldm_x4(af[rf], wsb + (uint32_t)(((wR + rf * 16 + rr) * WST + kk * 16 + ch * 8) * 2));
            }
            {
                int krow = (lane & 7) + ((lane >> 3) & 1) * 8;
                int pc = ((lane >> 4) & 1) * 8;
                #pragma unroll
                for (int pf = 0; pf < 2; pf++) {
                    uint32_t r4[4];
                    ldm_x4_t(r4, xsb + (uint32_t)(((kk * 16 + krow) * XST + wP + pf * 16 + pc) * 2));
                    bf[2 * pf][0] = r4[0]; bf[2 * pf][1] = r4[1];
                    bf[2 * pf + 1][0] = r4[2]; bf[2 * pf + 1][1] = r4[3];
                }
            }
            #pragma unroll
            for (int rf = 0; rf < 4; rf++)
                #pragma unroll
                for (int pg = 0; pg < 4; pg++)
                    mma_bf16(c[rf][pg], af[rf], bf[pg]);
        }
    }

    float a1 = 1.f, a2 = 1.f;
    if (isQ) { a1 = g_stats[1] * SCALE_; a2 = SCALE_; }
    __nv_bfloat16* ob = out + (size_t)b * 256 * Mt;
    #pragma unroll
    for (int rf = 0; rf < 4; rf++) {
        int R = R0 + wR + rf * 16 + (lane >> 2);
        float cv1 = a2 * cvec[R], cv2 = a2 * cvec[R + 8];
        #pragma unroll
        for (int pg = 0; pg < 4; pg++) {
            int P = P0 + wP + pg * 8 + (lane & 3) * 2;
            if (P < Mt) {
                *(__nv_bfloat162*)(ob + (size_t)R * Mt + P) =
                    __floats2bfloat162_rn(a1 * c[rf][pg][0] + cv1, a1 * c[rf][pg][1] + cv1);
                *(__nv_bfloat162*)(ob + (size_t)(R + 8) * Mt + P) =
                    __floats2bfloat162_rn(a1 * c[rf][pg][2] + cv2, a1 * c[rf][pg][3] + cv2);
            }
        }
    }
}

// ---------------------------------------------------------------------------
// O projection mma GEMM + fused bias + flat residual add (fp32 out):
//   out.flat[b, i*256+n] = res_bf16[b][i][:] @ Wo[n][:] + bo[n] + x.flat
// ---------------------------------------------------------------------------
__global__ void __launch_bounds__(256, 2) gemm_o(
    const __nv_bfloat16* __restrict__ A, const float* __restrict__ Wo,
    const float* __restrict__ bo, const float* __restrict__ x,
    float* __restrict__ out)
{
    __shared__ __align__(16) __nv_bfloat16 As[128 * WST];
    __shared__ __align__(16) __nv_bfloat16 Bs[128 * WST];
    const int I0 = blockIdx.x * 128;
    const int N0 = blockIdx.y * 128;
    const int b  = blockIdx.z;
    const int tid = threadIdx.x, lane = tid & 31, w = tid >> 5;
    const int wI = (w >> 2) * 64, wN = (w & 3) * 32;

    float c[4][4][4];
    #pragma unroll
    for (int i = 0; i < 4; i++)
        #pragma unroll
        for (int j = 0; j < 4; j++)
            #pragma unroll
            for (int r = 0; r < 4; r++) c[i][j][r] = 0.f;

    const uint32_t asb = smem_u32(As), bsb = smem_u32(Bs);

    for (int k0 = 0; k0 < 256; k0 += 32) {
        __syncthreads();
        #pragma unroll
        for (int f = tid; f < 512; f += 256) {
            int i = f >> 2, kq = (f & 3) * 8;
            int gi = I0 + i; if (gi > HW_ - 1) gi = HW_ - 1;
            *(uint4*)&As[i * WST + kq] =
                *(const uint4*)(A + ((size_t)(b * HW_) + gi) * 256 + k0 + kq);
        }
        #pragma unroll
        for (int f = tid; f < 1024; f += 256) {
            int n = f >> 3, kq = (f & 7) * 4;
            float4 v = *(const float4*)(Wo + (size_t)(N0 + n) * 256 + k0 + kq);
            *(__nv_bfloat162*)&Bs[n * WST + kq]     = __floats2bfloat162_rn(v.x, v.y);
            *(__nv_bfloat162*)&Bs[n * WST + kq + 2] = __floats2bfloat162_rn(v.z, v.w);
        }
        __syncthreads();

        #pragma unroll
        for (int kk = 0; kk < 2; kk++) {
            int rr = ((lane >> 3) & 1) * 8 + (lane & 7);
            int ch = (lane >> 4) & 1;
            uint32_t af[4][4], bf[4][2];
            #pragma unroll
            for (int mf = 0; mf < 4; mf++)
                ldm_x4(af[mf], asb + (uint32_t)(((wI + mf * 16 + rr) * WST + kk * 16 + ch * 8) * 2));
            #pragma unroll
            for (int ng = 0; ng < 2; ng++) {
                uint32_t r4[4];
                ldm_x4(r4, bsb + (uint32_t)(((wN + ng * 16 + rr) * WST + kk * 16 + ch * 8) * 2));
                bf[2 * ng][0] = r4[0]; bf[2 * ng][1] = r4[2];
                bf[2 * ng + 1][0] = r4[1]; bf[2 * ng + 1][1] = r4[3];
            }
            #pragma unroll
            for (int mf = 0; mf < 4; mf++)
                #pragma unroll
                for (int nf = 0; nf < 4; nf++)
                    mma_bf16(c[mf][nf], af[mf], bf[nf]);
        }
    }

    #pragma unroll
    for (int mf = 0; mf < 4; mf++) {
        int i1 = I0 + wI + mf * 16 + (lane >> 2);
        int i2 = i1 + 8;
        #pragma unroll
        for (int nf = 0; nf < 4; nf++) {
            int n = N0 + wN + nf * 8 + (lane & 3) * 2;
            float b0v = bo[n], b1v = bo[n + 1];
            if (i1 < HW_) {
                size_t flat = (size_t)b * (256 * HW_) + (size_t)i1 * 256 + n;
                float2 xv = *(const float2*)(x + flat);
                *(float2*)(out + flat) =
                    make_float2(c[mf][nf][0] + b0v + xv.x, c[mf][nf][1] + b1v + xv.y);
            }
            if (i2 < HW_) {
                size_t flat = (size_t)b * (256 * HW_) + (size_t)i2 * 256 + n;
                float2 xv = *(const float2*)(x + flat);
                *(float2*)(out + flat) =
                    make_float2(c[mf][nf][2] + b0v + xv.x, c[mf][nf][3] + b1v + xv.y);
            }
        }
    }
}

// ---------------------------------------------------------------------------
// bf16 flash attention; q/k/v in [b][hd][m] bf16 layout (direct coalesced
// copies into smem). Q/K fragments via ldmatrix.trans from [d][m]; V via
// non-trans ([d][j] == [n][k] row-major). Grid (b, h, itile): b innermost so
// batches sharing a bias slice are adjacent -> L2-resident bias.
// ---------------------------------------------------------------------------
#define QST 136
#define KST 72

__global__ void __launch_bounds__(256, 2) attn_mma_kernel(
    const __nv_bfloat16* __restrict__ qb, const __nv_bfloat16* __restrict__ kb,
    const __nv_bfloat16* __restrict__ vb, const float* __restrict__ bias,
    __nv_bfloat16* __restrict__ res)
{
    __shared__ __align__(16) __nv_bfloat16 Qs[32 * QST];
    __shared__ __align__(16) __nv_bfloat16 Ks[32 * KST];
    __shared__ __align__(16) __nv_bfloat16 Vs[32 * KST];

    const int b = blockIdx.x, h = blockIdx.y;
    const int i0 = blockIdx.z * 128;
    const int tid = threadIdx.x, lane = tid & 31, w = tid >> 5;

    const __nv_bfloat16* qsrc = qb + ((size_t)b * 256 + h * 32) * HW_;
    const __nv_bfloat16* ksrc = kb + ((size_t)b * 256 + h * 32) * KHW_;
    const __nv_bfloat16* vsrc = vb + ((size_t)b * 256 + h * 32) * KHW_;

    // --- Q tile: [32 d][128 i] direct copy ---
    #pragma unroll
    for (int f = tid; f < 512; f += 256) {
        int d = f >> 4, ii = (f & 15) * 8;
        int gi = i0 + ii; if (gi > HW_ - 8) gi = HW_ - 8;
        *(uint4*)&Qs[d * QST + ii] = *(const uint4*)(qsrc + (size_t)d * HW_ + gi);
    }
    __syncthreads();

    // --- Q A-fragments (trans from [k][m]) ---
    uint32_t qa[2][4];
    {
        const uint32_t qbase = smem_u32(Qs);
        int krow = (lane & 7) + ((lane >> 4) & 1) * 8;
        int mcol = w * 16 + ((lane >> 3) & 1) * 8;
        #pragma unroll
        for (int kk = 0; kk < 2; kk++)
            ldm_x4_t(qa[kk], qbase + (uint32_t)(((kk * 16 + krow) * QST + mcol) * 2));
    }

    float m0 = -1e30f, m1 = -1e30f;
    float l0 = 0.f, l1 = 0.f;
    float oacc[4][4];
    #pragma unroll
    for (int nf = 0; nf < 4; nf++)
        #pragma unroll
        for (int r = 0; r < 4; r++) oacc[nf][r] = 0.f;

    const uint32_t kbase = smem_u32(Ks);
    const uint32_t vbase = smem_u32(Vs);
    const int browA = i0 + w * 16 + (lane >> 2);
    const int biasRowA = (browA < HW_) ? browA : HW_ - 1;
    const int biasRowB = (browA + 8 < HW_) ? browA + 8 : HW_ - 1;
    const float* biasA = bias + ((size_t)h * HW_ + biasRowA) * KHW_;
    const float* biasB = bias + ((size_t)h * HW_ + biasRowB) * KHW_;

    for (int jt = 0; jt < 13; jt++) {
        const int j0 = jt * 64;
        __syncthreads();
        // --- K,V tiles: [32 d][64 j] direct copy ---
        {
            int d = tid >> 3, jj = (tid & 7) * 8;
            int gj = j0 + jj; if (gj > KHW_ - 8) gj = KHW_ - 8;
            *(uint4*)&Ks[d * KST + jj] = *(const uint4*)(ksrc + (size_t)d * KHW_ + gj);
            *(uint4*)&Vs[d * KST + jj] = *(const uint4*)(vsrc + (size_t)d * KHW_ + gj);
        }
        __syncthreads();

        // --- S = Q @ K^T (K B-frags: trans from [k=d][n=j]) ---
        float s[8][4];
        #pragma unroll
        for (int nf = 0; nf < 8; nf++)
            #pragma unroll
            for (int r = 0; r < 4; r++) s[nf][r] = 0.f;

        #pragma unroll
        for (int kk = 0; kk < 2; kk++) {
            uint32_t kbf[8][2];
            int krow = (lane & 7) + ((lane >> 3) & 1) * 8;
            int ncol = ((lane >> 4) & 1) * 8;
            #pragma unroll
            for (int jg = 0; jg < 4; jg++) {
                uint32_t r4[4];
                ldm_x4_t(r4, kbase + (uint32_t)(((kk * 16 + krow) * KST + jg * 16 + ncol) * 2));
                kbf[2 * jg][0] = r4[0]; kbf[2 * jg][1] = r4[1];
                kbf[2 * jg + 1][0] = r4[2]; kbf[2 * jg + 1][1] = r4[3];
            }
            #pragma unroll
            for (int nf = 0; nf < 8; nf++) mma_bf16(s[nf], qa[kk], kbf[nf]);
        }

        // --- bias + mask + online softmax ---
        float rmax0 = -1e30f, rmax1 = -1e30f;
        #pragma unroll
        for (int nf = 0; nf < 8; nf++) {
            int gj = j0 + nf * 8 + (lane & 3) * 2;
            bool jv = (gj < KHW_);
            int gjc = jv ? gj : (KHW_ - 2);
            float2 bA = *(const float2*)(biasA + gjc);
            float2 bB = *(const float2*)(biasB + gjc);
            float v0 = s[nf][0] + bA.x, v1 = s[nf][1] + bA.y;
            float v2 = s[nf][2] + bB.x, v3 = s[nf][3] + bB.y;
            if (!jv) { v0 = v1 = v2 = v3 = -1e30f; }
            s[nf][0] = v0; s[nf][1] = v1; s[nf][2] = v2; s[nf][3] = v3;
            rmax0 = fmaxf(rmax0, fmaxf(v0, v1));
            rmax1 = fmaxf(rmax1, fmaxf(v2, v3));
        }
        #pragma unroll
        for (int o = 1; o <= 2; o <<= 1) {
            rmax0 = fmaxf(rmax0, __shfl_xor_sync(0xffffffffu, rmax0, o));
            rmax1 = fmaxf(rmax1, __shfl_xor_sync(0xffffffffu, rmax1, o));
        }
        float mn0 = fmaxf(m0, rmax0), mn1 = fmaxf(m1, rmax1);
        float al0 = __expf(m0 - mn0), al1 = __expf(m1 - mn1);
        m0 = mn0; m1 = mn1;

        float rs0 = 0.f, rs1 = 0.f;
        uint32_t pa[4][4];
        #pragma unroll
        for (int nf = 0; nf < 8; nf++) {
            float p0 = __expf(s[nf][0] - mn0);
            float p1 = __expf(s[nf][1] - mn0);
            float p2 = __expf(s[nf][2] - mn1);
            float p3 = __expf(s[nf][3] - mn1);
            rs0 += p0 + p1; rs1 += p2 + p3;
            pa[nf >> 1][(nf & 1) * 2 + 0] = pack_bf16x2(p0, p1);
            pa[nf >> 1][(nf & 1) * 2 + 1] = pack_bf16x2(p2, p3);
        }
        #pragma unroll
        for (int o = 1; o <= 2; o <<= 1) {
            rs0 += __shfl_xor_sync(0xffffffffu, rs0, o);
            rs1 += __shfl_xor_sync(0xffffffffu, rs1, o);
        }
        l0 = al0 * l0 + rs0;
        l1 = al1 * l1 + rs1;
        #pragma unroll
        for (int nf = 0; nf < 4; nf++) {
            oacc[nf][0] *= al0; oacc[nf][1] *= al0;
            oacc[nf][2] *= al1; oacc[nf][3] *= al1;
        }

        // --- O += P @ V  (V B-frags: non-trans from [n=d][k=j]) ---
        uint32_t vbf[4][4][2];
        {
            int rr = ((lane >> 3) & 1) * 8 + (lane & 7);
            int ch = (lane >> 4) & 1;
            #pragma unroll
            for (int ng = 0; ng < 2; ng++)
                #pragma unroll
                for (int kf = 0; kf < 4; kf++) {
                    uint32_t r4[4];
                    ldm_x4(r4, vbase + (uint32_t)(((ng * 16 + rr) * KST + kf * 16 + ch * 8) * 2));
                    vbf[2 * ng][kf][0] = r4[0]; vbf[2 * ng][kf][1] = r4[2];
                    vbf[2 * ng + 1][kf][0] = r4[1]; vbf[2 * ng + 1][kf][1] = r4[3];
                }
        }
        #pragma unroll
        for (int kf = 0; kf < 4; kf++)
            #pragma unroll
            for (int nf = 0; nf < 4; nf++)
                mma_bf16(oacc[nf], pa[kf], vbf[nf][kf]);
    }

    // --- epilogue: normalize + bf16 store to res[b][i][hd] ---
    float inv0 = 1.f / l0, inv1 = 1.f / l1;
    int giA = i0 + w * 16 + (lane >> 2);
    int giB = giA + 8;
    #pragma unroll
    for (int nf = 0; nf < 4; nf++) {
        int col = h * 32 + nf * 8 + (lane & 3) * 2;
        if (giA < HW_)
            *(__nv_bfloat162*)(res + ((size_t)(b * HW_ + giA)) * 256 + col) =
                __floats2bfloat162_rn(oacc[nf][0] * inv0, oacc[nf][1] * inv0);
        if (giB < HW_)
            *(__nv_bfloat162*)(res + ((size_t)(b * HW_ + giB)) * 256 + col) =
                __floats2bfloat162_rn(oacc[nf][2] * inv1, oacc[nf][3] * inv1);
    }
}

// ---------------------------------------------------------------------------
extern "C" void kernel_launch(void* const* d_in, const int* in_sizes, int n_in,
                              void* d_out, int out_size) {
    const float* x     = (const float*)d_in[0];
    const float* Wk_dw = (const float*)d_in[1];
    const float* bk_dw = (const float*)d_in[2];
    const float* Wv_dw = (const float*)d_in[3];
    const float* bv_dw = (const float*)d_in[4];
    const float* Wq    = (const float*)d_in[5];
    const float* bq    = (const float*)d_in[6];
    const float* Wk    = (const float*)d_in[7];
    const float* bk    = (const float*)d_in[8];
    const float* Wv    = (const float*)d_in[9];
    const float* bv    = (const float*)d_in[10];
    const float* Wo    = (const float*)d_in[11];
    const float* bo    = (const float*)d_in[12];
    const float* Bb    = (const float*)d_in[13];
    float* out = (float*)d_out;

    __nv_bfloat16 *qp, *kp, *vp, *resp;
    float *ckp, *cvp, *cqp;
    cudaGetSymbolAddress((void**)&qp,  g_q);
    cudaGetSymbolAddress((void**)&kp,  g_k);
    cudaGetSymbolAddress((void**)&vp,  g_v);
    cudaGetSymbolAddress((void**)&resp, g_res);
    cudaGetSymbolAddress((void**)&ckp, g_ck);
    cudaGetSymbolAddress((void**)&cvp, g_cv);
    cudaGetSymbolAddress((void**)&cqp, g_cq);

    stats_partial<<<1024, 256>>>(x);
    stats_final<<<1, 256>>>(Wq, bq);
    dwconv_kernel<<<(B_ * C_ * KHW_ + 255) / 256, 256>>>(x, Wk_dw, bk_dw, Wv_dw, bv_dw);

    gemm_wx<<<dim3(25, 2, B_), 256>>>(Wq, x,   cqp, 1, HW_,  qp);
    gemm_wx<<<dim3(7,  2, B_), 256>>>(Wk, ckp, bk,  0, KHW_, kp);
    gemm_wx<<<dim3(7,  2, B_), 256>>>(Wv, cvp, bv,  0, KHW_, vp);

    attn_mma_kernel<<<dim3(B_, HEADS_, 25), 256>>>(qp, kp, vp, Bb, resp);

    gemm_o<<<dim3(25, 2, B_), 256>>>(resp, Wo, bo, x, out);
}

// round 4
// speedup vs baseline: 13.4376x; 1.1249x over previous
#include <cuda_runtime.h>
#include <cuda_bf16.h>
#include <math.h>
#include <stdint.h>

// Problem constants
#define B_   8
#define C_   256
#define H_   56
#define W_   56
#define HW_  3136        // 56*56
#define KHW_ 784         // 28*28
#define HEADS_ 8
#define NTOT_ 6422528    // B*C*HW
#define EPS_ 1e-5
#define SCALE_ 0.17677669529663687f   // 1/sqrt(32)

// Scratch (static device arrays — allocation-free)
__device__ __nv_bfloat16 g_q[B_ * 256 * HW_];    // [b][hd][i]
__device__ __nv_bfloat16 g_k[B_ * 256 * KHW_];   // [b][hd][j]
__device__ __nv_bfloat16 g_v[B_ * 256 * KHW_];   // [b][hd][j]
__device__ __nv_bfloat16 g_res[B_ * HW_ * 256];  // [b][i][hd]
__device__ __nv_bfloat16 g_ck[B_ * C_ * KHW_];   // conv-K out bf16 [b][c][j]
__device__ __nv_bfloat16 g_cv[B_ * C_ * KHW_];
__device__ __nv_bfloat16 g_xbf[NTOT_];           // x in bf16 [b][c][hw]
__device__ __nv_bfloat16 g_wq[65536], g_wk[65536], g_wv[65536], g_wo[65536];
__device__ float g_part[2048];
__device__ float g_stats[2];                     // mu, rstd
__device__ float g_cq[256];                      // folded Q bias

// ---------------------------------------------------------------------------
// asm helpers
// ---------------------------------------------------------------------------
__device__ __forceinline__ uint32_t smem_u32(const void* p) {
    return (uint32_t)__cvta_generic_to_shared(p);
}
__device__ __forceinline__ void ldm_x4(uint32_t* r, uint32_t addr) {
    asm volatile("ldmatrix.sync.aligned.m8n8.x4.shared.b16 {%0,%1,%2,%3}, [%4];"
        : "=r"(r[0]), "=r"(r[1]), "=r"(r[2]), "=r"(r[3]) : "r"(addr));
}
__device__ __forceinline__ void ldm_x4_t(uint32_t* r, uint32_t addr) {
    asm volatile("ldmatrix.sync.aligned.m8n8.x4.trans.shared.b16 {%0,%1,%2,%3}, [%4];"
        : "=r"(r[0]), "=r"(r[1]), "=r"(r[2]), "=r"(r[3]) : "r"(addr));
}
__device__ __forceinline__ void mma_bf16(float* d, const uint32_t* a, const uint32_t* b) {
    asm volatile(
        "mma.sync.aligned.m16n8k16.row.col.f32.bf16.bf16.f32 "
        "{%0,%1,%2,%3}, {%4,%5,%6,%7}, {%8,%9}, {%0,%1,%2,%3};"
        : "+f"(d[0]), "+f"(d[1]), "+f"(d[2]), "+f"(d[3])
        : "r"(a[0]), "r"(a[1]), "r"(a[2]), "r"(a[3]), "r"(b[0]), "r"(b[1]));
}
__device__ __forceinline__ uint32_t pack_bf16x2(float lo, float hi) {
    uint32_t r;
    asm("cvt.rn.bf16x2.f32 %0, %1, %2;" : "=r"(r) : "f"(hi), "f"(lo));
    return r;
}
__device__ __forceinline__ void cp16(uint32_t dst, const void* src) {
    asm volatile("cp.async.cg.shared.global [%0], [%1], 16;" :: "r"(dst), "l"(src));
}
__device__ __forceinline__ void cp_commit() {
    asm volatile("cp.async.commit_group;" ::: "memory");
}
__device__ __forceinline__ void cp_wait_all() {
    asm volatile("cp.async.wait_group 0;" ::: "memory");
}

// ---------------------------------------------------------------------------
// Prep: bf16 conversions (identical rounding to previous in-GEMM converts)
// ---------------------------------------------------------------------------
__global__ void cvt_w_kernel(const float* __restrict__ Wq, const float* __restrict__ Wk,
                             const float* __restrict__ Wv, const float* __restrict__ Wo) {
    int i = blockIdx.x * 256 + threadIdx.x;
    g_wq[i] = __float2bfloat16(Wq[i]);
    g_wk[i] = __float2bfloat16(Wk[i]);
    g_wv[i] = __float2bfloat16(Wv[i]);
    g_wo[i] = __float2bfloat16(Wo[i]);
}
__global__ void cvt_x_kernel(const float* __restrict__ x) {
    int i = blockIdx.x * 256 + threadIdx.x;   // NTOT/4 threads
    float4 v = ((const float4*)x)[i];
    __nv_bfloat162* o = (__nv_bfloat162*)(g_xbf + (size_t)i * 4);
    o[0] = __floats2bfloat162_rn(v.x, v.y);
    o[1] = __floats2bfloat162_rn(v.z, v.w);
}

// ---------------------------------------------------------------------------
// Stage 1: partial sums for global layernorm stats
// ---------------------------------------------------------------------------
__global__ void stats_partial(const float* __restrict__ x) {
    int tid = threadIdx.x;
    int gid = blockIdx.x * 256 + tid;
    const float4* x4 = (const float4*)x;
    float s = 0.f, ss = 0.f;
    for (int i = gid; i < NTOT_ / 4; i += 1024 * 256) {
        float4 v = x4[i];
        s  += v.x + v.y + v.z + v.w;
        ss += v.x * v.x + v.y * v.y + v.z * v.z + v.w * v.w;
    }
    #pragma unroll
    for (int o = 16; o; o >>= 1) {
        s  += __shfl_xor_sync(0xffffffffu, s, o);
        ss += __shfl_xor_sync(0xffffffffu, ss, o);
    }
    __shared__ float sh[16];
    int w = tid >> 5, lane = tid & 31;
    if (lane == 0) { sh[w] = s; sh[8 + w] = ss; }
    __syncthreads();
    if (tid == 0) {
        float a = 0.f, b = 0.f;
        #pragma unroll
        for (int i = 0; i < 8; i++) { a += sh[i]; b += sh[8 + i]; }
        g_part[blockIdx.x] = a;
        g_part[1024 + blockIdx.x] = b;
    }
}

// ---------------------------------------------------------------------------
// Stage 2: finalize mu/rstd, fold LN into Q bias: cq = bq - rstd*mu*rowsum(Wq)
// ---------------------------------------------------------------------------
__global__ void stats_final(const float* __restrict__ Wq, const float* __restrict__ bq) {
    int tid = threadIdx.x;
    double s = 0.0, ss = 0.0;
    for (int i = tid; i < 1024; i += 256) {
        s  += (double)g_part[i];
        ss += (double)g_part[1024 + i];
    }
    __shared__ double shs[256], shss[256];
    shs[tid] = s; shss[tid] = ss;
    __syncthreads();
    for (int o = 128; o; o >>= 1) {
        if (tid < o) { shs[tid] += shs[tid + o]; shss[tid] += shss[tid + o]; }
        __syncthreads();
    }
    __shared__ float mu_s, rstd_s;
    if (tid == 0) {
        double N = (double)NTOT_;
        double mu = shs[0] / N;
        double var = shss[0] / N - mu * mu;
        float rstd = (float)(1.0 / sqrt(var + EPS_));
        g_stats[0] = (float)mu;
        g_stats[1] = rstd;
        mu_s = (float)mu; rstd_s = rstd;
    }
    __syncthreads();
    float rs = 0.f;
    const float* wrow = Wq + (size_t)tid * 256;
    for (int k = 0; k < 256; k++) rs += wrow[k];
    g_cq[tid] = bq[tid] - rstd_s * mu_s * rs;
}

// ---------------------------------------------------------------------------
// Depthwise 3x3 stride-2 conv (K and V paths fused), bf16 output
// ---------------------------------------------------------------------------
__global__ void dwconv_kernel(const float* __restrict__ x,
                              const float* __restrict__ wk, const float* __restrict__ bkd,
                              const float* __restrict__ wv, const float* __restrict__ bvd) {
    int idx = blockIdx.x * blockDim.x + threadIdx.x;
    if (idx >= B_ * C_ * KHW_) return;
    int ox = idx % 28;
    int oy = (idx / 28) % 28;
    int c  = (idx / KHW_) % C_;
    int b  = idx / (KHW_ * C_);
    const float* xp = x + ((size_t)(b * C_ + c)) * HW_;
    float ak = 0.f, av = 0.f;
    #pragma unroll
    for (int ky = 0; ky < 3; ky++) {
        int iy = oy * 2 + ky - 1;
        if (iy < 0 || iy >= H_) continue;
        #pragma unroll
        for (int kx = 0; kx < 3; kx++) {
            int ix = ox * 2 + kx - 1;
            if (ix < 0 || ix >= W_) continue;
            float xv = xp[iy * W_ + ix];
            ak += xv * wk[c * 9 + ky * 3 + kx];
            av += xv * wv[c * 9 + ky * 3 + kx];
        }
    }
    g_ck[idx] = __float2bfloat16(ak + bkd[c]);
    g_cv[idx] = __float2bfloat16(av + bvd[c]);
}

// ---------------------------------------------------------------------------
// bf16 mma GEMM (2-stage cp.async): out[b][R][P] = a1*sum_k W[R][k]*X[b][k][P]
//   + a2*cvec[R].  W bf16 [256][256], X bf16 [b][256][Mt], out bf16.
// ---------------------------------------------------------------------------
#define WST 40
#define XST 136
__global__ void __launch_bounds__(256, 2) gemm_wx(
    const __nv_bfloat16* __restrict__ W, const __nv_bfloat16* __restrict__ X,
    const float* __restrict__ cvec, int isQ, int Mt,
    __nv_bfloat16* __restrict__ out)
{
    __shared__ __align__(16) __nv_bfloat16 Ws[2][128 * WST];
    __shared__ __align__(16) __nv_bfloat16 Xs[2][32 * XST];
    const int P0 = blockIdx.x * 128;
    const int R0 = blockIdx.y * 128;
    const int b  = blockIdx.z;
    const __nv_bfloat16* Xb = X + (size_t)b * 256 * Mt;
    const int tid = threadIdx.x, lane = tid & 31, w = tid >> 5;
    const int wR = (w >> 2) * 64, wP = (w & 3) * 32;

    float c[4][4][4];
    #pragma unroll
    for (int i = 0; i < 4; i++)
        #pragma unroll
        for (int j = 0; j < 4; j++)
            #pragma unroll
            for (int r = 0; r < 4; r++) c[i][j][r] = 0.f;

    const uint32_t wsb = smem_u32(Ws), xsb = smem_u32(Xs);

    // tile-load into stage buffer
    auto load_stage = [&](int k0, int buf) {
        uint32_t wd = wsb + buf * (128 * WST * 2);
        uint32_t xd = xsb + buf * (32 * XST * 2);
        #pragma unroll
        for (int t = 0; t < 2; t++) {
            int f = tid + t * 256;                  // f < 512
            int r = f >> 2, cc = (f & 3) * 8;
            cp16(wd + (uint32_t)((r * WST + cc) * 2),
                 W + (size_t)(R0 + r) * 256 + k0 + cc);
        }
        #pragma unroll
        for (int t = 0; t < 2; t++) {
            int f = tid + t * 256;
            int kk = f >> 4, p = (f & 15) * 8;
            int gp = P0 + p; if (gp > Mt - 8) gp = Mt - 8;
            cp16(xd + (uint32_t)((kk * XST + p) * 2),
                 Xb + (size_t)(k0 + kk) * Mt + gp);
        }
    };

    load_stage(0, 0);
    cp_commit();

    for (int s = 0; s < 8; s++) {
        cp_wait_all();
        __syncthreads();
        if (s + 1 < 8) { load_stage((s + 1) * 32, (s + 1) & 1); cp_commit(); }
        const int buf = s & 1;
        const uint32_t wb = wsb + buf * (128 * WST * 2);
        const uint32_t xb = xsb + buf * (32 * XST * 2);

        #pragma unroll
        for (int kk = 0; kk < 2; kk++) {
            uint32_t af[4][4], bf[4][2];
            {
                int rr = ((lane >> 3) & 1) * 8 + (lane & 7);
                int ch = (lane >> 4) & 1;
                #pragma unroll
                for (int rf = 0; rf < 4; rf++)
                    ldm_x4(af[rf], wb + (uint32_t)(((wR + rf * 16 + rr) * WST + kk * 16 + ch * 8) * 2));
            }
            {
                int krow = (lane & 7) + ((lane >> 3) & 1) * 8;
                int pc = ((lane >> 4) & 1) * 8;
                #pragma unroll
                for (int pf = 0; pf < 2; pf++) {
                    uint32_t r4[4];
                    ldm_x4_t(r4, xb + (uint32_t)(((kk * 16 + krow) * XST + wP + pf * 16 + pc) * 2));
                    bf[2 * pf][0] = r4[0]; bf[2 * pf][1] = r4[1];
                    bf[2 * pf + 1][0] = r4[2]; bf[2 * pf + 1][1] = r4[3];
                }
            }
            #pragma unroll
            for (int rf = 0; rf < 4; rf++)
                #pragma unroll
                for (int pg = 0; pg < 4; pg++)
                    mma_bf16(c[rf][pg], af[rf], bf[pg]);
        }
        __syncthreads();
    }

    float a1 = 1.f, a2 = 1.f;
    if (isQ) { a1 = g_stats[1] * SCALE_; a2 = SCALE_; }
    __nv_bfloat16* ob = out + (size_t)b * 256 * Mt;
    #pragma unroll
    for (int rf = 0; rf < 4; rf++) {
        int R = R0 + wR + rf * 16 + (lane >> 2);
        float cv1 = a2 * cvec[R], cv2 = a2 * cvec[R + 8];
        #pragma unroll
        for (int pg = 0; pg < 4; pg++) {
            int P = P0 + wP + pg * 8 + (lane & 3) * 2;
            if (P < Mt) {
                *(__nv_bfloat162*)(ob + (size_t)R * Mt + P) =
                    __floats2bfloat162_rn(a1 * c[rf][pg][0] + cv1, a1 * c[rf][pg][1] + cv1);
                *(__nv_bfloat162*)(ob + (size_t)(R + 8) * Mt + P) =
                    __floats2bfloat162_rn(a1 * c[rf][pg][2] + cv2, a1 * c[rf][pg][3] + cv2);
            }
        }
    }
}

// ---------------------------------------------------------------------------
// O projection mma GEMM (2-stage cp.async) + fused bias + flat residual add:
//   out.flat[b, i*256+n] = res_bf16[b][i][:] @ Wo[n][:] + bo[n] + x.flat
// ---------------------------------------------------------------------------
__global__ void __launch_bounds__(256, 2) gemm_o(
    const __nv_bfloat16* __restrict__ A, const __nv_bfloat16* __restrict__ Wo,
    const float* __restrict__ bo, const float* __restrict__ x,
    float* __restrict__ out)
{
    __shared__ __align__(16) __nv_bfloat16 As[2][128 * WST];
    __shared__ __align__(16) __nv_bfloat16 Bs[2][128 * WST];
    const int I0 = blockIdx.x * 128;
    const int N0 = blockIdx.y * 128;
    const int b  = blockIdx.z;
    const int tid = threadIdx.x, lane = tid & 31, w = tid >> 5;
    const int wI = (w >> 2) * 64, wN = (w & 3) * 32;

    float c[4][4][4];
    #pragma unroll
    for (int i = 0; i < 4; i++)
        #pragma unroll
        for (int j = 0; j < 4; j++)
            #pragma unroll
            for (int r = 0; r < 4; r++) c[i][j][r] = 0.f;

    const uint32_t asb = smem_u32(As), bsb = smem_u32(Bs);

    auto load_stage = [&](int k0, int buf) {
        uint32_t ad = asb + buf * (128 * WST * 2);
        uint32_t bd = bsb + buf * (128 * WST * 2);
        #pragma unroll
        for (int t = 0; t < 2; t++) {
            int f = tid + t * 256;
            int i = f >> 2, cc = (f & 3) * 8;
            int gi = I0 + i; if (gi > HW_ - 1) gi = HW_ - 1;
            cp16(ad + (uint32_t)((i * WST + cc) * 2),
                 A + ((size_t)(b * HW_) + gi) * 256 + k0 + cc);
        }
        #pragma unroll
        for (int t = 0; t < 2; t++) {
            int f = tid + t * 256;
            int n = f >> 2, cc = (f & 3) * 8;
            cp16(bd + (uint32_t)((n * WST + cc) * 2),
                 Wo + (size_t)(N0 + n) * 256 + k0 + cc);
        }
    };

    load_stage(0, 0);
    cp_commit();

    for (int s = 0; s < 8; s++) {
        cp_wait_all();
        __syncthreads();
        if (s + 1 < 8) { load_stage((s + 1) * 32, (s + 1) & 1); cp_commit(); }
        const int buf = s & 1;
        const uint32_t ab = asb + buf * (128 * WST * 2);
        const uint32_t bb = bsb + buf * (128 * WST * 2);

        #pragma unroll
        for (int kk = 0; kk < 2; kk++) {
            int rr = ((lane >> 3) & 1) * 8 + (lane & 7);
            int ch = (lane >> 4) & 1;
            uint32_t af[4][4], bf[4][2];
            #pragma unroll
            for (int mf = 0; mf < 4; mf++)
                ldm_x4(af[mf], ab + (uint32_t)(((wI + mf * 16 + rr) * WST + kk * 16 + ch * 8) * 2));
            #pragma unroll
            for (int ng = 0; ng < 2; ng++) {
                uint32_t r4[4];
                ldm_x4(r4, bb + (uint32_t)(((wN + ng * 16 + rr) * WST + kk * 16 + ch * 8) * 2));
                bf[2 * ng][0] = r4[0]; bf[2 * ng][1] = r4[2];
                bf[2 * ng + 1][0] = r4[1]; bf[2 * ng + 1][1] = r4[3];
            }
            #pragma unroll
            for (int mf = 0; mf < 4; mf++)
                #pragma unroll
                for (int nf = 0; nf < 4; nf++)
                    mma_bf16(c[mf][nf], af[mf], bf[nf]);
        }
        __syncthreads();
    }

    #pragma unroll
    for (int mf = 0; mf < 4; mf++) {
        int i1 = I0 + wI + mf * 16 + (lane >> 2);
        int i2 = i1 + 8;
        #pragma unroll
        for (int nf = 0; nf < 4; nf++) {
            int n = N0 + wN + nf * 8 + (lane & 3) * 2;
            float b0v = bo[n], b1v = bo[n + 1];
            if (i1 < HW_) {
                size_t flat = (size_t)b * (256 * HW_) + (size_t)i1 * 256 + n;
                float2 xv = *(const float2*)(x + flat);
                *(float2*)(out + flat) =
                    make_float2(c[mf][nf][0] + b0v + xv.x, c[mf][nf][1] + b1v + xv.y);
            }
            if (i2 < HW_) {
                size_t flat = (size_t)b * (256 * HW_) + (size_t)i2 * 256 + n;
                float2 xv = *(const float2*)(x + flat);
                *(float2*)(out + flat) =
                    make_float2(c[mf][nf][2] + b0v + xv.x, c[mf][nf][3] + b1v + xv.y);
            }
        }
    }
}

// ---------------------------------------------------------------------------
// bf16 flash attention with 2-stage cp.async pipeline for K/V AND bias.
// Dynamic smem layout (per block, 100864 B):
//   [0)      Qs   32 x 136 bf16   (8704)
//   [8704)   Ks   2 x 32 x 72 bf16 (9216)
//   [17920)  Vs   2 x 32 x 72 bf16 (9216)
//   [27136)  Bias 2 x 128 x 72 f32 (73728)  — stride 72 = conflict-free
// ---------------------------------------------------------------------------
#define QST 136
#define KST 72
#define BST 72
#define ATT_SMEM 100864
#define KVBUF (32 * KST * 2)      // bytes per K or V stage
#define BBUF  (128 * BST * 4)     // bytes per bias stage

__global__ void __launch_bounds__(256, 2) attn_mma_kernel(
    const __nv_bfloat16* __restrict__ qb, const __nv_bfloat16* __restrict__ kb,
    const __nv_bfloat16* __restrict__ vb, const float* __restrict__ bias,
    __nv_bfloat16* __restrict__ res)
{
    extern __shared__ __align__(16) char smraw[];
    __nv_bfloat16* Qs = (__nv_bfloat16*)smraw;
    float* BiasS = (float*)(smraw + 27136);

    const int b = blockIdx.x, h = blockIdx.y;
    const int i0 = blockIdx.z * 128;
    const int tid = threadIdx.x, lane = tid & 31, w = tid >> 5;

    const __nv_bfloat16* qsrc = qb + ((size_t)b * 256 + h * 32) * HW_;
    const __nv_bfloat16* ksrc = kb + ((size_t)b * 256 + h * 32) * KHW_;
    const __nv_bfloat16* vsrc = vb + ((size_t)b * 256 + h * 32) * KHW_;
    const float* bias_h = bias + (size_t)h * HW_ * KHW_;

    const uint32_t qbase = smem_u32(smraw);
    const uint32_t kbase0 = qbase + 8704;
    const uint32_t vbase0 = qbase + 17920;
    const uint32_t bbase0 = qbase + 27136;

    // --- Q tile: [32 d][128 i] direct copy ---
    #pragma unroll
    for (int f = tid; f < 512; f += 256) {
        int d = f >> 4, ii = (f & 15) * 8;
        int gi = i0 + ii; if (gi > HW_ - 8) gi = HW_ - 8;
        *(uint4*)&Qs[d * QST + ii] = *(const uint4*)(qsrc + (size_t)d * HW_ + gi);
    }

    // tile loader (K, V, bias) via cp.async
    auto load_tile = [&](int j0, int buf) {
        {
            int d = tid >> 3, jj = (tid & 7) * 8;
            int gj = j0 + jj; if (gj > KHW_ - 8) gj = KHW_ - 8;
            cp16(kbase0 + buf * KVBUF + (uint32_t)((d * KST + jj) * 2),
                 ksrc + (size_t)d * KHW_ + gj);
            cp16(vbase0 + buf * KVBUF + (uint32_t)((d * KST + jj) * 2),
                 vsrc + (size_t)d * KHW_ + gj);
        }
        #pragma unroll
        for (int t = 0; t < 8; t++) {
            int f = tid + t * 256;                 // f < 2048
            int r = f >> 4, c4 = (f & 15) * 4;
            int gr = i0 + r; if (gr > HW_ - 1) gr = HW_ - 1;
            int gc = j0 + c4; if (gc > KHW_ - 4) gc = KHW_ - 4;
            cp16(bbase0 + buf * BBUF + (uint32_t)((r * BST + c4) * 4),
                 bias_h + (size_t)gr * KHW_ + gc);
        }
    };

    load_tile(0, 0);
    cp_commit();
    __syncthreads();   // Q tile visible

    // --- Q A-fragments (trans from [k][m]) ---
    uint32_t qa[2][4];
    {
        int krow = (lane & 7) + ((lane >> 4) & 1) * 8;
        int mcol = w * 16 + ((lane >> 3) & 1) * 8;
        #pragma unroll
        for (int kk = 0; kk < 2; kk++)
            ldm_x4_t(qa[kk], qbase + (uint32_t)(((kk * 16 + krow) * QST + mcol) * 2));
    }

    float m0 = -1e30f, m1 = -1e30f;
    float l0 = 0.f, l1 = 0.f;
    float oacc[4][4];
    #pragma unroll
    for (int nf = 0; nf < 4; nf++)
        #pragma unroll
        for (int r = 0; r < 4; r++) oacc[nf][r] = 0.f;

    const int rA = w * 16 + (lane >> 2);    // local bias rows for this thread
    const int rB = rA + 8;

    for (int jt = 0; jt < 13; jt++) {
        const int j0 = jt * 64;
        cp_wait_all();
        __syncthreads();
        if (jt + 1 < 13) { load_tile((jt + 1) * 64, (jt + 1) & 1); cp_commit(); }

        const int buf = jt & 1;
        const uint32_t kbase = kbase0 + buf * KVBUF;
        const uint32_t vbase = vbase0 + buf * KVBUF;
        const float* bsm = BiasS + buf * (128 * BST);

        // --- S = Q @ K^T (K B-frags: trans from [k=d][n=j]) ---
        float s[8][4];
        #pragma unroll
        for (int nf = 0; nf < 8; nf++)
            #pragma unroll
            for (int r = 0; r < 4; r++) s[nf][r] = 0.f;

        #pragma unroll
        for (int kk = 0; kk < 2; kk++) {
            uint32_t kbf[8][2];
            int krow = (lane & 7) + ((lane >> 3) & 1) * 8;
            int ncol = ((lane >> 4) & 1) * 8;
            #pragma unroll
            for (int jg = 0; jg < 4; jg++) {
                uint32_t r4[4];
                ldm_x4_t(r4, kbase + (uint32_t)(((kk * 16 + krow) * KST + jg * 16 + ncol) * 2));
                kbf[2 * jg][0] = r4[0]; kbf[2 * jg][1] = r4[1];
                kbf[2 * jg + 1][0] = r4[2]; kbf[2 * jg + 1][1] = r4[3];
            }
            #pragma unroll
            for (int nf = 0; nf < 8; nf++) mma_bf16(s[nf], qa[kk], kbf[nf]);
        }

        // --- bias (from smem) + mask + online softmax ---
        float rmax0 = -1e30f, rmax1 = -1e30f;
        #pragma unroll
        for (int nf = 0; nf < 8; nf++) {
            int cj = nf * 8 + (lane & 3) * 2;
            int gj = j0 + cj;
            bool jv = (gj < KHW_);
            float2 bA = *(const float2*)(bsm + rA * BST + cj);
            float2 bB = *(const float2*)(bsm + rB * BST + cj);
            float v0 = s[nf][0] + bA.x, v1 = s[nf][1] + bA.y;
            float v2 = s[nf][2] + bB.x, v3 = s[nf][3] + bB.y;
            if (!jv) { v0 = v1 = v2 = v3 = -1e30f; }
            s[nf][0] = v0; s[nf][1] = v1; s[nf][2] = v2; s[nf][3] = v3;
            rmax0 = fmaxf(rmax0, fmaxf(v0, v1));
            rmax1 = fmaxf(rmax1, fmaxf(v2, v3));
        }
        #pragma unroll
        for (int o = 1; o <= 2; o <<= 1) {
            rmax0 = fmaxf(rmax0, __shfl_xor_sync(0xffffffffu, rmax0, o));
            rmax1 = fmaxf(rmax1, __shfl_xor_sync(0xffffffffu, rmax1, o));
        }
        float mn0 = fmaxf(m0, rmax0), mn1 = fmaxf(m1, rmax1);
        float al0 = __expf(m0 - mn0), al1 = __expf(m1 - mn1);
        m0 = mn0; m1 = mn1;

        float rs0 = 0.f, rs1 = 0.f;
        uint32_t pa[4][4];
        #pragma unroll
        for (int nf = 0; nf < 8; nf++) {
            float p0 = __expf(s[nf][0] - mn0);
            float p1 = __expf(s[nf][1] - mn0);
            float p2 = __expf(s[nf][2] - mn1);
            float p3 = __expf(s[nf][3] - mn1);
            rs0 += p0 + p1; rs1 += p2 + p3;
            pa[nf >> 1][(nf & 1) * 2 + 0] = pack_bf16x2(p0, p1);
            pa[nf >> 1][(nf & 1) * 2 + 1] = pack_bf16x2(p2, p3);
        }
        #pragma unroll
        for (int o = 1; o <= 2; o <<= 1) {
            rs0 += __shfl_xor_sync(0xffffffffu, rs0, o);
            rs1 += __shfl_xor_sync(0xffffffffu, rs1, o);
        }
        l0 = al0 * l0 + rs0;
        l1 = al1 * l1 + rs1;
        #pragma unroll
        for (int nf = 0; nf < 4; nf++) {
            oacc[nf][0] *= al0; oacc[nf][1] *= al0;
            oacc[nf][2] *= al1; oacc[nf][3] *= al1;
        }

        // --- O += P @ V  (V B-frags: non-trans from [n=d][k=j]) ---
        uint32_t vbf[4][4][2];
        {
            int rr = ((lane >> 3) & 1) * 8 + (lane & 7);
            int ch = (lane >> 4) & 1;
            #pragma unroll
            for (int ng = 0; ng < 2; ng++)
                #pragma unroll
                for (int kf = 0; kf < 4; kf++) {
                    uint32_t r4[4];
                    ldm_x4(r4, vbase + (uint32_t)(((ng * 16 + rr) * KST + kf * 16 + ch * 8) * 2));
                    vbf[2 * ng][kf][0] = r4[0]; vbf[2 * ng][kf][1] = r4[2];
                    vbf[2 * ng + 1][kf][0] = r4[1]; vbf[2 * ng + 1][kf][1] = r4[3];
                }
        }
        #pragma unroll
        for (int kf = 0; kf < 4; kf++)
            #pragma unroll
            for (int nf = 0; nf < 4; nf++)
                mma_bf16(oacc[nf], pa[kf], vbf[nf][kf]);
    }

    // --- epilogue: normalize + bf16 store to res[b][i][hd] ---
    float inv0 = 1.f / l0, inv1 = 1.f / l1;
    int giA = i0 + w * 16 + (lane >> 2);
    int giB = giA + 8;
    #pragma unroll
    for (int nf = 0; nf < 4; nf++) {
        int col = h * 32 + nf * 8 + (lane & 3) * 2;
        if (giA < HW_)
            *(__nv_bfloat162*)(res + ((size_t)(b * HW_ + giA)) * 256 + col) =
                __floats2bfloat162_rn(oacc[nf][0] * inv0, oacc[nf][1] * inv0);
        if (giB < HW_)
            *(__nv_bfloat162*)(res + ((size_t)(b * HW_ + giB)) * 256 + col) =
                __floats2bfloat162_rn(oacc[nf][2] * inv1, oacc[nf][3] * inv1);
    }
}

// ---------------------------------------------------------------------------
extern "C" void kernel_launch(void* const* d_in, const int* in_sizes, int n_in,
                              void* d_out, int out_size) {
    const float* x     = (const float*)d_in[0];
    const float* Wk_dw = (const float*)d_in[1];
    const float* bk_dw = (const float*)d_in[2];
    const float* Wv_dw = (const float*)d_in[3];
    const float* bv_dw = (const float*)d_in[4];
    const float* Wq    = (const float*)d_in[5];
    const float* bq    = (const float*)d_in[6];
    const float* Wk    = (const float*)d_in[7];
    const float* bk    = (const float*)d_in[8];
    const float* Wv    = (const float*)d_in[9];
    const float* bv    = (const float*)d_in[10];
    const float* Wo    = (const float*)d_in[11];
    const float* bo    = (const float*)d_in[12];
    const float* Bb    = (const float*)d_in[13];
    float* out = (float*)d_out;

    __nv_bfloat16 *qp, *kp, *vp, *resp, *ckp, *cvp, *xbfp;
    __nv_bfloat16 *wqp, *wkp, *wvp, *wop;
    float *cqp;
    cudaGetSymbolAddress((void**)&qp,   g_q);
    cudaGetSymbolAddress((void**)&kp,   g_k);
    cudaGetSymbolAddress((void**)&vp,   g_v);
    cudaGetSymbolAddress((void**)&resp, g_res);
    cudaGetSymbolAddress((void**)&ckp,  g_ck);
    cudaGetSymbolAddress((void**)&cvp,  g_cv);
    cudaGetSymbolAddress((void**)&xbfp, g_xbf);
    cudaGetSymbolAddress((void**)&wqp,  g_wq);
    cudaGetSymbolAddress((void**)&wkp,  g_wk);
    cudaGetSymbolAddress((void**)&wvp,  g_wv);
    cudaGetSymbolAddress((void**)&wop,  g_wo);
    cudaGetSymbolAddress((void**)&cqp,  g_cq);

    cudaFuncSetAttribute(attn_mma_kernel,
                         cudaFuncAttributeMaxDynamicSharedMemorySize, ATT_SMEM);

    cvt_x_kernel<<<NTOT_ / 4 / 256, 256>>>(x);
    cvt_w_kernel<<<256, 256>>>(Wq, Wk, Wv, Wo);
    stats_partial<<<1024, 256>>>(x);
    stats_final<<<1, 256>>>(Wq, bq);
    dwconv_kernel<<<(B_ * C_ * KHW_ + 255) / 256, 256>>>(x, Wk_dw, bk_dw, Wv_dw, bv_dw);

    gemm_wx<<<dim3(25, 2, B_), 256>>>(wqp, xbfp, cqp, 1, HW_,  qp);
    gemm_wx<<<dim3(7,  2, B_), 256>>>(wkp, ckp,  bk,  0, KHW_, kp);
    gemm_wx<<<dim3(7,  2, B_), 256>>>(wvp, cvp,  bv,  0, KHW_, vp);

    attn_mma_kernel<<<dim3(B_, HEADS_, 25), 256, ATT_SMEM>>>(qp, kp, vp, Bb, resp);

    gemm_o<<<dim3(25, 2, B_), 256>>>(resp, wop, bo, x, out);
}

// round 5
// speedup vs baseline: 13.8049x; 1.0273x over previous
#include <cuda_runtime.h>
#include <cuda_bf16.h>
#include <math.h>
#include <stdint.h>

// Problem constants
#define B_   8
#define C_   256
#define H_   56
#define W_   56
#define HW_  3136        // 56*56
#define KHW_ 784         // 28*28
#define HEADS_ 8
#define NTOT_ 6422528    // B*C*HW
#define NPART_ 6272      // NTOT/4/256 blocks in fused cvt+stats
#define BIASN_ 19668992  // HEADS*HW*KHW
#define EPS_ 1e-5
#define SCALE_ 0.17677669529663687f   // 1/sqrt(32)

// Scratch (static device arrays — allocation-free)
__device__ __nv_bfloat16 g_q[B_ * 256 * HW_];    // [b][hd][i]
__device__ __nv_bfloat16 g_k[B_ * 256 * KHW_];   // [b][hd][j]
__device__ __nv_bfloat16 g_v[B_ * 256 * KHW_];   // [b][hd][j]
__device__ __nv_bfloat16 g_res[B_ * HW_ * 256];  // [b][i][hd]
__device__ __nv_bfloat16 g_ck[B_ * C_ * KHW_];   // conv-K out bf16 [b][c][j]
__device__ __nv_bfloat16 g_cv[B_ * C_ * KHW_];
__device__ __nv_bfloat16 g_xbf[NTOT_];           // x in bf16 [b][c][hw]
__device__ __nv_bfloat16 g_bbf[BIASN_];          // bias in bf16
__device__ __nv_bfloat16 g_wq[65536], g_wk[65536], g_wv[65536], g_wo[65536];
__device__ float g_part[2 * NPART_];
__device__ float g_wqsum[256];
__device__ float g_stats[2];                     // mu, rstd
__device__ float g_cq[256];                      // folded Q bias

// ---------------------------------------------------------------------------
// asm helpers
// ---------------------------------------------------------------------------
__device__ __forceinline__ uint32_t smem_u32(const void* p) {
    return (uint32_t)__cvta_generic_to_shared(p);
}
__device__ __forceinline__ void ldm_x4(uint32_t* r, uint32_t addr) {
    asm volatile("ldmatrix.sync.aligned.m8n8.x4.shared.b16 {%0,%1,%2,%3}, [%4];"
        : "=r"(r[0]), "=r"(r[1]), "=r"(r[2]), "=r"(r[3]) : "r"(addr));
}
__device__ __forceinline__ void ldm_x4_t(uint32_t* r, uint32_t addr) {
    asm volatile("ldmatrix.sync.aligned.m8n8.x4.trans.shared.b16 {%0,%1,%2,%3}, [%4];"
        : "=r"(r[0]), "=r"(r[1]), "=r"(r[2]), "=r"(r[3]) : "r"(addr));
}
__device__ __forceinline__ void mma_bf16(float* d, const uint32_t* a, const uint32_t* b) {
    asm volatile(
        "mma.sync.aligned.m16n8k16.row.col.f32.bf16.bf16.f32 "
        "{%0,%1,%2,%3}, {%4,%5,%6,%7}, {%8,%9}, {%0,%1,%2,%3};"
        : "+f"(d[0]), "+f"(d[1]), "+f"(d[2]), "+f"(d[3])
        : "r"(a[0]), "r"(a[1]), "r"(a[2]), "r"(a[3]), "r"(b[0]), "r"(b[1]));
}
__device__ __forceinline__ uint32_t pack_bf16x2(float lo, float hi) {
    uint32_t r;
    asm("cvt.rn.bf16x2.f32 %0, %1, %2;" : "=r"(r) : "f"(hi), "f"(lo));
    return r;
}
__device__ __forceinline__ void cp16(uint32_t dst, const void* src) {
    asm volatile("cp.async.cg.shared.global [%0], [%1], 16;" :: "r"(dst), "l"(src));
}
__device__ __forceinline__ void cp_commit() {
    asm volatile("cp.async.commit_group;" ::: "memory");
}
__device__ __forceinline__ void cp_wait_all() {
    asm volatile("cp.async.wait_group 0;" ::: "memory");
}

// ---------------------------------------------------------------------------
// Fused: x fp32 -> bf16 + LN partial sums (x read ONCE)
// ---------------------------------------------------------------------------
__global__ void cvt_x_stats(const float* __restrict__ x) {
    int tid = threadIdx.x;
    int i = blockIdx.x * 256 + tid;            // group of 4 floats
    float4 v = ((const float4*)x)[i];
    __nv_bfloat162* o = (__nv_bfloat162*)(g_xbf + (size_t)i * 4);
    o[0] = __floats2bfloat162_rn(v.x, v.y);
    o[1] = __floats2bfloat162_rn(v.z, v.w);
    float s  = v.x + v.y + v.z + v.w;
    float ss = v.x * v.x + v.y * v.y + v.z * v.z + v.w * v.w;
    #pragma unroll
    for (int ofs = 16; ofs; ofs >>= 1) {
        s  += __shfl_xor_sync(0xffffffffu, s, ofs);
        ss += __shfl_xor_sync(0xffffffffu, ss, ofs);
    }
    __shared__ float sh[16];
    int w = tid >> 5, lane = tid & 31;
    if (lane == 0) { sh[w] = s; sh[8 + w] = ss; }
    __syncthreads();
    if (tid == 0) {
        float a = 0.f, b = 0.f;
        #pragma unroll
        for (int k = 0; k < 8; k++) { a += sh[k]; b += sh[8 + k]; }
        g_part[blockIdx.x] = a;
        g_part[NPART_ + blockIdx.x] = b;
    }
}

// ---------------------------------------------------------------------------
// Weight conversions + Wq rowsum (block r reduces row r of Wq)
// ---------------------------------------------------------------------------
__global__ void cvt_w_kernel(const float* __restrict__ Wq, const float* __restrict__ Wk,
                             const float* __restrict__ Wv, const float* __restrict__ Wo) {
    int r = blockIdx.x, tid = threadIdx.x;
    int i = r * 256 + tid;
    float wq = Wq[i];
    g_wq[i] = __float2bfloat16(wq);
    g_wk[i] = __float2bfloat16(Wk[i]);
    g_wv[i] = __float2bfloat16(Wv[i]);
    g_wo[i] = __float2bfloat16(Wo[i]);
    float s = wq;
    #pragma unroll
    for (int ofs = 16; ofs; ofs >>= 1) s += __shfl_xor_sync(0xffffffffu, s, ofs);
    __shared__ float sh[8];
    if ((tid & 31) == 0) sh[tid >> 5] = s;
    __syncthreads();
    if (tid == 0) {
        float a = 0.f;
        #pragma unroll
        for (int k = 0; k < 8; k++) a += sh[k];
        g_wqsum[r] = a;
    }
}

// ---------------------------------------------------------------------------
// Bias fp32 -> bf16
// ---------------------------------------------------------------------------
__global__ void cvt_bias(const float* __restrict__ Bb) {
    size_t i = (size_t)blockIdx.x * 256 + threadIdx.x;   // group of 8
    float4 a = ((const float4*)Bb)[2 * i];
    float4 b = ((const float4*)Bb)[2 * i + 1];
    __nv_bfloat162* o = (__nv_bfloat162*)(g_bbf + i * 8);
    o[0] = __floats2bfloat162_rn(a.x, a.y);
    o[1] = __floats2bfloat162_rn(a.z, a.w);
    o[2] = __floats2bfloat162_rn(b.x, b.y);
    o[3] = __floats2bfloat162_rn(b.z, b.w);
}

// ---------------------------------------------------------------------------
// Finalize mu/rstd + folded Q bias (uses precomputed g_wqsum)
// ---------------------------------------------------------------------------
__global__ void stats_final(const float* __restrict__ bq) {
    int tid = threadIdx.x;
    double s = 0.0, ss = 0.0;
    for (int i = tid; i < NPART_; i += 256) {
        s  += (double)g_part[i];
        ss += (double)g_part[NPART_ + i];
    }
    __shared__ double shs[256], shss[256];
    shs[tid] = s; shss[tid] = ss;
    __syncthreads();
    for (int o = 128; o; o >>= 1) {
        if (tid < o) { shs[tid] += shs[tid + o]; shss[tid] += shss[tid + o]; }
        __syncthreads();
    }
    __shared__ float mu_s, rstd_s;
    if (tid == 0) {
        double N = (double)NTOT_;
        double mu = shs[0] / N;
        double var = shss[0] / N - mu * mu;
        float rstd = (float)(1.0 / sqrt(var + EPS_));
        g_stats[0] = (float)mu;
        g_stats[1] = rstd;
        mu_s = (float)mu; rstd_s = rstd;
    }
    __syncthreads();
    g_cq[tid] = bq[tid] - rstd_s * mu_s * g_wqsum[tid];
}

// ---------------------------------------------------------------------------
// Depthwise 3x3 stride-2 conv (K and V paths fused), bf16 output
// ---------------------------------------------------------------------------
__global__ void dwconv_kernel(const float* __restrict__ x,
                              const float* __restrict__ wk, const float* __restrict__ bkd,
                              const float* __restrict__ wv, const float* __restrict__ bvd) {
    int idx = blockIdx.x * blockDim.x + threadIdx.x;
    if (idx >= B_ * C_ * KHW_) return;
    int ox = idx % 28;
    int oy = (idx / 28) % 28;
    int c  = (idx / KHW_) % C_;
    int b  = idx / (KHW_ * C_);
    const float* xp = x + ((size_t)(b * C_ + c)) * HW_;
    float ak = 0.f, av = 0.f;
    #pragma unroll
    for (int ky = 0; ky < 3; ky++) {
        int iy = oy * 2 + ky - 1;
        if (iy < 0 || iy >= H_) continue;
        #pragma unroll
        for (int kx = 0; kx < 3; kx++) {
            int ix = ox * 2 + kx - 1;
            if (ix < 0 || ix >= W_) continue;
            float xv = xp[iy * W_ + ix];
            ak += xv * wk[c * 9 + ky * 3 + kx];
            av += xv * wv[c * 9 + ky * 3 + kx];
        }
    }
    g_ck[idx] = __float2bfloat16(ak + bkd[c]);
    g_cv[idx] = __float2bfloat16(av + bvd[c]);
}

// ---------------------------------------------------------------------------
// bf16 mma GEMM (2-stage cp.async): out[b][R][P] = a1*sum_k W[R][k]*X[b][k][P]
//   + a2*cvec[R].  W bf16 [256][256], X bf16 [b][256][Mt], out bf16.
// ---------------------------------------------------------------------------
#define WST 40
#define XST 136
__global__ void __launch_bounds__(256, 2) gemm_wx(
    const __nv_bfloat16* __restrict__ W, const __nv_bfloat16* __restrict__ X,
    const float* __restrict__ cvec, int isQ, int Mt,
    __nv_bfloat16* __restrict__ out)
{
    __shared__ __align__(16) __nv_bfloat16 Ws[2][128 * WST];
    __shared__ __align__(16) __nv_bfloat16 Xs[2][32 * XST];
    const int P0 = blockIdx.x * 128;
    const int R0 = blockIdx.y * 128;
    const int b  = blockIdx.z;
    const __nv_bfloat16* Xb = X + (size_t)b * 256 * Mt;
    const int tid = threadIdx.x, lane = tid & 31, w = tid >> 5;
    const int wR = (w >> 2) * 64, wP = (w & 3) * 32;

    float c[4][4][4];
    #pragma unroll
    for (int i = 0; i < 4; i++)
        #pragma unroll
        for (int j = 0; j < 4; j++)
            #pragma unroll
            for (int r = 0; r < 4; r++) c[i][j][r] = 0.f;

    const uint32_t wsb = smem_u32(Ws), xsb = smem_u32(Xs);

    auto load_stage = [&](int k0, int buf) {
        uint32_t wd = wsb + buf * (128 * WST * 2);
        uint32_t xd = xsb + buf * (32 * XST * 2);
        #pragma unroll
        for (int t = 0; t < 2; t++) {
            int f = tid + t * 256;
            int r = f >> 2, cc = (f & 3) * 8;
            cp16(wd + (uint32_t)((r * WST + cc) * 2),
                 W + (size_t)(R0 + r) * 256 + k0 + cc);
        }
        #pragma unroll
        for (int t = 0; t < 2; t++) {
            int f = tid + t * 256;
            int kk = f >> 4, p = (f & 15) * 8;
            int gp = P0 + p; if (gp > Mt - 8) gp = Mt - 8;
            cp16(xd + (uint32_t)((kk * XST + p) * 2),
                 Xb + (size_t)(k0 + kk) * Mt + gp);
        }
    };

    load_stage(0, 0);
    cp_commit();

    for (int s = 0; s < 8; s++) {
        cp_wait_all();
        __syncthreads();
        if (s + 1 < 8) { load_stage((s + 1) * 32, (s + 1) & 1); cp_commit(); }
        const int buf = s & 1;
        const uint32_t wb = wsb + buf * (128 * WST * 2);
        const uint32_t xb = xsb + buf * (32 * XST * 2);

        #pragma unroll
        for (int kk = 0; kk < 2; kk++) {
            uint32_t af[4][4], bf[4][2];
            {
                int rr = ((lane >> 3) & 1) * 8 + (lane & 7);
                int ch = (lane >> 4) & 1;
                #pragma unroll
                for (int rf = 0; rf < 4; rf++)
                    ldm_x4(af[rf], wb + (uint32_t)(((wR + rf * 16 + rr) * WST + kk * 16 + ch * 8) * 2));
            }
            {
                int krow = (lane & 7) + ((lane >> 3) & 1) * 8;
                int pc = ((lane >> 4) & 1) * 8;
                #pragma unroll
                for (int pf = 0; pf < 2; pf++) {
                    uint32_t r4[4];
                    ldm_x4_t(r4, xb + (uint32_t)(((kk * 16 + krow) * XST + wP + pf * 16 + pc) * 2));
                    bf[2 * pf][0] = r4[0]; bf[2 * pf][1] = r4[1];
                    bf[2 * pf + 1][0] = r4[2]; bf[2 * pf + 1][1] = r4[3];
                }
            }
            #pragma unroll
            for (int rf = 0; rf < 4; rf++)
                #pragma unroll
                for (int pg = 0; pg < 4; pg++)
                    mma_bf16(c[rf][pg], af[rf], bf[pg]);
        }
        __syncthreads();
    }

    float a1 = 1.f, a2 = 1.f;
    if (isQ) { a1 = g_stats[1] * SCALE_; a2 = SCALE_; }
    __nv_bfloat16* ob = out + (size_t)b * 256 * Mt;
    #pragma unroll
    for (int rf = 0; rf < 4; rf++) {
        int R = R0 + wR + rf * 16 + (lane >> 2);
        float cv1 = a2 * cvec[R], cv2 = a2 * cvec[R + 8];
        #pragma unroll
        for (int pg = 0; pg < 4; pg++) {
            int P = P0 + wP + pg * 8 + (lane & 3) * 2;
            if (P < Mt) {
                *(__nv_bfloat162*)(ob + (size_t)R * Mt + P) =
                    __floats2bfloat162_rn(a1 * c[rf][pg][0] + cv1, a1 * c[rf][pg][1] + cv1);
                *(__nv_bfloat162*)(ob + (size_t)(R + 8) * Mt + P) =
                    __floats2bfloat162_rn(a1 * c[rf][pg][2] + cv2, a1 * c[rf][pg][3] + cv2);
            }
        }
    }
}

// ---------------------------------------------------------------------------
// O projection mma GEMM (2-stage cp.async) + fused bias + flat residual add
// ---------------------------------------------------------------------------
__global__ void __launch_bounds__(256, 2) gemm_o(
    const __nv_bfloat16* __restrict__ A, const __nv_bfloat16* __restrict__ Wo,
    const float* __restrict__ bo, const float* __restrict__ x,
    float* __restrict__ out)
{
    __shared__ __align__(16) __nv_bfloat16 As[2][128 * WST];
    __shared__ __align__(16) __nv_bfloat16 Bs[2][128 * WST];
    const int I0 = blockIdx.x * 128;
    const int N0 = blockIdx.y * 128;
    const int b  = blockIdx.z;
    const int tid = threadIdx.x, lane = tid & 31, w = tid >> 5;
    const int wI = (w >> 2) * 64, wN = (w & 3) * 32;

    float c[4][4][4];
    #pragma unroll
    for (int i = 0; i < 4; i++)
        #pragma unroll
        for (int j = 0; j < 4; j++)
            #pragma unroll
            for (int r = 0; r < 4; r++) c[i][j][r] = 0.f;

    const uint32_t asb = smem_u32(As), bsb = smem_u32(Bs);

    auto load_stage = [&](int k0, int buf) {
        uint32_t ad = asb + buf * (128 * WST * 2);
        uint32_t bd = bsb + buf * (128 * WST * 2);
        #pragma unroll
        for (int t = 0; t < 2; t++) {
            int f = tid + t * 256;
            int i = f >> 2, cc = (f & 3) * 8;
            int gi = I0 + i; if (gi > HW_ - 1) gi = HW_ - 1;
            cp16(ad + (uint32_t)((i * WST + cc) * 2),
                 A + ((size_t)(b * HW_) + gi) * 256 + k0 + cc);
        }
        #pragma unroll
        for (int t = 0; t < 2; t++) {
            int f = tid + t * 256;
            int n = f >> 2, cc = (f & 3) * 8;
            cp16(bd + (uint32_t)((n * WST + cc) * 2),
                 Wo + (size_t)(N0 + n) * 256 + k0 + cc);
        }
    };

    load_stage(0, 0);
    cp_commit();

    for (int s = 0; s < 8; s++) {
        cp_wait_all();
        __syncthreads();
        if (s + 1 < 8) { load_stage((s + 1) * 32, (s + 1) & 1); cp_commit(); }
        const int buf = s & 1;
        const uint32_t ab = asb + buf * (128 * WST * 2);
        const uint32_t bb = bsb + buf * (128 * WST * 2);

        #pragma unroll
        for (int kk = 0; kk < 2; kk++) {
            int rr = ((lane >> 3) & 1) * 8 + (lane & 7);
            int ch = (lane >> 4) & 1;
            uint32_t af[4][4], bf[4][2];
            #pragma unroll
            for (int mf = 0; mf < 4; mf++)
                ldm_x4(af[mf], ab + (uint32_t)(((wI + mf * 16 + rr) * WST + kk * 16 + ch * 8) * 2));
            #pragma unroll
            for (int ng = 0; ng < 2; ng++) {
                uint32_t r4[4];
                ldm_x4(r4, bb + (uint32_t)(((wN + ng * 16 + rr) * WST + kk * 16 + ch * 8) * 2));
                bf[2 * ng][0] = r4[0]; bf[2 * ng][1] = r4[2];
                bf[2 * ng + 1][0] = r4[1]; bf[2 * ng + 1][1] = r4[3];
            }
            #pragma unroll
            for (int mf = 0; mf < 4; mf++)
                #pragma unroll
                for (int nf = 0; nf < 4; nf++)
                    mma_bf16(c[mf][nf], af[mf], bf[nf]);
        }
        __syncthreads();
    }

    #pragma unroll
    for (int mf = 0; mf < 4; mf++) {
        int i1 = I0 + wI + mf * 16 + (lane >> 2);
        int i2 = i1 + 8;
        #pragma unroll
        for (int nf = 0; nf < 4; nf++) {
            int n = N0 + wN + nf * 8 + (lane & 3) * 2;
            float b0v = bo[n], b1v = bo[n + 1];
            if (i1 < HW_) {
                size_t flat = (size_t)b * (256 * HW_) + (size_t)i1 * 256 + n;
                float2 xv = *(const float2*)(x + flat);
                *(float2*)(out + flat) =
                    make_float2(c[mf][nf][0] + b0v + xv.x, c[mf][nf][1] + b1v + xv.y);
            }
            if (i2 < HW_) {
                size_t flat = (size_t)b * (256 * HW_) + (size_t)i2 * 256 + n;
                float2 xv = *(const float2*)(x + flat);
                *(float2*)(out + flat) =
                    make_float2(c[mf][nf][2] + b0v + xv.x, c[mf][nf][3] + b1v + xv.y);
            }
        }
    }
}

// ---------------------------------------------------------------------------
// bf16 flash attention with 2-stage cp.async pipeline for K/V AND bias (bf16).
// Dynamic smem layout (per block, 64000 B):
//   [0)      Qs   32 x 136 bf16    (8704)
//   [8704)   Ks   2 x 32 x 72 bf16 (9216)
//   [17920)  Vs   2 x 32 x 72 bf16 (9216)
//   [27136)  Bias 2 x 128 x 72 bf16 (36864) — stride 72 = conflict-free
// ---------------------------------------------------------------------------
#define QST 136
#define KST 72
#define BST 72
#define ATT_SMEM 64000
#define KVBUF (32 * KST * 2)      // bytes per K or V stage
#define BBUF  (128 * BST * 2)     // bytes per bias stage (bf16)

__global__ void __launch_bounds__(256, 2) attn_mma_kernel(
    const __nv_bfloat16* __restrict__ qb, const __nv_bfloat16* __restrict__ kb,
    const __nv_bfloat16* __restrict__ vb, const __nv_bfloat16* __restrict__ bias,
    __nv_bfloat16* __restrict__ res)
{
    extern __shared__ __align__(16) char smraw[];
    __nv_bfloat16* Qs = (__nv_bfloat16*)smraw;
    __nv_bfloat16* BiasS = (__nv_bfloat16*)(smraw + 27136);

    const int b = blockIdx.x, h = blockIdx.y;
    const int i0 = blockIdx.z * 128;
    const int tid = threadIdx.x, lane = tid & 31, w = tid >> 5;

    const __nv_bfloat16* qsrc = qb + ((size_t)b * 256 + h * 32) * HW_;
    const __nv_bfloat16* ksrc = kb + ((size_t)b * 256 + h * 32) * KHW_;
    const __nv_bfloat16* vsrc = vb + ((size_t)b * 256 + h * 32) * KHW_;
    const __nv_bfloat16* bias_h = bias + (size_t)h * HW_ * KHW_;

    const uint32_t qbase = smem_u32(smraw);
    const uint32_t kbase0 = qbase + 8704;
    const uint32_t vbase0 = qbase + 17920;
    const uint32_t bbase0 = qbase + 27136;

    // --- Q tile: [32 d][128 i] direct copy ---
    #pragma unroll
    for (int f = tid; f < 512; f += 256) {
        int d = f >> 4, ii = (f & 15) * 8;
        int gi = i0 + ii; if (gi > HW_ - 8) gi = HW_ - 8;
        *(uint4*)&Qs[d * QST + ii] = *(const uint4*)(qsrc + (size_t)d * HW_ + gi);
    }

    // tile loader (K, V, bias) via cp.async
    auto load_tile = [&](int j0, int buf) {
        {
            int d = tid >> 3, jj = (tid & 7) * 8;
            int gj = j0 + jj; if (gj > KHW_ - 8) gj = KHW_ - 8;
            cp16(kbase0 + buf * KVBUF + (uint32_t)((d * KST + jj) * 2),
                 ksrc + (size_t)d * KHW_ + gj);
            cp16(vbase0 + buf * KVBUF + (uint32_t)((d * KST + jj) * 2),
                 vsrc + (size_t)d * KHW_ + gj);
        }
        #pragma unroll
        for (int t = 0; t < 4; t++) {
            int f = tid + t * 256;                 // f < 1024
            int r = f >> 3, c8 = (f & 7) * 8;
            int gr = i0 + r; if (gr > HW_ - 1) gr = HW_ - 1;
            int gc = j0 + c8; if (gc > KHW_ - 8) gc = KHW_ - 8;
            cp16(bbase0 + buf * BBUF + (uint32_t)((r * BST + c8) * 2),
                 bias_h + (size_t)gr * KHW_ + gc);
        }
    };

    load_tile(0, 0);
    cp_commit();
    __syncthreads();   // Q tile visible

    // --- Q A-fragments (trans from [k][m]) ---
    uint32_t qa[2][4];
    {
        int krow = (lane & 7) + ((lane >> 4) & 1) * 8;
        int mcol = w * 16 + ((lane >> 3) & 1) * 8;
        #pragma unroll
        for (int kk = 0; kk < 2; kk++)
            ldm_x4_t(qa[kk], qbase + (uint32_t)(((kk * 16 + krow) * QST + mcol) * 2));
    }

    float m0 = -1e30f, m1 = -1e30f;
    float l0 = 0.f, l1 = 0.f;
    float oacc[4][4];
    #pragma unroll
    for (int nf = 0; nf < 4; nf++)
        #pragma unroll
        for (int r = 0; r < 4; r++) oacc[nf][r] = 0.f;

    const int rA = w * 16 + (lane >> 2);
    const int rB = rA + 8;

    for (int jt = 0; jt < 13; jt++) {
        const int j0 = jt * 64;
        cp_wait_all();
        __syncthreads();
        if (jt + 1 < 13) { load_tile((jt + 1) * 64, (jt + 1) & 1); cp_commit(); }

        const int buf = jt & 1;
        const uint32_t kbase = kbase0 + buf * KVBUF;
        const uint32_t vbase = vbase0 + buf * KVBUF;
        const __nv_bfloat16* bsm = BiasS + buf * (128 * BST);

        // --- S = Q @ K^T ---
        float s[8][4];
        #pragma unroll
        for (int nf = 0; nf < 8; nf++)
            #pragma unroll
            for (int r = 0; r < 4; r++) s[nf][r] = 0.f;

        #pragma unroll
        for (int kk = 0; kk < 2; kk++) {
            uint32_t kbf[8][2];
            int krow = (lane & 7) + ((lane >> 3) & 1) * 8;
            int ncol = ((lane >> 4) & 1) * 8;
            #pragma unroll
            for (int jg = 0; jg < 4; jg++) {
                uint32_t r4[4];
                ldm_x4_t(r4, kbase + (uint32_t)(((kk * 16 + krow) * KST + jg * 16 + ncol) * 2));
                kbf[2 * jg][0] = r4[0]; kbf[2 * jg][1] = r4[1];
                kbf[2 * jg + 1][0] = r4[2]; kbf[2 * jg + 1][1] = r4[3];
            }
            #pragma unroll
            for (int nf = 0; nf < 8; nf++) mma_bf16(s[nf], qa[kk], kbf[nf]);
        }

        // --- bias (bf16 smem) + mask + online softmax ---
        float rmax0 = -1e30f, rmax1 = -1e30f;
        #pragma unroll
        for (int nf = 0; nf < 8; nf++) {
            int cj = nf * 8 + (lane & 3) * 2;
            int gj = j0 + cj;
            bool jv = (gj < KHW_);
            float2 bA = __bfloat1622float2(*(const __nv_bfloat162*)(bsm + rA * BST + cj));
            float2 bB = __bfloat1622float2(*(const __nv_bfloat162*)(bsm + rB * BST + cj));
            float v0 = s[nf][0] + bA.x, v1 = s[nf][1] + bA.y;
            float v2 = s[nf][2] + bB.x, v3 = s[nf][3] + bB.y;
            if (!jv) { v0 = v1 = v2 = v3 = -1e30f; }
            s[nf][0] = v0; s[nf][1] = v1; s[nf][2] = v2; s[nf][3] = v3;
            rmax0 = fmaxf(rmax0, fmaxf(v0, v1));
            rmax1 = fmaxf(rmax1, fmaxf(v2, v3));
        }
        #pragma unroll
        for (int o = 1; o <= 2; o <<= 1) {
            rmax0 = fmaxf(rmax0, __shfl_xor_sync(0xffffffffu, rmax0, o));
            rmax1 = fmaxf(rmax1, __shfl_xor_sync(0xffffffffu, rmax1, o));
        }
        float mn0 = fmaxf(m0, rmax0), mn1 = fmaxf(m1, rmax1);
        float al0 = __expf(m0 - mn0), al1 = __expf(m1 - mn1);
        m0 = mn0; m1 = mn1;

        float rs0 = 0.f, rs1 = 0.f;
        uint32_t pa[4][4];
        #pragma unroll
        for (int nf = 0; nf < 8; nf++) {
            float p0 = __expf(s[nf][0] - mn0);
            float p1 = __expf(s[nf][1] - mn0);
            float p2 = __expf(s[nf][2] - mn1);
            float p3 = __expf(s[nf][3] - mn1);
            rs0 += p0 + p1; rs1 += p2 + p3;
            pa[nf >> 1][(nf & 1) * 2 + 0] = pack_bf16x2(p0, p1);
            pa[nf >> 1][(nf & 1) * 2 + 1] = pack_bf16x2(p2, p3);
        }
        #pragma unroll
        for (int o = 1; o <= 2; o <<= 1) {
            rs0 += __shfl_xor_sync(0xffffffffu, rs0, o);
            rs1 += __shfl_xor_sync(0xffffffffu, rs1, o);
        }
        l0 = al0 * l0 + rs0;
        l1 = al1 * l1 + rs1;
        #pragma unroll
        for (int nf = 0; nf < 4; nf++) {
            oacc[nf][0] *= al0; oacc[nf][1] *= al0;
            oacc[nf][2] *= al1; oacc[nf][3] *= al1;
        }

        // --- O += P @ V ---
        uint32_t vbf[4][4][2];
        {
            int rr = ((lane >> 3) & 1) * 8 + (lane & 7);
            int ch = (lane >> 4) & 1;
            #pragma unroll
            for (int ng = 0; ng < 2; ng++)
                #pragma unroll
                for (int kf = 0; kf < 4; kf++) {
                    uint32_t r4[4];
                    ldm_x4(r4, vbase + (uint32_t)(((ng * 16 + rr) * KST + kf * 16 + ch * 8) * 2));
                    vbf[2 * ng][kf][0] = r4[0]; vbf[2 * ng][kf][1] = r4[2];
                    vbf[2 * ng + 1][kf][0] = r4[1]; vbf[2 * ng + 1][kf][1] = r4[3];
                }
        }
        #pragma unroll
        for (int kf = 0; kf < 4; kf++)
            #pragma unroll
            for (int nf = 0; nf < 4; nf++)
                mma_bf16(oacc[nf], pa[kf], vbf[nf][kf]);
    }

    // --- epilogue: normalize + bf16 store to res[b][i][hd] ---
    float inv0 = 1.f / l0, inv1 = 1.f / l1;
    int giA = i0 + w * 16 + (lane >> 2);
    int giB = giA + 8;
    #pragma unroll
    for (int nf = 0; nf < 4; nf++) {
        int col = h * 32 + nf * 8 + (lane & 3) * 2;
        if (giA < HW_)
            *(__nv_bfloat162*)(res + ((size_t)(b * HW_ + giA)) * 256 + col) =
                __floats2bfloat162_rn(oacc[nf][0] * inv0, oacc[nf][1] * inv0);
        if (giB < HW_)
            *(__nv_bfloat162*)(res + ((size_t)(b * HW_ + giB)) * 256 + col) =
                __floats2bfloat162_rn(oacc[nf][2] * inv1, oacc[nf][3] * inv1);
    }
}

// ---------------------------------------------------------------------------
extern "C" void kernel_launch(void* const* d_in, const int* in_sizes, int n_in,
                              void* d_out, int out_size) {
    const float* x     = (const float*)d_in[0];
    const float* Wk_dw = (const float*)d_in[1];
    const float* bk_dw = (const float*)d_in[2];
    const float* Wv_dw = (const float*)d_in[3];
    const float* bv_dw = (const float*)d_in[4];
    const float* Wq    = (const float*)d_in[5];
    const float* bq    = (const float*)d_in[6];
    const float* Wk    = (const float*)d_in[7];
    const float* bk    = (const float*)d_in[8];
    const float* Wv    = (const float*)d_in[9];
    const float* bv    = (const float*)d_in[10];
    const float* Wo    = (const float*)d_in[11];
    const float* bo    = (const float*)d_in[12];
    const float* Bb    = (const float*)d_in[13];
    float* out = (float*)d_out;

    __nv_bfloat16 *qp, *kp, *vp, *resp, *ckp, *cvp, *xbfp, *bbfp;
    __nv_bfloat16 *wqp, *wkp, *wvp, *wop;
    float *cqp;
    cudaGetSymbolAddress((void**)&qp,   g_q);
    cudaGetSymbolAddress((void**)&kp,   g_k);
    cudaGetSymbolAddress((void**)&vp,   g_v);
    cudaGetSymbolAddress((void**)&resp, g_res);
    cudaGetSymbolAddress((void**)&ckp,  g_ck);
    cudaGetSymbolAddress((void**)&cvp,  g_cv);
    cudaGetSymbolAddress((void**)&xbfp, g_xbf);
    cudaGetSymbolAddress((void**)&bbfp, g_bbf);
    cudaGetSymbolAddress((void**)&wqp,  g_wq);
    cudaGetSymbolAddress((void**)&wkp,  g_wk);
    cudaGetSymbolAddress((void**)&wvp,  g_wv);
    cudaGetSymbolAddress((void**)&wop,  g_wo);
    cudaGetSymbolAddress((void**)&cqp,  g_cq);

    cudaFuncSetAttribute(attn_mma_kernel,
                         cudaFuncAttributeMaxDynamicSharedMemorySize, ATT_SMEM);

    cvt_x_stats<<<NPART_, 256>>>(x);
    cvt_w_kernel<<<256, 256>>>(Wq, Wk, Wv, Wo);
    cvt_bias<<<BIASN_ / 8 / 256, 256>>>(Bb);
    stats_final<<<1, 256>>>(bq);
    dwconv_kernel<<<(B_ * C_ * KHW_ + 255) / 256, 256>>>(x, Wk_dw, bk_dw, Wv_dw, bv_dw);

    gemm_wx<<<dim3(25, 2, B_), 256>>>(wqp, xbfp, cqp, 1, HW_,  qp);
    gemm_wx<<<dim3(7,  2, B_), 256>>>(wkp, ckp,  bk,  0, KHW_, kp);
    gemm_wx<<<dim3(7,  2, B_), 256>>>(wvp, cvp,  bv,  0, KHW_, vp);

    attn_mma_kernel<<<dim3(B_, HEADS_, 25), 256, ATT_SMEM>>>(qp, kp, vp, bbfp, resp);

    gemm_o<<<dim3(25, 2, B_), 256>>>(resp, wop, bo, x, out);
}

// round 6
// speedup vs baseline: 15.4492x; 1.1191x over previous
#include <cuda_runtime.h>
#include <cuda_bf16.h>
#include <math.h>
#include <stdint.h>

// Problem constants
#define B_   8
#define C_   256
#define H_   56
#define W_   56
#define HW_  3136        // 56*56
#define KHW_ 784         // 28*28
#define HEADS_ 8
#define NTOT_ 6422528    // B*C*HW
#define NPART_ 6272      // NTOT/4/256 blocks in fused cvt+stats
#define BIASN_ 19668992  // HEADS*HW*KHW
#define EPS_ 1e-5
#define SCALE_ 0.17677669529663687f   // 1/sqrt(32)

// Scratch (static device arrays — allocation-free)
__device__ __nv_bfloat16 g_q[B_ * 256 * HW_];    // [b][hd][i]
__device__ __nv_bfloat16 g_k[B_ * 256 * KHW_];   // [b][hd][j]
__device__ __nv_bfloat16 g_v[B_ * 256 * KHW_];   // [b][hd][j]
__device__ __nv_bfloat16 g_res[B_ * HW_ * 256];  // [b][i][hd]
__device__ __nv_bfloat16 g_ck[B_ * C_ * KHW_];   // conv-K out bf16 [b][c][j]
__device__ __nv_bfloat16 g_cv[B_ * C_ * KHW_];
__device__ __nv_bfloat16 g_xbf[NTOT_];           // x in bf16 [b][c][hw]
__device__ __nv_bfloat16 g_bbf[BIASN_];          // bias in bf16
__device__ __nv_bfloat16 g_wq[65536], g_wk[65536], g_wv[65536], g_wo[65536];
__device__ float g_part[2 * NPART_];
__device__ float g_wqsum[256];
__device__ float g_stats[2];                     // mu, rstd
__device__ float g_cq[256];                      // folded Q bias

// ---------------------------------------------------------------------------
// asm helpers
// ---------------------------------------------------------------------------
__device__ __forceinline__ uint32_t smem_u32(const void* p) {
    return (uint32_t)__cvta_generic_to_shared(p);
}
__device__ __forceinline__ void ldm_x4(uint32_t* r, uint32_t addr) {
    asm volatile("ldmatrix.sync.aligned.m8n8.x4.shared.b16 {%0,%1,%2,%3}, [%4];"
        : "=r"(r[0]), "=r"(r[1]), "=r"(r[2]), "=r"(r[3]) : "r"(addr));
}
__device__ __forceinline__ void ldm_x4_t(uint32_t* r, uint32_t addr) {
    asm volatile("ldmatrix.sync.aligned.m8n8.x4.trans.shared.b16 {%0,%1,%2,%3}, [%4];"
        : "=r"(r[0]), "=r"(r[1]), "=r"(r[2]), "=r"(r[3]) : "r"(addr));
}
__device__ __forceinline__ void mma_bf16(float* d, const uint32_t* a, const uint32_t* b) {
    asm volatile(
        "mma.sync.aligned.m16n8k16.row.col.f32.bf16.bf16.f32 "
        "{%0,%1,%2,%3}, {%4,%5,%6,%7}, {%8,%9}, {%0,%1,%2,%3};"
        : "+f"(d[0]), "+f"(d[1]), "+f"(d[2]), "+f"(d[3])
        : "r"(a[0]), "r"(a[1]), "r"(a[2]), "r"(a[3]), "r"(b[0]), "r"(b[1]));
}
__device__ __forceinline__ uint32_t pack_bf16x2(float lo, float hi) {
    uint32_t r;
    asm("cvt.rn.bf16x2.f32 %0, %1, %2;" : "=r"(r) : "f"(hi), "f"(lo));
    return r;
}
__device__ __forceinline__ void cp16(uint32_t dst, const void* src) {
    asm volatile("cp.async.cg.shared.global [%0], [%1], 16;" :: "r"(dst), "l"(src));
}
__device__ __forceinline__ void cp_commit() {
    asm volatile("cp.async.commit_group;" ::: "memory");
}
__device__ __forceinline__ void cp_wait_all() {
    asm volatile("cp.async.wait_group 0;" ::: "memory");
}

// ---------------------------------------------------------------------------
// Fused: x fp32 -> bf16 + LN partial sums (x read ONCE)
// ---------------------------------------------------------------------------
__global__ void cvt_x_stats(const float* __restrict__ x) {
    int tid = threadIdx.x;
    int i = blockIdx.x * 256 + tid;            // group of 4 floats
    float4 v = ((const float4*)x)[i];
    __nv_bfloat162* o = (__nv_bfloat162*)(g_xbf + (size_t)i * 4);
    o[0] = __floats2bfloat162_rn(v.x, v.y);
    o[1] = __floats2bfloat162_rn(v.z, v.w);
    float s  = v.x + v.y + v.z + v.w;
    float ss = v.x * v.x + v.y * v.y + v.z * v.z + v.w * v.w;
    #pragma unroll
    for (int ofs = 16; ofs; ofs >>= 1) {
        s  += __shfl_xor_sync(0xffffffffu, s, ofs);
        ss += __shfl_xor_sync(0xffffffffu, ss, ofs);
    }
    __shared__ float sh[16];
    int w = tid >> 5, lane = tid & 31;
    if (lane == 0) { sh[w] = s; sh[8 + w] = ss; }
    __syncthreads();
    if (tid == 0) {
        float a = 0.f, b = 0.f;
        #pragma unroll
        for (int k = 0; k < 8; k++) { a += sh[k]; b += sh[8 + k]; }
        g_part[blockIdx.x] = a;
        g_part[NPART_ + blockIdx.x] = b;
    }
}

// ---------------------------------------------------------------------------
// Weight conversions + Wq rowsum (block r reduces row r of Wq)
// ---------------------------------------------------------------------------
__global__ void cvt_w_kernel(const float* __restrict__ Wq, const float* __restrict__ Wk,
                             const float* __restrict__ Wv, const float* __restrict__ Wo) {
    int r = blockIdx.x, tid = threadIdx.x;
    int i = r * 256 + tid;
    float wq = Wq[i];
    g_wq[i] = __float2bfloat16(wq);
    g_wk[i] = __float2bfloat16(Wk[i]);
    g_wv[i] = __float2bfloat16(Wv[i]);
    g_wo[i] = __float2bfloat16(Wo[i]);
    float s = wq;
    #pragma unroll
    for (int ofs = 16; ofs; ofs >>= 1) s += __shfl_xor_sync(0xffffffffu, s, ofs);
    __shared__ float sh[8];
    if ((tid & 31) == 0) sh[tid >> 5] = s;
    __syncthreads();
    if (tid == 0) {
        float a = 0.f;
        #pragma unroll
        for (int k = 0; k < 8; k++) a += sh[k];
        g_wqsum[r] = a;
    }
}

// ---------------------------------------------------------------------------
// Bias fp32 -> bf16
// ---------------------------------------------------------------------------
__global__ void cvt_bias(const float* __restrict__ Bb) {
    size_t i = (size_t)blockIdx.x * 256 + threadIdx.x;   // group of 8
    float4 a = ((const float4*)Bb)[2 * i];
    float4 b = ((const float4*)Bb)[2 * i + 1];
    __nv_bfloat162* o = (__nv_bfloat162*)(g_bbf + i * 8);
    o[0] = __floats2bfloat162_rn(a.x, a.y);
    o[1] = __floats2bfloat162_rn(a.z, a.w);
    o[2] = __floats2bfloat162_rn(b.x, b.y);
    o[3] = __floats2bfloat162_rn(b.z, b.w);
}

// ---------------------------------------------------------------------------
// Finalize mu/rstd + folded Q bias (float4-vectorized partial loads)
// ---------------------------------------------------------------------------
__global__ void stats_final(const float* __restrict__ bq) {
    int tid = threadIdx.x;
    const float4* p4  = (const float4*)g_part;            // 1568 vec sums
    const float4* ps4 = (const float4*)(g_part + NPART_); // 1568 vec sumsq
    double s = 0.0, ss = 0.0;
    for (int i = tid; i < NPART_ / 4; i += 256) {
        float4 a = p4[i];
        float4 b = ps4[i];
        s  += (double)((a.x + a.y) + (a.z + a.w));
        ss += (double)((b.x + b.y) + (b.z + b.w));
    }
    __shared__ double shs[256], shss[256];
    shs[tid] = s; shss[tid] = ss;
    __syncthreads();
    for (int o = 128; o; o >>= 1) {
        if (tid < o) { shs[tid] += shs[tid + o]; shss[tid] += shss[tid + o]; }
        __syncthreads();
    }
    __shared__ float mu_s, rstd_s;
    if (tid == 0) {
        double N = (double)NTOT_;
        double mu = shs[0] / N;
        double var = shss[0] / N - mu * mu;
        float rstd = (float)(1.0 / sqrt(var + EPS_));
        g_stats[0] = (float)mu;
        g_stats[1] = rstd;
        mu_s = (float)mu; rstd_s = rstd;
    }
    __syncthreads();
    g_cq[tid] = bq[tid] - rstd_s * mu_s * g_wqsum[tid];
}

// ---------------------------------------------------------------------------
// Depthwise 3x3 stride-2 conv (K and V paths fused), bf16 output
// ---------------------------------------------------------------------------
__global__ void dwconv_kernel(const float* __restrict__ x,
                              const float* __restrict__ wk, const float* __restrict__ bkd,
                              const float* __restrict__ wv, const float* __restrict__ bvd) {
    int idx = blockIdx.x * blockDim.x + threadIdx.x;
    if (idx >= B_ * C_ * KHW_) return;
    int ox = idx % 28;
    int oy = (idx / 28) % 28;
    int c  = (idx / KHW_) % C_;
    int b  = idx / (KHW_ * C_);
    const float* xp = x + ((size_t)(b * C_ + c)) * HW_;
    float ak = 0.f, av = 0.f;
    #pragma unroll
    for (int ky = 0; ky < 3; ky++) {
        int iy = oy * 2 + ky - 1;
        if (iy < 0 || iy >= H_) continue;
        #pragma unroll
        for (int kx = 0; kx < 3; kx++) {
            int ix = ox * 2 + kx - 1;
            if (ix < 0 || ix >= W_) continue;
            float xv = xp[iy * W_ + ix];
            ak += xv * wk[c * 9 + ky * 3 + kx];
            av += xv * wv[c * 9 + ky * 3 + kx];
        }
    }
    g_ck[idx] = __float2bfloat16(ak + bkd[c]);
    g_cv[idx] = __float2bfloat16(av + bvd[c]);
}

// ---------------------------------------------------------------------------
// bf16 mma GEMM (2-stage cp.async): out[b][R][P] = a1*sum_k W[R][k]*X[b][k][P]
//   + a2*cvec[R].  W bf16 [256][256], X bf16 [b][256][Mt], out bf16.
// ---------------------------------------------------------------------------
#define WST 40
#define XST 136
__global__ void __launch_bounds__(256, 2) gemm_wx(
    const __nv_bfloat16* __restrict__ W, const __nv_bfloat16* __restrict__ X,
    const float* __restrict__ cvec, int isQ, int Mt,
    __nv_bfloat16* __restrict__ out)
{
    __shared__ __align__(16) __nv_bfloat16 Ws[2][128 * WST];
    __shared__ __align__(16) __nv_bfloat16 Xs[2][32 * XST];
    const int P0 = blockIdx.x * 128;
    const int R0 = blockIdx.y * 128;
    const int b  = blockIdx.z;
    const __nv_bfloat16* Xb = X + (size_t)b * 256 * Mt;
    const int tid = threadIdx.x, lane = tid & 31, w = tid >> 5;
    const int wR = (w >> 2) * 64, wP = (w & 3) * 32;

    float c[4][4][4];
    #pragma unroll
    for (int i = 0; i < 4; i++)
        #pragma unroll
        for (int j = 0; j < 4; j++)
            #pragma unroll
            for (int r = 0; r < 4; r++) c[i][j][r] = 0.f;

    const uint32_t wsb = smem_u32(Ws), xsb = smem_u32(Xs);

    auto load_stage = [&](int k0, int buf) {
        uint32_t wd = wsb + buf * (128 * WST * 2);
        uint32_t xd = xsb + buf * (32 * XST * 2);
        #pragma unroll
        for (int t = 0; t < 2; t++) {
            int f = tid + t * 256;
            int r = f >> 2, cc = (f & 3) * 8;
            cp16(wd + (uint32_t)((r * WST + cc) * 2),
                 W + (size_t)(R0 + r) * 256 + k0 + cc);
        }
        #pragma unroll
        for (int t = 0; t < 2; t++) {
            int f = tid + t * 256;
            int kk = f >> 4, p = (f & 15) * 8;
            int gp = P0 + p; if (gp > Mt - 8) gp = Mt - 8;
            cp16(xd + (uint32_t)((kk * XST + p) * 2),
                 Xb + (size_t)(k0 + kk) * Mt + gp);
        }
    };

    load_stage(0, 0);
    cp_commit();

    for (int s = 0; s < 8; s++) {
        cp_wait_all();
        __syncthreads();
        if (s + 1 < 8) { load_stage((s + 1) * 32, (s + 1) & 1); cp_commit(); }
        const int buf = s & 1;
        const uint32_t wb = wsb + buf * (128 * WST * 2);
        const uint32_t xb = xsb + buf * (32 * XST * 2);

        #pragma unroll
        for (int kk = 0; kk < 2; kk++) {
            uint32_t af[4][4], bf[4][2];
            {
                int rr = ((lane >> 3) & 1) * 8 + (lane & 7);
                int ch = (lane >> 4) & 1;
                #pragma unroll
                for (int rf = 0; rf < 4; rf++)
                    ldm_x4(af[rf], wb + (uint32_t)(((wR + rf * 16 + rr) * WST + kk * 16 + ch * 8) * 2));
            }
            {
                int krow = (lane & 7) + ((lane >> 3) & 1) * 8;
                int pc = ((lane >> 4) & 1) * 8;
                #pragma unroll
                for (int pf = 0; pf < 2; pf++) {
                    uint32_t r4[4];
                    ldm_x4_t(r4, xb + (uint32_t)(((kk * 16 + krow) * XST + wP + pf * 16 + pc) * 2));
                    bf[2 * pf][0] = r4[0]; bf[2 * pf][1] = r4[1];
                    bf[2 * pf + 1][0] = r4[2]; bf[2 * pf + 1][1] = r4[3];
                }
            }
            #pragma unroll
            for (int rf = 0; rf < 4; rf++)
                #pragma unroll
                for (int pg = 0; pg < 4; pg++)
                    mma_bf16(c[rf][pg], af[rf], bf[pg]);
        }
        __syncthreads();
    }

    float a1 = 1.f, a2 = 1.f;
    if (isQ) { a1 = g_stats[1] * SCALE_; a2 = SCALE_; }
    __nv_bfloat16* ob = out + (size_t)b * 256 * Mt;
    #pragma unroll
    for (int rf = 0; rf < 4; rf++) {
        int R = R0 + wR + rf * 16 + (lane >> 2);
        float cv1 = a2 * cvec[R], cv2 = a2 * cvec[R + 8];
        #pragma unroll
        for (int pg = 0; pg < 4; pg++) {
            int P = P0 + wP + pg * 8 + (lane & 3) * 2;
            if (P < Mt) {
                *(__nv_bfloat162*)(ob + (size_t)R * Mt + P) =
                    __floats2bfloat162_rn(a1 * c[rf][pg][0] + cv1, a1 * c[rf][pg][1] + cv1);
                *(__nv_bfloat162*)(ob + (size_t)(R + 8) * Mt + P) =
                    __floats2bfloat162_rn(a1 * c[rf][pg][2] + cv2, a1 * c[rf][pg][3] + cv2);
            }
        }
    }
}

// ---------------------------------------------------------------------------
// O projection mma GEMM (2-stage cp.async) + fused bias + flat residual add
// ---------------------------------------------------------------------------
__global__ void __launch_bounds__(256, 2) gemm_o(
    const __nv_bfloat16* __restrict__ A, const __nv_bfloat16* __restrict__ Wo,
    const float* __restrict__ bo, const float* __restrict__ x,
    float* __restrict__ out)
{
    __shared__ __align__(16) __nv_bfloat16 As[2][128 * WST];
    __shared__ __align__(16) __nv_bfloat16 Bs[2][128 * WST];
    const int I0 = blockIdx.x * 128;
    const int N0 = blockIdx.y * 128;
    const int b  = blockIdx.z;
    const int tid = threadIdx.x, lane = tid & 31, w = tid >> 5;
    const int wI = (w >> 2) * 64, wN = (w & 3) * 32;

    float c[4][4][4];
    #pragma unroll
    for (int i = 0; i < 4; i++)
        #pragma unroll
        for (int j = 0; j < 4; j++)
            #pragma unroll
            for (int r = 0; r < 4; r++) c[i][j][r] = 0.f;

    const uint32_t asb = smem_u32(As), bsb = smem_u32(Bs);

    auto load_stage = [&](int k0, int buf) {
        uint32_t ad = asb + buf * (128 * WST * 2);
        uint32_t bd = bsb + buf * (128 * WST * 2);
        #pragma unroll
        for (int t = 0; t < 2; t++) {
            int f = tid + t * 256;
            int i = f >> 2, cc = (f & 3) * 8;
            int gi = I0 + i; if (gi > HW_ - 1) gi = HW_ - 1;
            cp16(ad + (uint32_t)((i * WST + cc) * 2),
                 A + ((size_t)(b * HW_) + gi) * 256 + k0 + cc);
        }
        #pragma unroll
        for (int t = 0; t < 2; t++) {
            int f = tid + t * 256;
            int n = f >> 2, cc = (f & 3) * 8;
            cp16(bd + (uint32_t)((n * WST + cc) * 2),
                 Wo + (size_t)(N0 + n) * 256 + k0 + cc);
        }
    };

    load_stage(0, 0);
    cp_commit();

    for (int s = 0; s < 8; s++) {
        cp_wait_all();
        __syncthreads();
        if (s + 1 < 8) { load_stage((s + 1) * 32, (s + 1) & 1); cp_commit(); }
        const int buf = s & 1;
        const uint32_t ab = asb + buf * (128 * WST * 2);
        const uint32_t bb = bsb + buf * (128 * WST * 2);

        #pragma unroll
        for (int kk = 0; kk < 2; kk++) {
            int rr = ((lane >> 3) & 1) * 8 + (lane & 7);
            int ch = (lane >> 4) & 1;
            uint32_t af[4][4], bf[4][2];
            #pragma unroll
            for (int mf = 0; mf < 4; mf++)
                ldm_x4(af[mf], ab + (uint32_t)(((wI + mf * 16 + rr) * WST + kk * 16 + ch * 8) * 2));
            #pragma unroll
            for (int ng = 0; ng < 2; ng++) {
                uint32_t r4[4];
                ldm_x4(r4, bb + (uint32_t)(((wN + ng * 16 + rr) * WST + kk * 16 + ch * 8) * 2));
                bf[2 * ng][0] = r4[0]; bf[2 * ng][1] = r4[2];
                bf[2 * ng + 1][0] = r4[1]; bf[2 * ng + 1][1] = r4[3];
            }
            #pragma unroll
            for (int mf = 0; mf < 4; mf++)
                #pragma unroll
                for (int nf = 0; nf < 4; nf++)
                    mma_bf16(c[mf][nf], af[mf], bf[nf]);
        }
        __syncthreads();
    }

    #pragma unroll
    for (int mf = 0; mf < 4; mf++) {
        int i1 = I0 + wI + mf * 16 + (lane >> 2);
        int i2 = i1 + 8;
        #pragma unroll
        for (int nf = 0; nf < 4; nf++) {
            int n = N0 + wN + nf * 8 + (lane & 3) * 2;
            float b0v = bo[n], b1v = bo[n + 1];
            if (i1 < HW_) {
                size_t flat = (size_t)b * (256 * HW_) + (size_t)i1 * 256 + n;
                float2 xv = *(const float2*)(x + flat);
                *(float2*)(out + flat) =
                    make_float2(c[mf][nf][0] + b0v + xv.x, c[mf][nf][1] + b1v + xv.y);
            }
            if (i2 < HW_) {
                size_t flat = (size_t)b * (256 * HW_) + (size_t)i2 * 256 + n;
                float2 xv = *(const float2*)(x + flat);
                *(float2*)(out + flat) =
                    make_float2(c[mf][nf][2] + b0v + xv.x, c[mf][nf][3] + b1v + xv.y);
            }
        }
    }
}

// ---------------------------------------------------------------------------
// bf16 flash attention with 2-stage cp.async pipeline for K/V AND bias (bf16).
// Dynamic smem layout (per block, 64000 B):
//   [0)      Qs   32 x 136 bf16    (8704)
//   [8704)   Ks   2 x 32 x 72 bf16 (9216)
//   [17920)  Vs   2 x 32 x 72 bf16 (9216)
//   [27136)  Bias 2 x 128 x 72 bf16 (36864) — stride 72 = conflict-free
// ---------------------------------------------------------------------------
#define QST 136
#define KST 72
#define BST 72
#define ATT_SMEM 64000
#define KVBUF (32 * KST * 2)      // bytes per K or V stage
#define BBUF  (128 * BST * 2)     // bytes per bias stage (bf16)

__global__ void __launch_bounds__(256, 2) attn_mma_kernel(
    const __nv_bfloat16* __restrict__ qb, const __nv_bfloat16* __restrict__ kb,
    const __nv_bfloat16* __restrict__ vb, const __nv_bfloat16* __restrict__ bias,
    __nv_bfloat16* __restrict__ res)
{
    extern __shared__ __align__(16) char smraw[];
    __nv_bfloat16* Qs = (__nv_bfloat16*)smraw;
    __nv_bfloat16* BiasS = (__nv_bfloat16*)(smraw + 27136);

    const int b = blockIdx.x, h = blockIdx.y;
    const int i0 = blockIdx.z * 128;
    const int tid = threadIdx.x, lane = tid & 31, w = tid >> 5;

    const __nv_bfloat16* qsrc = qb + ((size_t)b * 256 + h * 32) * HW_;
    const __nv_bfloat16* ksrc = kb + ((size_t)b * 256 + h * 32) * KHW_;
    const __nv_bfloat16* vsrc = vb + ((size_t)b * 256 + h * 32) * KHW_;
    const __nv_bfloat16* bias_h = bias + (size_t)h * HW_ * KHW_;

    const uint32_t qbase = smem_u32(smraw);
    const uint32_t kbase0 = qbase + 8704;
    const uint32_t vbase0 = qbase + 17920;
    const uint32_t bbase0 = qbase + 27136;

    // --- Q tile: [32 d][128 i] direct copy ---
    #pragma unroll
    for (int f = tid; f < 512; f += 256) {
        int d = f >> 4, ii = (f & 15) * 8;
        int gi = i0 + ii; if (gi > HW_ - 8) gi = HW_ - 8;
        *(uint4*)&Qs[d * QST + ii] = *(const uint4*)(qsrc + (size_t)d * HW_ + gi);
    }

    // tile loader (K, V, bias) via cp.async
    auto load_tile = [&](int j0, int buf) {
        {
            int d = tid >> 3, jj = (tid & 7) * 8;
            int gj = j0 + jj; if (gj > KHW_ - 8) gj = KHW_ - 8;
            cp16(kbase0 + buf * KVBUF + (uint32_t)((d * KST + jj) * 2),
                 ksrc + (size_t)d * KHW_ + gj);
            cp16(vbase0 + buf * KVBUF + (uint32_t)((d * KST + jj) * 2),
                 vsrc + (size_t)d * KHW_ + gj);
        }
        #pragma unroll
        for (int t = 0; t < 4; t++) {
            int f = tid + t * 256;                 // f < 1024
            int r = f >> 3, c8 = (f & 7) * 8;
            int gr = i0 + r; if (gr > HW_ - 1) gr = HW_ - 1;
            int gc = j0 + c8; if (gc > KHW_ - 8) gc = KHW_ - 8;
            cp16(bbase0 + buf * BBUF + (uint32_t)((r * BST + c8) * 2),
                 bias_h + (size_t)gr * KHW_ + gc);
        }
    };

    load_tile(0, 0);
    cp_commit();
    __syncthreads();   // Q tile visible

    // --- Q A-fragments (trans from [k][m]) ---
    uint32_t qa[2][4];
    {
        int krow = (lane & 7) + ((lane >> 4) & 1) * 8;
        int mcol = w * 16 + ((lane >> 3) & 1) * 8;
        #pragma unroll
        for (int kk = 0; kk < 2; kk++)
            ldm_x4_t(qa[kk], qbase + (uint32_t)(((kk * 16 + krow) * QST + mcol) * 2));
    }

    float m0 = -1e30f, m1 = -1e30f;
    float l0 = 0.f, l1 = 0.f;
    float oacc[4][4];
    #pragma unroll
    for (int nf = 0; nf < 4; nf++)
        #pragma unroll
        for (int r = 0; r < 4; r++) oacc[nf][r] = 0.f;

    const int rA = w * 16 + (lane >> 2);
    const int rB = rA + 8;

    for (int jt = 0; jt < 13; jt++) {
        const int j0 = jt * 64;
        cp_wait_all();
        __syncthreads();
        if (jt + 1 < 13) { load_tile((jt + 1) * 64, (jt + 1) & 1); cp_commit(); }

        const int buf = jt & 1;
        const uint32_t kbase = kbase0 + buf * KVBUF;
        const uint32_t vbase = vbase0 + buf * KVBUF;
        const __nv_bfloat16* bsm = BiasS + buf * (128 * BST);

        // --- S = Q @ K^T ---
        float s[8][4];
        #pragma unroll
        for (int nf = 0; nf < 8; nf++)
            #pragma unroll
            for (int r = 0; r < 4; r++) s[nf][r] = 0.f;

        #pragma unroll
        for (int kk = 0; kk < 2; kk++) {
            uint32_t kbf[8][2];
            int krow = (lane & 7) + ((lane >> 3) & 1) * 8;
            int ncol = ((lane >> 4) & 1) * 8;
            #pragma unroll
            for (int jg = 0; jg < 4; jg++) {
                uint32_t r4[4];
                ldm_x4_t(r4, kbase + (uint32_t)(((kk * 16 + krow) * KST + jg * 16 + ncol) * 2));
                kbf[2 * jg][0] = r4[0]; kbf[2 * jg][1] = r4[1];
                kbf[2 * jg + 1][0] = r4[2]; kbf[2 * jg + 1][1] = r4[3];
            }
            #pragma unroll
            for (int nf = 0; nf < 8; nf++) mma_bf16(s[nf], qa[kk], kbf[nf]);
        }

        // --- bias (bf16 smem) + mask + online softmax ---
        float rmax0 = -1e30f, rmax1 = -1e30f;
        #pragma unroll
        for (int nf = 0; nf < 8; nf++) {
            int cj = nf * 8 + (lane & 3) * 2;
            int gj = j0 + cj;
            bool jv = (gj < KHW_);
            float2 bA = __bfloat1622float2(*(const __nv_bfloat162*)(bsm + rA * BST + cj));
            float2 bB = __bfloat1622float2(*(const __nv_bfloat162*)(bsm + rB * BST + cj));
            float v0 = s[nf][0] + bA.x, v1 = s[nf][1] + bA.y;
            float v2 = s[nf][2] + bB.x, v3 = s[nf][3] + bB.y;
            if (!jv) { v0 = v1 = v2 = v3 = -1e30f; }
            s[nf][0] = v0; s[nf][1] = v1; s[nf][2] = v2; s[nf][3] = v3;
            rmax0 = fmaxf(rmax0, fmaxf(v0, v1));
            rmax1 = fmaxf(rmax1, fmaxf(v2, v3));
        }
        #pragma unroll
        for (int o = 1; o <= 2; o <<= 1) {
            rmax0 = fmaxf(rmax0, __shfl_xor_sync(0xffffffffu, rmax0, o));
            rmax1 = fmaxf(rmax1, __shfl_xor_sync(0xffffffffu, rmax1, o));
        }
        float mn0 = fmaxf(m0, rmax0), mn1 = fmaxf(m1, rmax1);
        float al0 = __expf(m0 - mn0), al1 = __expf(m1 - mn1);
        m0 = mn0; m1 = mn1;

        float rs0 = 0.f, rs1 = 0.f;
        uint32_t pa[4][4];
        #pragma unroll
        for (int nf = 0; nf < 8; nf++) {
            float p0 = __expf(s[nf][0] - mn0);
            float p1 = __expf(s[nf][1] - mn0);
            float p2 = __expf(s[nf][2] - mn1);
            float p3 = __expf(s[nf][3] - mn1);
            rs0 += p0 + p1; rs1 += p2 + p3;
            pa[nf >> 1][(nf & 1) * 2 + 0] = pack_bf16x2(p0, p1);
            pa[nf >> 1][(nf & 1) * 2 + 1] = pack_bf16x2(p2, p3);
        }
        #pragma unroll
        for (int o = 1; o <= 2; o <<= 1) {
            rs0 += __shfl_xor_sync(0xffffffffu, rs0, o);
            rs1 += __shfl_xor_sync(0xffffffffu, rs1, o);
        }
        l0 = al0 * l0 + rs0;
        l1 = al1 * l1 + rs1;
        #pragma unroll
        for (int nf = 0; nf < 4; nf++) {
            oacc[nf][0] *= al0; oacc[nf][1] *= al0;
            oacc[nf][2] *= al1; oacc[nf][3] *= al1;
        }

        // --- O += P @ V ---
        uint32_t vbf[4][4][2];
        {
            int rr = ((lane >> 3) & 1) * 8 + (lane & 7);
            int ch = (lane >> 4) & 1;
            #pragma unroll
            for (int ng = 0; ng < 2; ng++)
                #pragma unroll
                for (int kf = 0; kf < 4; kf++) {
                    uint32_t r4[4];
                    ldm_x4(r4, vbase + (uint32_t)(((ng * 16 + rr) * KST + kf * 16 + ch * 8) * 2));
                    vbf[2 * ng][kf][0] = r4[0]; vbf[2 * ng][kf][1] = r4[2];
                    vbf[2 * ng + 1][kf][0] = r4[1]; vbf[2 * ng + 1][kf][1] = r4[3];
                }
        }
        #pragma unroll
        for (int kf = 0; kf < 4; kf++)
            #pragma unroll
            for (int nf = 0; nf < 4; nf++)
                mma_bf16(oacc[nf], pa[kf], vbf[nf][kf]);
    }

    // --- epilogue: normalize + bf16 store to res[b][i][hd] ---
    float inv0 = 1.f / l0, inv1 = 1.f / l1;
    int giA = i0 + w * 16 + (lane >> 2);
    int giB = giA + 8;
    #pragma unroll
    for (int nf = 0; nf < 4; nf++) {
        int col = h * 32 + nf * 8 + (lane & 3) * 2;
        if (giA < HW_)
            *(__nv_bfloat162*)(res + ((size_t)(b * HW_ + giA)) * 256 + col) =
                __floats2bfloat162_rn(oacc[nf][0] * inv0, oacc[nf][1] * inv0);
        if (giB < HW_)
            *(__nv_bfloat162*)(res + ((size_t)(b * HW_ + giB)) * 256 + col) =
                __floats2bfloat162_rn(oacc[nf][2] * inv1, oacc[nf][3] * inv1);
    }
}

// ---------------------------------------------------------------------------
extern "C" void kernel_launch(void* const* d_in, const int* in_sizes, int n_in,
                              void* d_out, int out_size) {
    const float* x     = (const float*)d_in[0];
    const float* Wk_dw = (const float*)d_in[1];
    const float* bk_dw = (const float*)d_in[2];
    const float* Wv_dw = (const float*)d_in[3];
    const float* bv_dw = (const float*)d_in[4];
    const float* Wq    = (const float*)d_in[5];
    const float* bq    = (const float*)d_in[6];
    const float* Wk    = (const float*)d_in[7];
    const float* bk    = (const float*)d_in[8];
    const float* Wv    = (const float*)d_in[9];
    const float* bv    = (const float*)d_in[10];
    const float* Wo    = (const float*)d_in[11];
    const float* bo    = (const float*)d_in[12];
    const float* Bb    = (const float*)d_in[13];
    float* out = (float*)d_out;

    __nv_bfloat16 *qp, *kp, *vp, *resp, *ckp, *cvp, *xbfp, *bbfp;
    __nv_bfloat16 *wqp, *wkp, *wvp, *wop;
    float *cqp;
    cudaGetSymbolAddress((void**)&qp,   g_q);
    cudaGetSymbolAddress((void**)&kp,   g_k);
    cudaGetSymbolAddress((void**)&vp,   g_v);
    cudaGetSymbolAddress((void**)&resp, g_res);
    cudaGetSymbolAddress((void**)&ckp,  g_ck);
    cudaGetSymbolAddress((void**)&cvp,  g_cv);
    cudaGetSymbolAddress((void**)&xbfp, g_xbf);
    cudaGetSymbolAddress((void**)&bbfp, g_bbf);
    cudaGetSymbolAddress((void**)&wqp,  g_wq);
    cudaGetSymbolAddress((void**)&wkp,  g_wk);
    cudaGetSymbolAddress((void**)&wvp,  g_wv);
    cudaGetSymbolAddress((void**)&wop,  g_wo);
    cudaGetSymbolAddress((void**)&cqp,  g_cq);

    cudaFuncSetAttribute(attn_mma_kernel,
                         cudaFuncAttributeMaxDynamicSharedMemorySize, ATT_SMEM);

    // Fork two side streams off the (possibly capturing) default stream.
    cudaStream_t s1, s2;
    cudaStreamCreateWithFlags(&s1, cudaStreamNonBlocking);
    cudaStreamCreateWithFlags(&s2, cudaStreamNonBlocking);
    cudaEvent_t evRoot, evW, ev1, ev2;
    cudaEventCreateWithFlags(&evRoot, cudaEventDisableTiming);
    cudaEventCreateWithFlags(&evW,    cudaEventDisableTiming);
    cudaEventCreateWithFlags(&ev1,    cudaEventDisableTiming);
    cudaEventCreateWithFlags(&ev2,    cudaEventDisableTiming);

    cudaEventRecord(evRoot, 0);
    cudaStreamWaitEvent(s1, evRoot, 0);
    cudaStreamWaitEvent(s2, evRoot, 0);

    // side stream 1: bias conversion (independent until attention)
    cvt_bias<<<BIASN_ / 8 / 256, 256, 0, s1>>>(Bb);
    cudaEventRecord(ev1, s1);

    // side stream 2: dwconv (depends only on x), then K/V GEMMs (need cvt_w)
    dwconv_kernel<<<(B_ * C_ * KHW_ + 255) / 256, 256, 0, s2>>>(x, Wk_dw, bk_dw, Wv_dw, bv_dw);

    // main chain: x conversion + stats, weight conversion, Q GEMM
    cvt_x_stats<<<NPART_, 256>>>(x);
    cvt_w_kernel<<<256, 256>>>(Wq, Wk, Wv, Wo);
    cudaEventRecord(evW, 0);
    stats_final<<<1, 256>>>(bq);
    gemm_wx<<<dim3(25, 2, B_), 256>>>(wqp, xbfp, cqp, 1, HW_, qp);

    cudaStreamWaitEvent(s2, evW, 0);
    gemm_wx<<<dim3(7, 2, B_), 256, 0, s2>>>(wkp, ckp, bk, 0, KHW_, kp);
    gemm_wx<<<dim3(7, 2, B_), 256, 0, s2>>>(wvp, cvp, bv, 0, KHW_, vp);
    cudaEventRecord(ev2, s2);

    // join before attention
    cudaStreamWaitEvent(0, ev1, 0);
    cudaStreamWaitEvent(0, ev2, 0);

    attn_mma_kernel<<<dim3(B_, HEADS_, 25), 256, ATT_SMEM>>>(qp, kp, vp, bbfp, resp);

    gemm_o<<<dim3(25, 2, B_), 256>>>(resp, wop, bo, x, out);

    cudaEventDestroy(evRoot);
    cudaEventDestroy(evW);
    cudaEventDestroy(ev1);
    cudaEventDestroy(ev2);
    cudaStreamDestroy(s1);
    cudaStreamDestroy(s2);
}

// round 7
// speedup vs baseline: 16.8509x; 1.0907x over previous
#include <cuda_runtime.h>
#include <cuda_bf16.h>
#include <cuda_fp16.h>
#include <math.h>
#include <stdint.h>

// Problem constants
#define B_   8
#define C_   256
#define H_   56
#define W_   56
#define HW_  3136        // 56*56
#define KHW_ 784         // 28*28
#define HEADS_ 8
#define NTOT_ 6422528    // B*C*HW
#define NPART_ 6272      // NTOT/4/256 blocks in fused cvt+stats
#define BIASN_ 19668992  // HEADS*HW*KHW
#define EPS_ 1e-5
#define SCALE_ 0.17677669529663687f   // 1/sqrt(32)
#define LOG2E_ 1.4426950408889634f

// Scratch (static device arrays — allocation-free)
__device__ __nv_bfloat16 g_q[B_ * 256 * HW_];    // [b][hd][i]  (log2e-scaled)
__device__ __nv_bfloat16 g_k[B_ * 256 * KHW_];   // [b][hd][j]
__device__ __half        g_v[B_ * 256 * KHW_];   // [b][hd][j]  fp16
__device__ __nv_bfloat16 g_res[B_ * HW_ * 256];  // [b][i][hd]
__device__ __nv_bfloat16 g_ck[B_ * C_ * KHW_];   // conv-K out bf16 [b][c][j]
__device__ __nv_bfloat16 g_cv[B_ * C_ * KHW_];
__device__ __nv_bfloat16 g_xbf[NTOT_];           // x in bf16 [b][c][hw]
__device__ __nv_bfloat16 g_bbf[BIASN_];          // bias*log2e in bf16
__device__ __nv_bfloat16 g_wq[65536], g_wk[65536], g_wv[65536], g_wo[65536];
__device__ float g_part[2 * NPART_];
__device__ float g_wqsum[256];
__device__ float g_stats[2];                     // mu, rstd
__device__ float g_cq[256];                      // folded Q bias

// ---------------------------------------------------------------------------
// asm helpers
// ---------------------------------------------------------------------------
__device__ __forceinline__ uint32_t smem_u32(const void* p) {
    return (uint32_t)__cvta_generic_to_shared(p);
}
__device__ __forceinline__ void ldm_x4(uint32_t* r, uint32_t addr) {
    asm volatile("ldmatrix.sync.aligned.m8n8.x4.shared.b16 {%0,%1,%2,%3}, [%4];"
        : "=r"(r[0]), "=r"(r[1]), "=r"(r[2]), "=r"(r[3]) : "r"(addr));
}
__device__ __forceinline__ void ldm_x4_t(uint32_t* r, uint32_t addr) {
    asm volatile("ldmatrix.sync.aligned.m8n8.x4.trans.shared.b16 {%0,%1,%2,%3}, [%4];"
        : "=r"(r[0]), "=r"(r[1]), "=r"(r[2]), "=r"(r[3]) : "r"(addr));
}
__device__ __forceinline__ void mma_bf16(float* d, const uint32_t* a, const uint32_t* b) {
    asm volatile(
        "mma.sync.aligned.m16n8k16.row.col.f32.bf16.bf16.f32 "
        "{%0,%1,%2,%3}, {%4,%5,%6,%7}, {%8,%9}, {%0,%1,%2,%3};"
        : "+f"(d[0]), "+f"(d[1]), "+f"(d[2]), "+f"(d[3])
        : "r"(a[0]), "r"(a[1]), "r"(a[2]), "r"(a[3]), "r"(b[0]), "r"(b[1]));
}
__device__ __forceinline__ void mma_f16(float* d, const uint32_t* a, const uint32_t* b) {
    asm volatile(
        "mma.sync.aligned.m16n8k16.row.col.f32.f16.f16.f32 "
        "{%0,%1,%2,%3}, {%4,%5,%6,%7}, {%8,%9}, {%0,%1,%2,%3};"
        : "+f"(d[0]), "+f"(d[1]), "+f"(d[2]), "+f"(d[3])
        : "r"(a[0]), "r"(a[1]), "r"(a[2]), "r"(a[3]), "r"(b[0]), "r"(b[1]));
}
// pack (lo,hi) to f16x2 and apply 2^x per half
__device__ __forceinline__ uint32_t packex2(float lo, float hi) {
    uint32_t t, r;
    asm("cvt.rn.f16x2.f32 %0, %1, %2;" : "=r"(t) : "f"(hi), "f"(lo));
    asm("ex2.approx.f16x2 %0, %1;" : "=r"(r) : "r"(t));
    return r;
}
__device__ __forceinline__ void cp16(uint32_t dst, const void* src) {
    asm volatile("cp.async.cg.shared.global [%0], [%1], 16;" :: "r"(dst), "l"(src));
}
__device__ __forceinline__ void cp_commit() {
    asm volatile("cp.async.commit_group;" ::: "memory");
}
__device__ __forceinline__ void cp_wait_all() {
    asm volatile("cp.async.wait_group 0;" ::: "memory");
}
__device__ __forceinline__ void cp_wait_1() {
    asm volatile("cp.async.wait_group 1;" ::: "memory");
}

// ---------------------------------------------------------------------------
// Fused: x fp32 -> bf16 + LN partial sums (x read ONCE)
// ---------------------------------------------------------------------------
__global__ void cvt_x_stats(const float* __restrict__ x) {
    int tid = threadIdx.x;
    int i = blockIdx.x * 256 + tid;
    float4 v = ((const float4*)x)[i];
    __nv_bfloat162* o = (__nv_bfloat162*)(g_xbf + (size_t)i * 4);
    o[0] = __floats2bfloat162_rn(v.x, v.y);
    o[1] = __floats2bfloat162_rn(v.z, v.w);
    float s  = v.x + v.y + v.z + v.w;
    float ss = v.x * v.x + v.y * v.y + v.z * v.z + v.w * v.w;
    #pragma unroll
    for (int ofs = 16; ofs; ofs >>= 1) {
        s  += __shfl_xor_sync(0xffffffffu, s, ofs);
        ss += __shfl_xor_sync(0xffffffffu, ss, ofs);
    }
    __shared__ float sh[16];
    int w = tid >> 5, lane = tid & 31;
    if (lane == 0) { sh[w] = s; sh[8 + w] = ss; }
    __syncthreads();
    if (tid == 0) {
        float a = 0.f, b = 0.f;
        #pragma unroll
        for (int k = 0; k < 8; k++) { a += sh[k]; b += sh[8 + k]; }
        g_part[blockIdx.x] = a;
        g_part[NPART_ + blockIdx.x] = b;
    }
}

// ---------------------------------------------------------------------------
// Weight conversions (vectorized) + Wq rowsum (block r handles row r)
// ---------------------------------------------------------------------------
__global__ void cvt_w_kernel(const float* __restrict__ Wq, const float* __restrict__ Wk,
                             const float* __restrict__ Wv, const float* __restrict__ Wo) {
    int r = blockIdx.x, tid = threadIdx.x;   // 256 blocks x 64 threads? -> 256 threads, 4 elems each
    int base = r * 256 + (tid & 63) * 4;
    // each thread converts 4 elems of each matrix (threads 0-63 cover the row; 4 groups)
    int grp = tid >> 6;      // 0..3 selects matrix
    const float* src = (grp == 0) ? Wq : (grp == 1) ? Wk : (grp == 2) ? Wv : Wo;
    __nv_bfloat16* dst = (grp == 0) ? g_wq : (grp == 1) ? g_wk : (grp == 2) ? g_wv : g_wo;
    float4 v = *(const float4*)(src + base);
    *(__nv_bfloat162*)(dst + base)     = __floats2bfloat162_rn(v.x, v.y);
    *(__nv_bfloat162*)(dst + base + 2) = __floats2bfloat162_rn(v.z, v.w);
    // rowsum of Wq from group 0 threads
    float s = (grp == 0) ? (v.x + v.y) + (v.z + v.w) : 0.f;
    #pragma unroll
    for (int ofs = 16; ofs; ofs >>= 1) s += __shfl_xor_sync(0xffffffffu, s, ofs);
    __shared__ float sh[8];
    if ((tid & 31) == 0) sh[tid >> 5] = s;
    __syncthreads();
    if (tid == 0) g_wqsum[r] = sh[0] + sh[1];
}

// ---------------------------------------------------------------------------
// Bias fp32 -> bf16, scaled by log2e (log2-domain softmax)
// ---------------------------------------------------------------------------
__global__ void cvt_bias(const float* __restrict__ Bb) {
    size_t i = (size_t)blockIdx.x * 256 + threadIdx.x;   // group of 8
    float4 a = ((const float4*)Bb)[2 * i];
    float4 b = ((const float4*)Bb)[2 * i + 1];
    __nv_bfloat162* o = (__nv_bfloat162*)(g_bbf + i * 8);
    o[0] = __floats2bfloat162_rn(a.x * LOG2E_, a.y * LOG2E_);
    o[1] = __floats2bfloat162_rn(a.z * LOG2E_, a.w * LOG2E_);
    o[2] = __floats2bfloat162_rn(b.x * LOG2E_, b.y * LOG2E_);
    o[3] = __floats2bfloat162_rn(b.z * LOG2E_, b.w * LOG2E_);
}

// ---------------------------------------------------------------------------
// Finalize mu/rstd + folded Q bias
// ---------------------------------------------------------------------------
__global__ void stats_final(const float* __restrict__ bq) {
    int tid = threadIdx.x;
    const float4* p4  = (const float4*)g_part;
    const float4* ps4 = (const float4*)(g_part + NPART_);
    double s = 0.0, ss = 0.0;
    for (int i = tid; i < NPART_ / 4; i += 256) {
        float4 a = p4[i];
        float4 b = ps4[i];
        s  += (double)((a.x + a.y) + (a.z + a.w));
        ss += (double)((b.x + b.y) + (b.z + b.w));
    }
    __shared__ double shs[256], shss[256];
    shs[tid] = s; shss[tid] = ss;
    __syncthreads();
    for (int o = 128; o; o >>= 1) {
        if (tid < o) { shs[tid] += shs[tid + o]; shss[tid] += shss[tid + o]; }
        __syncthreads();
    }
    __shared__ float mu_s, rstd_s;
    if (tid == 0) {
        double N = (double)NTOT_;
        double mu = shs[0] / N;
        double var = shss[0] / N - mu * mu;
        float rstd = (float)(1.0 / sqrt(var + EPS_));
        g_stats[0] = (float)mu;
        g_stats[1] = rstd;
        mu_s = (float)mu; rstd_s = rstd;
    }
    __syncthreads();
    g_cq[tid] = bq[tid] - rstd_s * mu_s * g_wqsum[tid];
}

// ---------------------------------------------------------------------------
// Depthwise 3x3 stride-2 conv (K and V paths fused), bf16 output
// ---------------------------------------------------------------------------
__global__ void dwconv_kernel(const float* __restrict__ x,
                              const float* __restrict__ wk, const float* __restrict__ bkd,
                              const float* __restrict__ wv, const float* __restrict__ bvd) {
    int idx = blockIdx.x * blockDim.x + threadIdx.x;
    if (idx >= B_ * C_ * KHW_) return;
    int ox = idx % 28;
    int oy = (idx / 28) % 28;
    int c  = (idx / KHW_) % C_;
    int b  = idx / (KHW_ * C_);
    const float* xp = x + ((size_t)(b * C_ + c)) * HW_;
    float ak = 0.f, av = 0.f;
    #pragma unroll
    for (int ky = 0; ky < 3; ky++) {
        int iy = oy * 2 + ky - 1;
        if (iy < 0 || iy >= H_) continue;
        #pragma unroll
        for (int kx = 0; kx < 3; kx++) {
            int ix = ox * 2 + kx - 1;
            if (ix < 0 || ix >= W_) continue;
            float xv = xp[iy * W_ + ix];
            ak += xv * wk[c * 9 + ky * 3 + kx];
            av += xv * wv[c * 9 + ky * 3 + kx];
        }
    }
    g_ck[idx] = __float2bfloat16(ak + bkd[c]);
    g_cv[idx] = __float2bfloat16(av + bvd[c]);
}

// ---------------------------------------------------------------------------
// bf16 mma GEMM (2-stage cp.async): out[b][R][P] = a1*sum_k W[R][k]*X[b][k][P]
//   + a2*cvec[R].  mode: 0 = K (bf16 out), 1 = Q (bf16, LN+scale+log2e),
//   2 = V (fp16 out)
// ---------------------------------------------------------------------------
#define WST 40
#define XST 136
__global__ void __launch_bounds__(256, 2) gemm_wx(
    const __nv_bfloat16* __restrict__ W, const __nv_bfloat16* __restrict__ X,
    const float* __restrict__ cvec, int mode, int Mt,
    void* __restrict__ outp)
{
    __shared__ __align__(16) __nv_bfloat16 Ws[2][128 * WST];
    __shared__ __align__(16) __nv_bfloat16 Xs[2][32 * XST];
    const int P0 = blockIdx.x * 128;
    const int R0 = blockIdx.y * 128;
    const int b  = blockIdx.z;
    const __nv_bfloat16* Xb = X + (size_t)b * 256 * Mt;
    const int tid = threadIdx.x, lane = tid & 31, w = tid >> 5;
    const int wR = (w >> 2) * 64, wP = (w & 3) * 32;

    float c[4][4][4];
    #pragma unroll
    for (int i = 0; i < 4; i++)
        #pragma unroll
        for (int j = 0; j < 4; j++)
            #pragma unroll
            for (int r = 0; r < 4; r++) c[i][j][r] = 0.f;

    const uint32_t wsb = smem_u32(Ws), xsb = smem_u32(Xs);

    auto load_stage = [&](int k0, int buf) {
        uint32_t wd = wsb + buf * (128 * WST * 2);
        uint32_t xd = xsb + buf * (32 * XST * 2);
        #pragma unroll
        for (int t = 0; t < 2; t++) {
            int f = tid + t * 256;
            int r = f >> 2, cc = (f & 3) * 8;
            cp16(wd + (uint32_t)((r * WST + cc) * 2),
                 W + (size_t)(R0 + r) * 256 + k0 + cc);
        }
        #pragma unroll
        for (int t = 0; t < 2; t++) {
            int f = tid + t * 256;
            int kk = f >> 4, p = (f & 15) * 8;
            int gp = P0 + p; if (gp > Mt - 8) gp = Mt - 8;
            cp16(xd + (uint32_t)((kk * XST + p) * 2),
                 Xb + (size_t)(k0 + kk) * Mt + gp);
        }
    };

    load_stage(0, 0);
    cp_commit();

    for (int s = 0; s < 8; s++) {
        cp_wait_all();
        __syncthreads();
        if (s + 1 < 8) { load_stage((s + 1) * 32, (s + 1) & 1); cp_commit(); }
        const int buf = s & 1;
        const uint32_t wb = wsb + buf * (128 * WST * 2);
        const uint32_t xb = xsb + buf * (32 * XST * 2);

        #pragma unroll
        for (int kk = 0; kk < 2; kk++) {
            uint32_t af[4][4], bf[4][2];
            {
                int rr = ((lane >> 3) & 1) * 8 + (lane & 7);
                int ch = (lane >> 4) & 1;
                #pragma unroll
                for (int rf = 0; rf < 4; rf++)
                    ldm_x4(af[rf], wb + (uint32_t)(((wR + rf * 16 + rr) * WST + kk * 16 + ch * 8) * 2));
            }
            {
                int krow = (lane & 7) + ((lane >> 3) & 1) * 8;
                int pc = ((lane >> 4) & 1) * 8;
                #pragma unroll
                for (int pf = 0; pf < 2; pf++) {
                    uint32_t r4[4];
                    ldm_x4_t(r4, xb + (uint32_t)(((kk * 16 + krow) * XST + wP + pf * 16 + pc) * 2));
                    bf[2 * pf][0] = r4[0]; bf[2 * pf][1] = r4[1];
                    bf[2 * pf + 1][0] = r4[2]; bf[2 * pf + 1][1] = r4[3];
                }
            }
            #pragma unroll
            for (int rf = 0; rf < 4; rf++)
                #pragma unroll
                for (int pg = 0; pg < 4; pg++)
                    mma_bf16(c[rf][pg], af[rf], bf[pg]);
        }
        __syncthreads();
    }

    float a1 = 1.f, a2 = 1.f;
    if (mode == 1) { a1 = g_stats[1] * SCALE_ * LOG2E_; a2 = SCALE_ * LOG2E_; }
    #pragma unroll
    for (int rf = 0; rf < 4; rf++) {
        int R = R0 + wR + rf * 16 + (lane >> 2);
        float cv1 = a2 * cvec[R], cv2 = a2 * cvec[R + 8];
        #pragma unroll
        for (int pg = 0; pg < 4; pg++) {
            int P = P0 + wP + pg * 8 + (lane & 3) * 2;
            if (P < Mt) {
                if (mode == 2) {
                    __half* ob = (__half*)outp + (size_t)b * 256 * Mt;
                    *(__half2*)(ob + (size_t)R * Mt + P) =
                        __floats2half2_rn(a1 * c[rf][pg][0] + cv1, a1 * c[rf][pg][1] + cv1);
                    *(__half2*)(ob + (size_t)(R + 8) * Mt + P) =
                        __floats2half2_rn(a1 * c[rf][pg][2] + cv2, a1 * c[rf][pg][3] + cv2);
                } else {
                    __nv_bfloat16* ob = (__nv_bfloat16*)outp + (size_t)b * 256 * Mt;
                    *(__nv_bfloat162*)(ob + (size_t)R * Mt + P) =
                        __floats2bfloat162_rn(a1 * c[rf][pg][0] + cv1, a1 * c[rf][pg][1] + cv1);
                    *(__nv_bfloat162*)(ob + (size_t)(R + 8) * Mt + P) =
                        __floats2bfloat162_rn(a1 * c[rf][pg][2] + cv2, a1 * c[rf][pg][3] + cv2);
                }
            }
        }
    }
}

// ---------------------------------------------------------------------------
// O projection mma GEMM (2-stage cp.async) + fused bias + flat residual add
// ---------------------------------------------------------------------------
__global__ void __launch_bounds__(256, 2) gemm_o(
    const __nv_bfloat16* __restrict__ A, const __nv_bfloat16* __restrict__ Wo,
    const float* __restrict__ bo, const float* __restrict__ x,
    float* __restrict__ out)
{
    __shared__ __align__(16) __nv_bfloat16 As[2][128 * WST];
    __shared__ __align__(16) __nv_bfloat16 Bs[2][128 * WST];
    const int I0 = blockIdx.x * 128;
    const int N0 = blockIdx.y * 128;
    const int b  = blockIdx.z;
    const int tid = threadIdx.x, lane = tid & 31, w = tid >> 5;
    const int wI = (w >> 2) * 64, wN = (w & 3) * 32;

    float c[4][4][4];
    #pragma unroll
    for (int i = 0; i < 4; i++)
        #pragma unroll
        for (int j = 0; j < 4; j++)
            #pragma unroll
            for (int r = 0; r < 4; r++) c[i][j][r] = 0.f;

    const uint32_t asb = smem_u32(As), bsb = smem_u32(Bs);

    auto load_stage = [&](int k0, int buf) {
        uint32_t ad = asb + buf * (128 * WST * 2);
        uint32_t bd = bsb + buf * (128 * WST * 2);
        #pragma unroll
        for (int t = 0; t < 2; t++) {
            int f = tid + t * 256;
            int i = f >> 2, cc = (f & 3) * 8;
            int gi = I0 + i; if (gi > HW_ - 1) gi = HW_ - 1;
            cp16(ad + (uint32_t)((i * WST + cc) * 2),
                 A + ((size_t)(b * HW_) + gi) * 256 + k0 + cc);
        }
        #pragma unroll
        for (int t = 0; t < 2; t++) {
            int f = tid + t * 256;
            int n = f >> 2, cc = (f & 3) * 8;
            cp16(bd + (uint32_t)((n * WST + cc) * 2),
                 Wo + (size_t)(N0 + n) * 256 + k0 + cc);
        }
    };

    load_stage(0, 0);
    cp_commit();

    for (int s = 0; s < 8; s++) {
        cp_wait_all();
        __syncthreads();
        if (s + 1 < 8) { load_stage((s + 1) * 32, (s + 1) & 1); cp_commit(); }
        const int buf = s & 1;
        const uint32_t ab = asb + buf * (128 * WST * 2);
        const uint32_t bb = bsb + buf * (128 * WST * 2);

        #pragma unroll
        for (int kk = 0; kk < 2; kk++) {
            int rr = ((lane >> 3) & 1) * 8 + (lane & 7);
            int ch = (lane >> 4) & 1;
            uint32_t af[4][4], bf[4][2];
            #pragma unroll
            for (int mf = 0; mf < 4; mf++)
                ldm_x4(af[mf], ab + (uint32_t)(((wI + mf * 16 + rr) * WST + kk * 16 + ch * 8) * 2));
            #pragma unroll
            for (int ng = 0; ng < 2; ng++) {
                uint32_t r4[4];
                ldm_x4(r4, bb + (uint32_t)(((wN + ng * 16 + rr) * WST + kk * 16 + ch * 8) * 2));
                bf[2 * ng][0] = r4[0]; bf[2 * ng][1] = r4[2];
                bf[2 * ng + 1][0] = r4[1]; bf[2 * ng + 1][1] = r4[3];
            }
            #pragma unroll
            for (int mf = 0; mf < 4; mf++)
                #pragma unroll
                for (int nf = 0; nf < 4; nf++)
                    mma_bf16(c[mf][nf], af[mf], bf[nf]);
        }
        __syncthreads();
    }

    #pragma unroll
    for (int mf = 0; mf < 4; mf++) {
        int i1 = I0 + wI + mf * 16 + (lane >> 2);
        int i2 = i1 + 8;
        #pragma unroll
        for (int nf = 0; nf < 4; nf++) {
            int n = N0 + wN + nf * 8 + (lane & 3) * 2;
            float b0v = bo[n], b1v = bo[n + 1];
            if (i1 < HW_) {
                size_t flat = (size_t)b * (256 * HW_) + (size_t)i1 * 256 + n;
                float2 xv = *(const float2*)(x + flat);
                *(float2*)(out + flat) =
                    make_float2(c[mf][nf][0] + b0v + xv.x, c[mf][nf][1] + b1v + xv.y);
            }
            if (i2 < HW_) {
                size_t flat = (size_t)b * (256 * HW_) + (size_t)i2 * 256 + n;
                float2 xv = *(const float2*)(x + flat);
                *(float2*)(out + flat) =
                    make_float2(c[mf][nf][2] + b0v + xv.x, c[mf][nf][3] + b1v + xv.y);
            }
        }
    }
}

// ---------------------------------------------------------------------------
// Flash attention, log2-domain fixed-max softmax, f16x2 packed ex2,
// denominators via ones-column mma, 3-stage cp.async pipeline.
// smem: Qs 8704 | 3 stages x (K 4608 + V 4608 + bias 18432) = 91648 B
// ---------------------------------------------------------------------------
#define QST 136
#define KST 72
#define BST 72
#define KBUF  (32 * KST * 2)
#define VBUF  (32 * KST * 2)
#define BBUF  (128 * BST * 2)
#define STAGEB (KBUF + VBUF + BBUF)     // 27648
#define ATT_SMEM (8704 + 3 * STAGEB)    // 91648

__global__ void __launch_bounds__(256, 2) attn_mma_kernel(
    const __nv_bfloat16* __restrict__ qb, const __nv_bfloat16* __restrict__ kb,
    const __half* __restrict__ vb, const __nv_bfloat16* __restrict__ bias,
    __nv_bfloat16* __restrict__ res)
{
    extern __shared__ __align__(16) char smraw[];
    __nv_bfloat16* Qs = (__nv_bfloat16*)smraw;

    const int b = blockIdx.x, h = blockIdx.y;
    const int i0 = blockIdx.z * 128;
    const int tid = threadIdx.x, lane = tid & 31, w = tid >> 5;

    const __nv_bfloat16* qsrc = qb + ((size_t)b * 256 + h * 32) * HW_;
    const __nv_bfloat16* ksrc = kb + ((size_t)b * 256 + h * 32) * KHW_;
    const __half*        vsrc = vb + ((size_t)b * 256 + h * 32) * KHW_;
    const __nv_bfloat16* bias_h = bias + (size_t)h * HW_ * KHW_;

    const uint32_t qbase = smem_u32(smraw);
    const uint32_t stage0 = qbase + 8704;

    // --- Q tile: [32 d][128 i] direct copy ---
    #pragma unroll
    for (int f = tid; f < 512; f += 256) {
        int d = f >> 4, ii = (f & 15) * 8;
        int gi = i0 + ii; if (gi > HW_ - 8) gi = HW_ - 8;
        *(uint4*)&Qs[d * QST + ii] = *(const uint4*)(qsrc + (size_t)d * HW_ + gi);
    }

    auto load_tile = [&](int j0, int buf) {
        uint32_t sb = stage0 + buf * STAGEB;
        {
            int d = tid >> 3, jj = (tid & 7) * 8;
            int gj = j0 + jj; if (gj > KHW_ - 8) gj = KHW_ - 8;
            cp16(sb + (uint32_t)((d * KST + jj) * 2), ksrc + (size_t)d * KHW_ + gj);
            cp16(sb + KBUF + (uint32_t)((d * KST + jj) * 2), vsrc + (size_t)d * KHW_ + gj);
        }
        #pragma unroll
        for (int t = 0; t < 4; t++) {
            int f = tid + t * 256;                 // f < 1024
            int r = f >> 3, c8 = (f & 7) * 8;
            int gr = i0 + r; if (gr > HW_ - 1) gr = HW_ - 1;
            int gc = j0 + c8; if (gc > KHW_ - 8) gc = KHW_ - 8;
            cp16(sb + KBUF + VBUF + (uint32_t)((r * BST + c8) * 2),
                 bias_h + (size_t)gr * KHW_ + gc);
        }
    };

    load_tile(0, 0);  cp_commit();
    load_tile(64, 1); cp_commit();
    __syncthreads();   // Q tile visible

    // --- Q A-fragments ---
    uint32_t qa[2][4];
    {
        int krow = (lane & 7) + ((lane >> 4) & 1) * 8;
        int mcol = w * 16 + ((lane >> 3) & 1) * 8;
        #pragma unroll
        for (int kk = 0; kk < 2; kk++)
            ldm_x4_t(qa[kk], qbase + (uint32_t)(((kk * 16 + krow) * QST + mcol) * 2));
    }

    float oacc[4][4];
    #pragma unroll
    for (int nf = 0; nf < 4; nf++)
        #pragma unroll
        for (int r = 0; r < 4; r++) oacc[nf][r] = 0.f;
    float c5[4] = {0.f, 0.f, 0.f, 0.f};            // denominator accumulator
    const uint32_t bone = (lane < 4) ? 0x3C003C00u : 0u;  // ones-column B frag
    uint32_t bones[2] = {bone, bone};

    const int rA = w * 16 + (lane >> 2);
    const int rB = rA + 8;

    #pragma unroll 1
    for (int jt = 0; jt < 13; jt++) {
        if (jt == 12) cp_wait_all(); else cp_wait_1();
        __syncthreads();
        if (jt + 2 < 13) { load_tile((jt + 2) * 64, (jt + 2) % 3); cp_commit(); }

        const uint32_t sb = stage0 + (jt % 3) * STAGEB;
        const uint32_t kbase = sb;
        const uint32_t vbase = sb + KBUF;
        const __nv_bfloat16* bsm = (const __nv_bfloat16*)(smraw + (8704 + (jt % 3) * STAGEB + KBUF + VBUF));

        // --- S = Q @ K^T (log2-domain scores) ---
        float s[8][4];
        #pragma unroll
        for (int nf = 0; nf < 8; nf++)
            #pragma unroll
            for (int r = 0; r < 4; r++) s[nf][r] = 0.f;

        #pragma unroll
        for (int kk = 0; kk < 2; kk++) {
            uint32_t kbf[8][2];
            int krow = (lane & 7) + ((lane >> 3) & 1) * 8;
            int ncol = ((lane >> 4) & 1) * 8;
            #pragma unroll
            for (int jg = 0; jg < 4; jg++) {
                uint32_t r4[4];
                ldm_x4_t(r4, kbase + (uint32_t)(((kk * 16 + krow) * KST + jg * 16 + ncol) * 2));
                kbf[2 * jg][0] = r4[0]; kbf[2 * jg][1] = r4[1];
                kbf[2 * jg + 1][0] = r4[2]; kbf[2 * jg + 1][1] = r4[3];
            }
            #pragma unroll
            for (int nf = 0; nf < 8; nf++) mma_bf16(s[nf], qa[kk], kbf[nf]);
        }

        // --- V fragments (issued early to overlap softmax) ---
        uint32_t vbf[4][4][2];
        {
            int rr = ((lane >> 3) & 1) * 8 + (lane & 7);
            int ch = (lane >> 4) & 1;
            #pragma unroll
            for (int ng = 0; ng < 2; ng++)
                #pragma unroll
                for (int kf = 0; kf < 4; kf++) {
                    uint32_t r4[4];
                    ldm_x4(r4, vbase + (uint32_t)(((ng * 16 + rr) * KST + kf * 16 + ch * 8) * 2));
                    vbf[2 * ng][kf][0] = r4[0]; vbf[2 * ng][kf][1] = r4[2];
                    vbf[2 * ng + 1][kf][0] = r4[1]; vbf[2 * ng + 1][kf][1] = r4[3];
                }
        }

        // --- softmax numerators: p = 2^(s + bias_l2), fixed max ---
        uint32_t pa[4][4];
        const int cjb = (lane & 3) * 2;
        if (jt < 12) {
            #pragma unroll
            for (int nf = 0; nf < 8; nf++) {
                int cj = nf * 8 + cjb;
                float2 bA = __bfloat1622float2(*(const __nv_bfloat162*)(bsm + rA * BST + cj));
                float2 bB = __bfloat1622float2(*(const __nv_bfloat162*)(bsm + rB * BST + cj));
                pa[nf >> 1][(nf & 1) * 2 + 0] = packex2(s[nf][0] + bA.x, s[nf][1] + bA.y);
                pa[nf >> 1][(nf & 1) * 2 + 1] = packex2(s[nf][2] + bB.x, s[nf][3] + bB.y);
            }
        } else {
            #pragma unroll
            for (int a = 0; a < 4; a++)
                #pragma unroll
                for (int r = 0; r < 4; r++) pa[a][r] = 0u;
            #pragma unroll
            for (int nf = 0; nf < 2; nf++) {   // only 16 valid columns in last tile
                int cj = nf * 8 + cjb;
                float2 bA = __bfloat1622float2(*(const __nv_bfloat162*)(bsm + rA * BST + cj));
                float2 bB = __bfloat1622float2(*(const __nv_bfloat162*)(bsm + rB * BST + cj));
                pa[0][nf * 2 + 0] = packex2(s[nf][0] + bA.x, s[nf][1] + bA.y);
                pa[0][nf * 2 + 1] = packex2(s[nf][2] + bB.x, s[nf][3] + bB.y);
            }
        }

        // --- O += P @ V, denom += P @ ones ---
        #pragma unroll
        for (int kf = 0; kf < 4; kf++) {
            #pragma unroll
            for (int nf = 0; nf < 4; nf++)
                mma_f16(oacc[nf], pa[kf], vbf[nf][kf]);
            mma_f16(c5, pa[kf], bones);
        }
    }

    // --- epilogue: broadcast denominators, normalize, store ---
    int src = (lane >> 2) << 2;
    float l0 = __shfl_sync(0xffffffffu, c5[0], src);
    float l1 = __shfl_sync(0xffffffffu, c5[2], src);
    float inv0 = 1.f / l0, inv1 = 1.f / l1;
    int giA = i0 + rA;
    int giB = i0 + rB;
    #pragma unroll
    for (int nf = 0; nf < 4; nf++) {
        int col = h * 32 + nf * 8 + (lane & 3) * 2;
        if (giA < HW_)
            *(__nv_bfloat162*)(res + ((size_t)(b * HW_ + giA)) * 256 + col) =
                __floats2bfloat162_rn(oacc[nf][0] * inv0, oacc[nf][1] * inv0);
        if (giB < HW_)
            *(__nv_bfloat162*)(res + ((size_t)(b * HW_ + giB)) * 256 + col) =
                __floats2bfloat162_rn(oacc[nf][2] * inv1, oacc[nf][3] * inv1);
    }
}

// ---------------------------------------------------------------------------
extern "C" void kernel_launch(void* const* d_in, const int* in_sizes, int n_in,
                              void* d_out, int out_size) {
    const float* x     = (const float*)d_in[0];
    const float* Wk_dw = (const float*)d_in[1];
    const float* bk_dw = (const float*)d_in[2];
    const float* Wv_dw = (const float*)d_in[3];
    const float* bv_dw = (const float*)d_in[4];
    const float* Wq    = (const float*)d_in[5];
    const float* bq    = (const float*)d_in[6];
    const float* Wk    = (const float*)d_in[7];
    const float* bk    = (const float*)d_in[8];
    const float* Wv    = (const float*)d_in[9];
    const float* bv    = (const float*)d_in[10];
    const float* Wo    = (const float*)d_in[11];
    const float* bo    = (const float*)d_in[12];
    const float* Bb    = (const float*)d_in[13];
    float* out = (float*)d_out;

    __nv_bfloat16 *qp, *kp, *resp, *ckp, *cvp, *xbfp, *bbfp;
    __half* vp;
    __nv_bfloat16 *wqp, *wkp, *wvp, *wop;
    float *cqp;
    cudaGetSymbolAddress((void**)&qp,   g_q);
    cudaGetSymbolAddress((void**)&kp,   g_k);
    cudaGetSymbolAddress((void**)&vp,   g_v);
    cudaGetSymbolAddress((void**)&resp, g_res);
    cudaGetSymbolAddress((void**)&ckp,  g_ck);
    cudaGetSymbolAddress((void**)&cvp,  g_cv);
    cudaGetSymbolAddress((void**)&xbfp, g_xbf);
    cudaGetSymbolAddress((void**)&bbfp, g_bbf);
    cudaGetSymbolAddress((void**)&wqp,  g_wq);
    cudaGetSymbolAddress((void**)&wkp,  g_wk);
    cudaGetSymbolAddress((void**)&wvp,  g_wv);
    cudaGetSymbolAddress((void**)&wop,  g_wo);
    cudaGetSymbolAddress((void**)&cqp,  g_cq);

    cudaFuncSetAttribute(attn_mma_kernel,
                         cudaFuncAttributeMaxDynamicSharedMemorySize, ATT_SMEM);

    cudaStream_t s1, s2;
    cudaStreamCreateWithFlags(&s1, cudaStreamNonBlocking);
    cudaStreamCreateWithFlags(&s2, cudaStreamNonBlocking);
    cudaEvent_t evRoot, evW, ev1, ev2;
    cudaEventCreateWithFlags(&evRoot, cudaEventDisableTiming);
    cudaEventCreateWithFlags(&evW,    cudaEventDisableTiming);
    cudaEventCreateWithFlags(&ev1,    cudaEventDisableTiming);
    cudaEventCreateWithFlags(&ev2,    cudaEventDisableTiming);

    cudaEventRecord(evRoot, 0);
    cudaStreamWaitEvent(s1, evRoot, 0);
    cudaStreamWaitEvent(s2, evRoot, 0);

    // s1: weight conversion first (unblocks everything), then bias conversion
    cvt_w_kernel<<<256, 256, 0, s1>>>(Wq, Wk, Wv, Wo);
    cudaEventRecord(evW, s1);
    cvt_bias<<<BIASN_ / 8 / 256, 256, 0, s1>>>(Bb);
    cudaEventRecord(ev1, s1);

    // s2: dwconv, then K/V projections
    dwconv_kernel<<<(B_ * C_ * KHW_ + 255) / 256, 256, 0, s2>>>(x, Wk_dw, bk_dw, Wv_dw, bv_dw);
    cudaStreamWaitEvent(s2, evW, 0);
    gemm_wx<<<dim3(7, 2, B_), 256, 0, s2>>>(wkp, ckp, bk, 0, KHW_, kp);
    gemm_wx<<<dim3(7, 2, B_), 256, 0, s2>>>(wvp, cvp, bv, 2, KHW_, vp);
    cudaEventRecord(ev2, s2);

    // main: x conversion + stats, then Q projection
    cvt_x_stats<<<NPART_, 256>>>(x);
    cudaStreamWaitEvent(0, evW, 0);
    stats_final<<<1, 256>>>(bq);
    gemm_wx<<<dim3(25, 2, B_), 256>>>(wqp, xbfp, cqp, 1, HW_, qp);

    cudaStreamWaitEvent(0, ev1, 0);
    cudaStreamWaitEvent(0, ev2, 0);

    attn_mma_kernel<<<dim3(B_, HEADS_, 25), 256, ATT_SMEM>>>(qp, kp, vp, bbfp, resp);

    gemm_o<<<dim3(25, 2, B_), 256>>>(resp, wop, bo, x, out);

    cudaEventDestroy(evRoot);
    cudaEventDestroy(evW);
    cudaEventDestroy(ev1);
    cudaEventDestroy(ev2);
    cudaStreamDestroy(s1);
    cudaStreamDestroy(s2);
}

// round 8
// speedup vs baseline: 17.1777x; 1.0194x over previous
#include <cuda_runtime.h>
#include <cuda_bf16.h>
#include <cuda_fp16.h>
#include <math.h>
#include <stdint.h>

// Problem constants
#define B_   8
#define C_   256
#define H_   56
#define W_   56
#define HW_  3136        // 56*56
#define KHW_ 784         // 28*28
#define HEADS_ 8
#define NTOT_ 6422528    // B*C*HW
#define NPART_ 6272      // NTOT/4/256 blocks in fused cvt+stats
#define BIASN_ 19668992  // HEADS*HW*KHW
#define EPS_ 1e-5
#define SCALE_ 0.17677669529663687f   // 1/sqrt(32)
#define LOG2E_ 1.4426950408889634f

// Scratch (static device arrays — allocation-free)
__device__ __nv_bfloat16 g_q[B_ * 256 * HW_];    // [b][hd][i]  (log2e-scaled)
__device__ __nv_bfloat16 g_k[B_ * 256 * KHW_];   // [b][hd][j]
__device__ __half        g_v[B_ * 256 * KHW_];   // [b][hd][j]  fp16
__device__ __nv_bfloat16 g_res[B_ * HW_ * 256];  // [b][i][hd]
__device__ __nv_bfloat16 g_ck[B_ * C_ * KHW_];   // conv-K out bf16 [b][c][j]
__device__ __nv_bfloat16 g_cv[B_ * C_ * KHW_];
__device__ __nv_bfloat16 g_xbf[NTOT_];           // x in bf16 [b][c][hw]
__device__ __half        g_bbf[BIASN_];          // bias*log2e in fp16
__device__ __nv_bfloat16 g_wq[65536], g_wk[65536], g_wv[65536], g_wo[65536];
__device__ float g_part[2 * NPART_];
__device__ float g_wqsum[256];
__device__ float g_stats[2];                     // mu, rstd
__device__ float g_cq[256];                      // folded Q bias

// ---------------------------------------------------------------------------
// asm helpers
// ---------------------------------------------------------------------------
__device__ __forceinline__ uint32_t smem_u32(const void* p) {
    return (uint32_t)__cvta_generic_to_shared(p);
}
__device__ __forceinline__ void ldm_x4(uint32_t* r, uint32_t addr) {
    asm volatile("ldmatrix.sync.aligned.m8n8.x4.shared.b16 {%0,%1,%2,%3}, [%4];"
        : "=r"(r[0]), "=r"(r[1]), "=r"(r[2]), "=r"(r[3]) : "r"(addr));
}
__device__ __forceinline__ void ldm_x4_t(uint32_t* r, uint32_t addr) {
    asm volatile("ldmatrix.sync.aligned.m8n8.x4.trans.shared.b16 {%0,%1,%2,%3}, [%4];"
        : "=r"(r[0]), "=r"(r[1]), "=r"(r[2]), "=r"(r[3]) : "r"(addr));
}
__device__ __forceinline__ void mma_bf16(float* d, const uint32_t* a, const uint32_t* b) {
    asm volatile(
        "mma.sync.aligned.m16n8k16.row.col.f32.bf16.bf16.f32 "
        "{%0,%1,%2,%3}, {%4,%5,%6,%7}, {%8,%9}, {%0,%1,%2,%3};"
        : "+f"(d[0]), "+f"(d[1]), "+f"(d[2]), "+f"(d[3])
        : "r"(a[0]), "r"(a[1]), "r"(a[2]), "r"(a[3]), "r"(b[0]), "r"(b[1]));
}
__device__ __forceinline__ void mma_f16(float* d, const uint32_t* a, const uint32_t* b) {
    asm volatile(
        "mma.sync.aligned.m16n8k16.row.col.f32.f16.f16.f32 "
        "{%0,%1,%2,%3}, {%4,%5,%6,%7}, {%8,%9}, {%0,%1,%2,%3};"
        : "+f"(d[0]), "+f"(d[1]), "+f"(d[2]), "+f"(d[3])
        : "r"(a[0]), "r"(a[1]), "r"(a[2]), "r"(a[3]), "r"(b[0]), "r"(b[1]));
}
// p = 2^(cvtf16x2(s_lo,s_hi) + bias_f16x2)
__device__ __forceinline__ uint32_t bias_ex2(float lo, float hi, uint32_t bias2) {
    uint32_t t, u, r;
    asm("cvt.rn.f16x2.f32 %0, %1, %2;" : "=r"(t) : "f"(hi), "f"(lo));
    asm("add.f16x2 %0, %1, %2;" : "=r"(u) : "r"(t), "r"(bias2));
    asm("ex2.approx.f16x2 %0, %1;" : "=r"(r) : "r"(u));
    return r;
}
__device__ __forceinline__ void cp16(uint32_t dst, const void* src) {
    asm volatile("cp.async.cg.shared.global [%0], [%1], 16;" :: "r"(dst), "l"(src));
}
__device__ __forceinline__ void cp_commit() {
    asm volatile("cp.async.commit_group;" ::: "memory");
}
__device__ __forceinline__ void cp_wait_all() {
    asm volatile("cp.async.wait_group 0;" ::: "memory");
}
__device__ __forceinline__ void cp_wait_1() {
    asm volatile("cp.async.wait_group 1;" ::: "memory");
}

// ---------------------------------------------------------------------------
// Fused: x fp32 -> bf16 + LN partial sums (x read ONCE)
// ---------------------------------------------------------------------------
__global__ void cvt_x_stats(const float* __restrict__ x) {
    int tid = threadIdx.x;
    int i = blockIdx.x * 256 + tid;
    float4 v = ((const float4*)x)[i];
    __nv_bfloat162* o = (__nv_bfloat162*)(g_xbf + (size_t)i * 4);
    o[0] = __floats2bfloat162_rn(v.x, v.y);
    o[1] = __floats2bfloat162_rn(v.z, v.w);
    float s  = v.x + v.y + v.z + v.w;
    float ss = v.x * v.x + v.y * v.y + v.z * v.z + v.w * v.w;
    #pragma unroll
    for (int ofs = 16; ofs; ofs >>= 1) {
        s  += __shfl_xor_sync(0xffffffffu, s, ofs);
        ss += __shfl_xor_sync(0xffffffffu, ss, ofs);
    }
    __shared__ float sh[16];
    int w = tid >> 5, lane = tid & 31;
    if (lane == 0) { sh[w] = s; sh[8 + w] = ss; }
    __syncthreads();
    if (tid == 0) {
        float a = 0.f, b = 0.f;
        #pragma unroll
        for (int k = 0; k < 8; k++) { a += sh[k]; b += sh[8 + k]; }
        g_part[blockIdx.x] = a;
        g_part[NPART_ + blockIdx.x] = b;
    }
}

// ---------------------------------------------------------------------------
// Weight conversions (vectorized) + Wq rowsum (block r handles row r)
// ---------------------------------------------------------------------------
__global__ void cvt_w_kernel(const float* __restrict__ Wq, const float* __restrict__ Wk,
                             const float* __restrict__ Wv, const float* __restrict__ Wo) {
    int r = blockIdx.x, tid = threadIdx.x;
    int base = r * 256 + (tid & 63) * 4;
    int grp = tid >> 6;      // 0..3 selects matrix
    const float* src = (grp == 0) ? Wq : (grp == 1) ? Wk : (grp == 2) ? Wv : Wo;
    __nv_bfloat16* dst = (grp == 0) ? g_wq : (grp == 1) ? g_wk : (grp == 2) ? g_wv : g_wo;
    float4 v = *(const float4*)(src + base);
    *(__nv_bfloat162*)(dst + base)     = __floats2bfloat162_rn(v.x, v.y);
    *(__nv_bfloat162*)(dst + base + 2) = __floats2bfloat162_rn(v.z, v.w);
    float s = (grp == 0) ? (v.x + v.y) + (v.z + v.w) : 0.f;
    #pragma unroll
    for (int ofs = 16; ofs; ofs >>= 1) s += __shfl_xor_sync(0xffffffffu, s, ofs);
    __shared__ float sh[8];
    if ((tid & 31) == 0) sh[tid >> 5] = s;
    __syncthreads();
    if (tid == 0) g_wqsum[r] = sh[0] + sh[1];
}

// ---------------------------------------------------------------------------
// Bias fp32 -> fp16, scaled by log2e (log2-domain softmax, f16 add path)
// ---------------------------------------------------------------------------
__global__ void cvt_bias(const float* __restrict__ Bb) {
    size_t i = (size_t)blockIdx.x * 256 + threadIdx.x;   // group of 8
    float4 a = ((const float4*)Bb)[2 * i];
    float4 b = ((const float4*)Bb)[2 * i + 1];
    __half2* o = (__half2*)(g_bbf + i * 8);
    o[0] = __floats2half2_rn(a.x * LOG2E_, a.y * LOG2E_);
    o[1] = __floats2half2_rn(a.z * LOG2E_, a.w * LOG2E_);
    o[2] = __floats2half2_rn(b.x * LOG2E_, b.y * LOG2E_);
    o[3] = __floats2half2_rn(b.z * LOG2E_, b.w * LOG2E_);
}

// ---------------------------------------------------------------------------
// Finalize mu/rstd + folded Q bias
// ---------------------------------------------------------------------------
__global__ void stats_final(const float* __restrict__ bq) {
    int tid = threadIdx.x;
    const float4* p4  = (const float4*)g_part;
    const float4* ps4 = (const float4*)(g_part + NPART_);
    double s = 0.0, ss = 0.0;
    for (int i = tid; i < NPART_ / 4; i += 256) {
        float4 a = p4[i];
        float4 b = ps4[i];
        s  += (double)((a.x + a.y) + (a.z + a.w));
        ss += (double)((b.x + b.y) + (b.z + b.w));
    }
    __shared__ double shs[256], shss[256];
    shs[tid] = s; shss[tid] = ss;
    __syncthreads();
    for (int o = 128; o; o >>= 1) {
        if (tid < o) { shs[tid] += shs[tid + o]; shss[tid] += shss[tid + o]; }
        __syncthreads();
    }
    __shared__ float mu_s, rstd_s;
    if (tid == 0) {
        double N = (double)NTOT_;
        double mu = shs[0] / N;
        double var = shss[0] / N - mu * mu;
        float rstd = (float)(1.0 / sqrt(var + EPS_));
        g_stats[0] = (float)mu;
        g_stats[1] = rstd;
        mu_s = (float)mu; rstd_s = rstd;
    }
    __syncthreads();
    g_cq[tid] = bq[tid] - rstd_s * mu_s * g_wqsum[tid];
}

// ---------------------------------------------------------------------------
// Depthwise 3x3 stride-2 conv (K and V paths fused), bf16 output
// ---------------------------------------------------------------------------
__global__ void dwconv_kernel(const float* __restrict__ x,
                              const float* __restrict__ wk, const float* __restrict__ bkd,
                              const float* __restrict__ wv, const float* __restrict__ bvd) {
    int idx = blockIdx.x * blockDim.x + threadIdx.x;
    if (idx >= B_ * C_ * KHW_) return;
    int ox = idx % 28;
    int oy = (idx / 28) % 28;
    int c  = (idx / KHW_) % C_;
    int b  = idx / (KHW_ * C_);
    const float* xp = x + ((size_t)(b * C_ + c)) * HW_;
    float ak = 0.f, av = 0.f;
    #pragma unroll
    for (int ky = 0; ky < 3; ky++) {
        int iy = oy * 2 + ky - 1;
        if (iy < 0 || iy >= H_) continue;
        #pragma unroll
        for (int kx = 0; kx < 3; kx++) {
            int ix = ox * 2 + kx - 1;
            if (ix < 0 || ix >= W_) continue;
            float xv = xp[iy * W_ + ix];
            ak += xv * wk[c * 9 + ky * 3 + kx];
            av += xv * wv[c * 9 + ky * 3 + kx];
        }
    }
    g_ck[idx] = __float2bfloat16(ak + bkd[c]);
    g_cv[idx] = __float2bfloat16(av + bvd[c]);
}

// ---------------------------------------------------------------------------
// Shared mma-GEMM core (2-stage cp.async), used by Q, K+V, O kernels.
// Computes c[4][4][4] = W128 x X128 over K=256 given smem loaders.
// ---------------------------------------------------------------------------
#define WST 40
#define XST 136

// bf16 mma GEMM: out = a1*(W @ X) + a2*cvec.  Q projection (mode 1).
__global__ void __launch_bounds__(256, 2) gemm_wx(
    const __nv_bfloat16* __restrict__ W, const __nv_bfloat16* __restrict__ X,
    const float* __restrict__ cvec, int mode, int Mt,
    void* __restrict__ outp)
{
    __shared__ __align__(16) __nv_bfloat16 Ws[2][128 * WST];
    __shared__ __align__(16) __nv_bfloat16 Xs[2][32 * XST];
    const int P0 = blockIdx.x * 128;
    const int R0 = blockIdx.y * 128;
    const int b  = blockIdx.z;
    const __nv_bfloat16* Xb = X + (size_t)b * 256 * Mt;
    const int tid = threadIdx.x, lane = tid & 31, w = tid >> 5;
    const int wR = (w >> 2) * 64, wP = (w & 3) * 32;

    float c[4][4][4];
    #pragma unroll
    for (int i = 0; i < 4; i++)
        #pragma unroll
        for (int j = 0; j < 4; j++)
            #pragma unroll
            for (int r = 0; r < 4; r++) c[i][j][r] = 0.f;

    const uint32_t wsb = smem_u32(Ws), xsb = smem_u32(Xs);

    auto load_stage = [&](int k0, int buf) {
        uint32_t wd = wsb + buf * (128 * WST * 2);
        uint32_t xd = xsb + buf * (32 * XST * 2);
        #pragma unroll
        for (int t = 0; t < 2; t++) {
            int f = tid + t * 256;
            int r = f >> 2, cc = (f & 3) * 8;
            cp16(wd + (uint32_t)((r * WST + cc) * 2),
                 W + (size_t)(R0 + r) * 256 + k0 + cc);
        }
        #pragma unroll
        for (int t = 0; t < 2; t++) {
            int f = tid + t * 256;
            int kk = f >> 4, p = (f & 15) * 8;
            int gp = P0 + p; if (gp > Mt - 8) gp = Mt - 8;
            cp16(xd + (uint32_t)((kk * XST + p) * 2),
                 Xb + (size_t)(k0 + kk) * Mt + gp);
        }
    };

    load_stage(0, 0);
    cp_commit();

    for (int s = 0; s < 8; s++) {
        cp_wait_all();
        __syncthreads();
        if (s + 1 < 8) { load_stage((s + 1) * 32, (s + 1) & 1); cp_commit(); }
        const int buf = s & 1;
        const uint32_t wb = wsb + buf * (128 * WST * 2);
        const uint32_t xb = xsb + buf * (32 * XST * 2);

        #pragma unroll
        for (int kk = 0; kk < 2; kk++) {
            uint32_t af[4][4], bf[4][2];
            {
                int rr = ((lane >> 3) & 1) * 8 + (lane & 7);
                int ch = (lane >> 4) & 1;
                #pragma unroll
                for (int rf = 0; rf < 4; rf++)
                    ldm_x4(af[rf], wb + (uint32_t)(((wR + rf * 16 + rr) * WST + kk * 16 + ch * 8) * 2));
            }
            {
                int krow = (lane & 7) + ((lane >> 3) & 1) * 8;
                int pc = ((lane >> 4) & 1) * 8;
                #pragma unroll
                for (int pf = 0; pf < 2; pf++) {
                    uint32_t r4[4];
                    ldm_x4_t(r4, xb + (uint32_t)(((kk * 16 + krow) * XST + wP + pf * 16 + pc) * 2));
                    bf[2 * pf][0] = r4[0]; bf[2 * pf][1] = r4[1];
                    bf[2 * pf + 1][0] = r4[2]; bf[2 * pf + 1][1] = r4[3];
                }
            }
            #pragma unroll
            for (int rf = 0; rf < 4; rf++)
                #pragma unroll
                for (int pg = 0; pg < 4; pg++)
                    mma_bf16(c[rf][pg], af[rf], bf[pg]);
        }
        __syncthreads();
    }

    float a1 = 1.f, a2 = 1.f;
    if (mode == 1) { a1 = g_stats[1] * SCALE_ * LOG2E_; a2 = SCALE_ * LOG2E_; }
    #pragma unroll
    for (int rf = 0; rf < 4; rf++) {
        int R = R0 + wR + rf * 16 + (lane >> 2);
        float cv1 = a2 * cvec[R], cv2 = a2 * cvec[R + 8];
        #pragma unroll
        for (int pg = 0; pg < 4; pg++) {
            int P = P0 + wP + pg * 8 + (lane & 3) * 2;
            if (P < Mt) {
                if (mode == 2) {
                    __half* ob = (__half*)outp + (size_t)b * 256 * Mt;
                    *(__half2*)(ob + (size_t)R * Mt + P) =
                        __floats2half2_rn(a1 * c[rf][pg][0] + cv1, a1 * c[rf][pg][1] + cv1);
                    *(__half2*)(ob + (size_t)(R + 8) * Mt + P) =
                        __floats2half2_rn(a1 * c[rf][pg][2] + cv2, a1 * c[rf][pg][3] + cv2);
                } else {
                    __nv_bfloat16* ob = (__nv_bfloat16*)outp + (size_t)b * 256 * Mt;
                    *(__nv_bfloat162*)(ob + (size_t)R * Mt + P) =
                        __floats2bfloat162_rn(a1 * c[rf][pg][0] + cv1, a1 * c[rf][pg][1] + cv1);
                    *(__nv_bfloat162*)(ob + (size_t)(R + 8) * Mt + P) =
                        __floats2bfloat162_rn(a1 * c[rf][pg][2] + cv2, a1 * c[rf][pg][3] + cv2);
                }
            }
        }
    }
}

// Fused K+V projection: blockIdx.z = b*2 + isV. 224 blocks in one launch.
__global__ void __launch_bounds__(256, 2) gemm_kv(
    const float* __restrict__ bk, const float* __restrict__ bv)
{
    const int z = blockIdx.z;
    const int b = z >> 1, isV = z & 1;
    const __nv_bfloat16* W = isV ? g_wv : g_wk;
    const __nv_bfloat16* X = (isV ? g_cv : g_ck) + (size_t)b * 256 * KHW_;
    const float* cvec = isV ? bv : bk;

    __shared__ __align__(16) __nv_bfloat16 Ws[2][128 * WST];
    __shared__ __align__(16) __nv_bfloat16 Xs[2][32 * XST];
    const int P0 = blockIdx.x * 128;
    const int R0 = blockIdx.y * 128;
    const int tid = threadIdx.x, lane = tid & 31, w = tid >> 5;
    const int wR = (w >> 2) * 64, wP = (w & 3) * 32;

    float c[4][4][4];
    #pragma unroll
    for (int i = 0; i < 4; i++)
        #pragma unroll
        for (int j = 0; j < 4; j++)
            #pragma unroll
            for (int r = 0; r < 4; r++) c[i][j][r] = 0.f;

    const uint32_t wsb = smem_u32(Ws), xsb = smem_u32(Xs);

    auto load_stage = [&](int k0, int buf) {
        uint32_t wd = wsb + buf * (128 * WST * 2);
        uint32_t xd = xsb + buf * (32 * XST * 2);
        #pragma unroll
        for (int t = 0; t < 2; t++) {
            int f = tid + t * 256;
            int r = f >> 2, cc = (f & 3) * 8;
            cp16(wd + (uint32_t)((r * WST + cc) * 2),
                 W + (size_t)(R0 + r) * 256 + k0 + cc);
        }
        #pragma unroll
        for (int t = 0; t < 2; t++) {
            int f = tid + t * 256;
            int kk = f >> 4, p = (f & 15) * 8;
            int gp = P0 + p; if (gp > KHW_ - 8) gp = KHW_ - 8;
            cp16(xd + (uint32_t)((kk * XST + p) * 2),
                 X + (size_t)(k0 + kk) * KHW_ + gp);
        }
    };

    load_stage(0, 0);
    cp_commit();

    for (int s = 0; s < 8; s++) {
        cp_wait_all();
        __syncthreads();
        if (s + 1 < 8) { load_stage((s + 1) * 32, (s + 1) & 1); cp_commit(); }
        const int buf = s & 1;
        const uint32_t wb = wsb + buf * (128 * WST * 2);
        const uint32_t xb = xsb + buf * (32 * XST * 2);

        #pragma unroll
        for (int kk = 0; kk < 2; kk++) {
            uint32_t af[4][4], bf[4][2];
            {
                int rr = ((lane >> 3) & 1) * 8 + (lane & 7);
                int ch = (lane >> 4) & 1;
                #pragma unroll
                for (int rf = 0; rf < 4; rf++)
                    ldm_x4(af[rf], wb + (uint32_t)(((wR + rf * 16 + rr) * WST + kk * 16 + ch * 8) * 2));
            }
            {
                int krow = (lane & 7) + ((lane >> 3) & 1) * 8;
                int pc = ((lane >> 4) & 1) * 8;
                #pragma unroll
                for (int pf = 0; pf < 2; pf++) {
                    uint32_t r4[4];
                    ldm_x4_t(r4, xb + (uint32_t)(((kk * 16 + krow) * XST + wP + pf * 16 + pc) * 2));
                    bf[2 * pf][0] = r4[0]; bf[2 * pf][1] = r4[1];
                    bf[2 * pf + 1][0] = r4[2]; bf[2 * pf + 1][1] = r4[3];
                }
            }
            #pragma unroll
            for (int rf = 0; rf < 4; rf++)
                #pragma unroll
                for (int pg = 0; pg < 4; pg++)
                    mma_bf16(c[rf][pg], af[rf], bf[pg]);
        }
        __syncthreads();
    }

    #pragma unroll
    for (int rf = 0; rf < 4; rf++) {
        int R = R0 + wR + rf * 16 + (lane >> 2);
        float cv1 = cvec[R], cv2 = cvec[R + 8];
        #pragma unroll
        for (int pg = 0; pg < 4; pg++) {
            int P = P0 + wP + pg * 8 + (lane & 3) * 2;
            if (P < KHW_) {
                if (isV) {
                    __half* ob = g_v + (size_t)b * 256 * KHW_;
                    *(__half2*)(ob + (size_t)R * KHW_ + P) =
                        __floats2half2_rn(c[rf][pg][0] + cv1, c[rf][pg][1] + cv1);
                    *(__half2*)(ob + (size_t)(R + 8) * KHW_ + P) =
                        __floats2half2_rn(c[rf][pg][2] + cv2, c[rf][pg][3] + cv2);
                } else {
                    __nv_bfloat16* ob = g_k + (size_t)b * 256 * KHW_;
                    *(__nv_bfloat162*)(ob + (size_t)R * KHW_ + P) =
                        __floats2bfloat162_rn(c[rf][pg][0] + cv1, c[rf][pg][1] + cv1);
                    *(__nv_bfloat162*)(ob + (size_t)(R + 8) * KHW_ + P) =
                        __floats2bfloat162_rn(c[rf][pg][2] + cv2, c[rf][pg][3] + cv2);
                }
            }
        }
    }
}

// ---------------------------------------------------------------------------
// O projection mma GEMM (2-stage cp.async) + fused bias + flat residual add
// ---------------------------------------------------------------------------
__global__ void __launch_bounds__(256, 2) gemm_o(
    const __nv_bfloat16* __restrict__ A, const __nv_bfloat16* __restrict__ Wo,
    const float* __restrict__ bo, const float* __restrict__ x,
    float* __restrict__ out)
{
    __shared__ __align__(16) __nv_bfloat16 As[2][128 * WST];
    __shared__ __align__(16) __nv_bfloat16 Bs[2][128 * WST];
    const int I0 = blockIdx.x * 128;
    const int N0 = blockIdx.y * 128;
    const int b  = blockIdx.z;
    const int tid = threadIdx.x, lane = tid & 31, w = tid >> 5;
    const int wI = (w >> 2) * 64, wN = (w & 3) * 32;

    float c[4][4][4];
    #pragma unroll
    for (int i = 0; i < 4; i++)
        #pragma unroll
        for (int j = 0; j < 4; j++)
            #pragma unroll
            for (int r = 0; r < 4; r++) c[i][j][r] = 0.f;

    const uint32_t asb = smem_u32(As), bsb = smem_u32(Bs);

    auto load_stage = [&](int k0, int buf) {
        uint32_t ad = asb + buf * (128 * WST * 2);
        uint32_t bd = bsb + buf * (128 * WST * 2);
        #pragma unroll
        for (int t = 0; t < 2; t++) {
            int f = tid + t * 256;
            int i = f >> 2, cc = (f & 3) * 8;
            int gi = I0 + i; if (gi > HW_ - 1) gi = HW_ - 1;
            cp16(ad + (uint32_t)((i * WST + cc) * 2),
                 A + ((size_t)(b * HW_) + gi) * 256 + k0 + cc);
        }
        #pragma unroll
        for (int t = 0; t < 2; t++) {
            int f = tid + t * 256;
            int n = f >> 2, cc = (f & 3) * 8;
            cp16(bd + (uint32_t)((n * WST + cc) * 2),
                 Wo + (size_t)(N0 + n) * 256 + k0 + cc);
        }
    };

    load_stage(0, 0);
    cp_commit();

    for (int s = 0; s < 8; s++) {
        cp_wait_all();
        __syncthreads();
        if (s + 1 < 8) { load_stage((s + 1) * 32, (s + 1) & 1); cp_commit(); }
        const int buf = s & 1;
        const uint32_t ab = asb + buf * (128 * WST * 2);
        const uint32_t bb = bsb + buf * (128 * WST * 2);

        #pragma unroll
        for (int kk = 0; kk < 2; kk++) {
            int rr = ((lane >> 3) & 1) * 8 + (lane & 7);
            int ch = (lane >> 4) & 1;
            uint32_t af[4][4], bf[4][2];
            #pragma unroll
            for (int mf = 0; mf < 4; mf++)
                ldm_x4(af[mf], ab + (uint32_t)(((wI + mf * 16 + rr) * WST + kk * 16 + ch * 8) * 2));
            #pragma unroll
            for (int ng = 0; ng < 2; ng++) {
                uint32_t r4[4];
                ldm_x4(r4, bb + (uint32_t)(((wN + ng * 16 + rr) * WST + kk * 16 + ch * 8) * 2));
                bf[2 * ng][0] = r4[0]; bf[2 * ng][1] = r4[2];
                bf[2 * ng + 1][0] = r4[1]; bf[2 * ng + 1][1] = r4[3];
            }
            #pragma unroll
            for (int mf = 0; mf < 4; mf++)
                #pragma unroll
                for (int nf = 0; nf < 4; nf++)
                    mma_bf16(c[mf][nf], af[mf], bf[nf]);
        }
        __syncthreads();
    }

    #pragma unroll
    for (int mf = 0; mf < 4; mf++) {
        int i1 = I0 + wI + mf * 16 + (lane >> 2);
        int i2 = i1 + 8;
        #pragma unroll
        for (int nf = 0; nf < 4; nf++) {
            int n = N0 + wN + nf * 8 + (lane & 3) * 2;
            float b0v = bo[n], b1v = bo[n + 1];
            if (i1 < HW_) {
                size_t flat = (size_t)b * (256 * HW_) + (size_t)i1 * 256 + n;
                float2 xv = *(const float2*)(x + flat);
                *(float2*)(out + flat) =
                    make_float2(c[mf][nf][0] + b0v + xv.x, c[mf][nf][1] + b1v + xv.y);
            }
            if (i2 < HW_) {
                size_t flat = (size_t)b * (256 * HW_) + (size_t)i2 * 256 + n;
                float2 xv = *(const float2*)(x + flat);
                *(float2*)(out + flat) =
                    make_float2(c[mf][nf][2] + b0v + xv.x, c[mf][nf][3] + b1v + xv.y);
            }
        }
    }
}

// ---------------------------------------------------------------------------
// Flash attention, log2-domain fixed-max softmax, bias via ldmatrix + f16x2
// add + ex2, denominators via ones-column mma, 3-stage cp.async pipeline.
// smem: Qs 8704 | 3 stages x (K 4608 + V 4608 + bias(f16) 18432)
// ---------------------------------------------------------------------------
#define QST 136
#define KST 72
#define BST 72
#define KBUF  (32 * KST * 2)
#define VBUF  (32 * KST * 2)
#define BBUF  (128 * BST * 2)
#define STAGEB (KBUF + VBUF + BBUF)     // 27648
#define ATT_SMEM (8704 + 3 * STAGEB)    // 91648

__global__ void __launch_bounds__(256, 2) attn_mma_kernel(
    const __nv_bfloat16* __restrict__ qb, const __nv_bfloat16* __restrict__ kb,
    const __half* __restrict__ vb, const __half* __restrict__ bias,
    __nv_bfloat16* __restrict__ res)
{
    extern __shared__ __align__(16) char smraw[];
    __nv_bfloat16* Qs = (__nv_bfloat16*)smraw;

    const int b = blockIdx.x, h = blockIdx.y;
    const int i0 = blockIdx.z * 128;
    const int tid = threadIdx.x, lane = tid & 31, w = tid >> 5;

    const __nv_bfloat16* qsrc = qb + ((size_t)b * 256 + h * 32) * HW_;
    const __nv_bfloat16* ksrc = kb + ((size_t)b * 256 + h * 32) * KHW_;
    const __half*        vsrc = vb + ((size_t)b * 256 + h * 32) * KHW_;
    const __half*        bias_h = bias + (size_t)h * HW_ * KHW_;

    const uint32_t qbase = smem_u32(smraw);
    const uint32_t stage0 = qbase + 8704;

    // --- Q tile: [32 d][128 i] direct copy ---
    #pragma unroll
    for (int f = tid; f < 512; f += 256) {
        int d = f >> 4, ii = (f & 15) * 8;
        int gi = i0 + ii; if (gi > HW_ - 8) gi = HW_ - 8;
        *(uint4*)&Qs[d * QST + ii] = *(const uint4*)(qsrc + (size_t)d * HW_ + gi);
    }

    auto load_tile = [&](int j0, int buf) {
        uint32_t sb = stage0 + buf * STAGEB;
        {
            int d = tid >> 3, jj = (tid & 7) * 8;
            int gj = j0 + jj; if (gj > KHW_ - 8) gj = KHW_ - 8;
            cp16(sb + (uint32_t)((d * KST + jj) * 2), ksrc + (size_t)d * KHW_ + gj);
            cp16(sb + KBUF + (uint32_t)((d * KST + jj) * 2), vsrc + (size_t)d * KHW_ + gj);
        }
        #pragma unroll
        for (int t = 0; t < 4; t++) {
            int f = tid + t * 256;                 // f < 1024
            int r = f >> 3, c8 = (f & 7) * 8;
            int gr = i0 + r; if (gr > HW_ - 1) gr = HW_ - 1;
            int gc = j0 + c8; if (gc > KHW_ - 8) gc = KHW_ - 8;
            cp16(sb + KBUF + VBUF + (uint32_t)((r * BST + c8) * 2),
                 bias_h + (size_t)gr * KHW_ + gc);
        }
    };

    load_tile(0, 0);  cp_commit();
    load_tile(64, 1); cp_commit();
    __syncthreads();   // Q tile visible

    // --- Q A-fragments ---
    uint32_t qa[2][4];
    {
        int krow = (lane & 7) + ((lane >> 4) & 1) * 8;
        int mcol = w * 16 + ((lane >> 3) & 1) * 8;
        #pragma unroll
        for (int kk = 0; kk < 2; kk++)
            ldm_x4_t(qa[kk], qbase + (uint32_t)(((kk * 16 + krow) * QST + mcol) * 2));
    }

    float oacc[4][4];
    #pragma unroll
    for (int nf = 0; nf < 4; nf++)
        #pragma unroll
        for (int r = 0; r < 4; r++) oacc[nf][r] = 0.f;
    float c5[4] = {0.f, 0.f, 0.f, 0.f};            // denominator accumulator
    const uint32_t bone = (lane < 4) ? 0x3C003C00u : 0u;  // ones-column B frag
    uint32_t bones[2] = {bone, bone};

    const int rA = w * 16 + (lane >> 2);
    const int rB = rA + 8;
    // ldmatrix lane-address components (shared by V and bias loads)
    const int rr = ((lane >> 3) & 1) * 8 + (lane & 7);
    const int ch = (lane >> 4) & 1;

    #pragma unroll 1
    for (int jt = 0; jt < 13; jt++) {
        if (jt == 12) cp_wait_all(); else cp_wait_1();
        __syncthreads();
        if (jt + 2 < 13) { load_tile((jt + 2) * 64, (jt + 2) % 3); cp_commit(); }

        const uint32_t sb = stage0 + (jt % 3) * STAGEB;
        const uint32_t kbase = sb;
        const uint32_t vbase = sb + KBUF;
        const uint32_t bbase = sb + KBUF + VBUF;

        // --- S = Q @ K^T (log2-domain scores) ---
        float s[8][4];
        #pragma unroll
        for (int nf = 0; nf < 8; nf++)
            #pragma unroll
            for (int r = 0; r < 4; r++) s[nf][r] = 0.f;

        #pragma unroll
        for (int kk = 0; kk < 2; kk++) {
            uint32_t kbf[8][2];
            int krow = (lane & 7) + ((lane >> 3) & 1) * 8;
            int ncol = ((lane >> 4) & 1) * 8;
            #pragma unroll
            for (int jg = 0; jg < 4; jg++) {
                uint32_t r4[4];
                ldm_x4_t(r4, kbase + (uint32_t)(((kk * 16 + krow) * KST + jg * 16 + ncol) * 2));
                kbf[2 * jg][0] = r4[0]; kbf[2 * jg][1] = r4[1];
                kbf[2 * jg + 1][0] = r4[2]; kbf[2 * jg + 1][1] = r4[3];
            }
            #pragma unroll
            for (int nf = 0; nf < 8; nf++) mma_bf16(s[nf], qa[kk], kbf[nf]);
        }

        // --- V fragments (issued early to overlap softmax) ---
        uint32_t vbf[4][4][2];
        #pragma unroll
        for (int ng = 0; ng < 2; ng++)
            #pragma unroll
            for (int kf = 0; kf < 4; kf++) {
                uint32_t r4[4];
                ldm_x4(r4, vbase + (uint32_t)(((ng * 16 + rr) * KST + kf * 16 + ch * 8) * 2));
                vbf[2 * ng][kf][0] = r4[0]; vbf[2 * ng][kf][1] = r4[2];
                vbf[2 * ng + 1][kf][0] = r4[1]; vbf[2 * ng + 1][kf][1] = r4[3];
            }

        // --- softmax numerators: p = 2^(s + bias_l2) via ldmatrix bias + f16 ---
        // bias fragment layout (m8n8 b16) == accumulator layout, so ldm_x4 of
        // the warp's 16x16 bias region yields {rA cols0-7, rB cols0-7,
        // rA cols8-15, rB cols8-15} matching s[2cg], s[2cg+1].
        uint32_t pa[4][4];
        if (jt < 12) {
            #pragma unroll
            for (int cg = 0; cg < 4; cg++) {
                uint32_t bb4[4];
                ldm_x4(bb4, bbase + (uint32_t)(((w * 16 + rr) * BST + cg * 16 + ch * 8) * 2));
                pa[cg][0] = bias_ex2(s[2 * cg][0],     s[2 * cg][1],     bb4[0]);
                pa[cg][1] = bias_ex2(s[2 * cg][2],     s[2 * cg][3],     bb4[1]);
                pa[cg][2] = bias_ex2(s[2 * cg + 1][0], s[2 * cg + 1][1], bb4[2]);
                pa[cg][3] = bias_ex2(s[2 * cg + 1][2], s[2 * cg + 1][3], bb4[3]);
            }
        } else {
            // last tile: only cols 0..15 valid (784 = 12*64 + 16) = cg 0 exactly
            uint32_t bb4[4];
            ldm_x4(bb4, bbase + (uint32_t)(((w * 16 + rr) * BST + ch * 8) * 2));
            pa[0][0] = bias_ex2(s[0][0], s[0][1], bb4[0]);
            pa[0][1] = bias_ex2(s[0][2], s[0][3], bb4[1]);
            pa[0][2] = bias_ex2(s[1][0], s[1][1], bb4[2]);
            pa[0][3] = bias_ex2(s[1][2], s[1][3], bb4[3]);
            #pragma unroll
            for (int cg = 1; cg < 4; cg++)
                #pragma unroll
                for (int r = 0; r < 4; r++) pa[cg][r] = 0u;
        }

        // --- O += P @ V, denom += P @ ones ---
        #pragma unroll
        for (int kf = 0; kf < 4; kf++) {
            #pragma unroll
            for (int nf = 0; nf < 4; nf++)
                mma_f16(oacc[nf], pa[kf], vbf[nf][kf]);
            mma_f16(c5, pa[kf], bones);
        }
    }

    // --- epilogue: broadcast denominators, normalize, store ---
    int src = (lane >> 2) << 2;
    float l0 = __shfl_sync(0xffffffffu, c5[0], src);
    float l1 = __shfl_sync(0xffffffffu, c5[2], src);
    float inv0 = 1.f / l0, inv1 = 1.f / l1;
    int giA = i0 + rA;
    int giB = i0 + rB;
    #pragma unroll
    for (int nf = 0; nf < 4; nf++) {
        int col = h * 32 + nf * 8 + (lane & 3) * 2;
        if (giA < HW_)
            *(__nv_bfloat162*)(res + ((size_t)(b * HW_ + giA)) * 256 + col) =
                __floats2bfloat162_rn(oacc[nf][0] * inv0, oacc[nf][1] * inv0);
        if (giB < HW_)
            *(__nv_bfloat162*)(res + ((size_t)(b * HW_ + giB)) * 256 + col) =
                __floats2bfloat162_rn(oacc[nf][2] * inv1, oacc[nf][3] * inv1);
    }
}

// ---------------------------------------------------------------------------
extern "C" void kernel_launch(void* const* d_in, const int* in_sizes, int n_in,
                              void* d_out, int out_size) {
    const float* x     = (const float*)d_in[0];
    const float* Wk_dw = (const float*)d_in[1];
    const float* bk_dw = (const float*)d_in[2];
    const float* Wv_dw = (const float*)d_in[3];
    const float* bv_dw = (const float*)d_in[4];
    const float* Wq    = (const float*)d_in[5];
    const float* bq    = (const float*)d_in[6];
    const float* Wk    = (const float*)d_in[7];
    const float* bk    = (const float*)d_in[8];
    const float* Wv    = (const float*)d_in[9];
    const float* bv    = (const float*)d_in[10];
    const float* Wo    = (const float*)d_in[11];
    const float* bo    = (const float*)d_in[12];
    const float* Bb    = (const float*)d_in[13];
    float* out = (float*)d_out;

    __nv_bfloat16 *qp, *kp, *resp, *xbfp;
    __half *vp, *bbfp;
    __nv_bfloat16 *wqp, *wop;
    float *cqp;
    cudaGetSymbolAddress((void**)&qp,   g_q);
    cudaGetSymbolAddress((void**)&kp,   g_k);
    cudaGetSymbolAddress((void**)&vp,   g_v);
    cudaGetSymbolAddress((void**)&resp, g_res);
    cudaGetSymbolAddress((void**)&xbfp, g_xbf);
    cudaGetSymbolAddress((void**)&bbfp, g_bbf);
    cudaGetSymbolAddress((void**)&wqp,  g_wq);
    cudaGetSymbolAddress((void**)&wop,  g_wo);
    cudaGetSymbolAddress((void**)&cqp,  g_cq);

    cudaFuncSetAttribute(attn_mma_kernel,
                         cudaFuncAttributeMaxDynamicSharedMemorySize, ATT_SMEM);

    cudaStream_t s1, s2;
    cudaStreamCreateWithFlags(&s1, cudaStreamNonBlocking);
    cudaStreamCreateWithFlags(&s2, cudaStreamNonBlocking);
    cudaEvent_t evRoot, evW, ev1, ev2;
    cudaEventCreateWithFlags(&evRoot, cudaEventDisableTiming);
    cudaEventCreateWithFlags(&evW,    cudaEventDisableTiming);
    cudaEventCreateWithFlags(&ev1,    cudaEventDisableTiming);
    cudaEventCreateWithFlags(&ev2,    cudaEventDisableTiming);

    cudaEventRecord(evRoot, 0);
    cudaStreamWaitEvent(s1, evRoot, 0);
    cudaStreamWaitEvent(s2, evRoot, 0);

    // s1: weight conversion first (unblocks everything), then bias conversion
    cvt_w_kernel<<<256, 256, 0, s1>>>(Wq, Wk, Wv, Wo);
    cudaEventRecord(evW, s1);
    cvt_bias<<<BIASN_ / 8 / 256, 256, 0, s1>>>(Bb);
    cudaEventRecord(ev1, s1);

    // s2: dwconv, then fused K+V projections (one launch, 224 blocks)
    dwconv_kernel<<<(B_ * C_ * KHW_ + 255) / 256, 256, 0, s2>>>(x, Wk_dw, bk_dw, Wv_dw, bv_dw);
    cudaStreamWaitEvent(s2, evW, 0);
    gemm_kv<<<dim3(7, 2, 16), 256, 0, s2>>>(bk, bv);
    cudaEventRecord(ev2, s2);

    // main: x conversion + stats, then Q projection
    cvt_x_stats<<<NPART_, 256>>>(x);
    cudaStreamWaitEvent(0, evW, 0);
    stats_final<<<1, 256>>>(bq);
    gemm_wx<<<dim3(25, 2, B_), 256>>>(wqp, xbfp, cqp, 1, HW_, qp);

    cudaStreamWaitEvent(0, ev1, 0);
    cudaStreamWaitEvent(0, ev2, 0);

    attn_mma_kernel<<<dim3(B_, HEADS_, 25), 256, ATT_SMEM>>>(qp, kp, vp, bbfp, resp);

    gemm_o<<<dim3(25, 2, B_), 256>>>(resp, wop, bo, x, out);

    cudaEventDestroy(evRoot);
    cudaEventDestroy(evW);
    cudaEventDestroy(ev1);
    cudaEventDestroy(ev2);
    cudaStreamDestroy(s1);
    cudaStreamDestroy(s2);
}

// round 9
// speedup vs baseline: 18.3376x; 1.0675x over previous
#include <cuda_runtime.h>
#include <cuda_bf16.h>
#include <cuda_fp16.h>
#include <math.h>
#include <stdint.h>

// Problem constants
#define B_   8
#define C_   256
#define H_   56
#define W_   56
#define HW_  3136        // 56*56
#define KHW_ 784         // 28*28
#define HEADS_ 8
#define NTOT_ 6422528    // B*C*HW
#define NPART_ 6272      // NTOT/4/256 blocks in fused cvt+stats
#define BIASN_ 19668992  // HEADS*HW*KHW
#define EPS_ 1e-5
#define SCALE_ 0.17677669529663687f   // 1/sqrt(32)
#define LOG2E_ 1.4426950408889634f

// Scratch (static device arrays — allocation-free)
__device__ __nv_bfloat16 g_q[B_ * 256 * HW_];    // [b][hd][i]  (log2e-scaled)
__device__ __nv_bfloat16 g_k[B_ * 256 * KHW_];   // [b][hd][j]
__device__ __half        g_v[B_ * 256 * KHW_];   // [b][hd][j]  fp16
__device__ __nv_bfloat16 g_res[B_ * HW_ * 256];  // [b][i][hd]
__device__ __nv_bfloat16 g_ck[B_ * C_ * KHW_];   // conv-K out bf16 [b][c][j]
__device__ __nv_bfloat16 g_cv[B_ * C_ * KHW_];
__device__ __nv_bfloat16 g_xbf[NTOT_];           // x in bf16 [b][c][hw]
__device__ __half        g_bbf[BIASN_];          // bias*log2e in fp16
__device__ __nv_bfloat16 g_wq[65536], g_wk[65536], g_wv[65536], g_wo[65536];
__device__ float g_part[2 * NPART_];
__device__ float g_wqsum[256];
__device__ float g_stats[2];                     // mu, rstd
__device__ float g_cq[256];                      // folded Q bias

// ---------------------------------------------------------------------------
// asm helpers
// ---------------------------------------------------------------------------
__device__ __forceinline__ uint32_t smem_u32(const void* p) {
    return (uint32_t)__cvta_generic_to_shared(p);
}
__device__ __forceinline__ void ldm_x4(uint32_t* r, uint32_t addr) {
    asm volatile("ldmatrix.sync.aligned.m8n8.x4.shared.b16 {%0,%1,%2,%3}, [%4];"
        : "=r"(r[0]), "=r"(r[1]), "=r"(r[2]), "=r"(r[3]) : "r"(addr));
}
__device__ __forceinline__ void ldm_x4_t(uint32_t* r, uint32_t addr) {
    asm volatile("ldmatrix.sync.aligned.m8n8.x4.trans.shared.b16 {%0,%1,%2,%3}, [%4];"
        : "=r"(r[0]), "=r"(r[1]), "=r"(r[2]), "=r"(r[3]) : "r"(addr));
}
__device__ __forceinline__ void mma_bf16(float* d, const uint32_t* a, const uint32_t* b) {
    asm volatile(
        "mma.sync.aligned.m16n8k16.row.col.f32.bf16.bf16.f32 "
        "{%0,%1,%2,%3}, {%4,%5,%6,%7}, {%8,%9}, {%0,%1,%2,%3};"
        : "+f"(d[0]), "+f"(d[1]), "+f"(d[2]), "+f"(d[3])
        : "r"(a[0]), "r"(a[1]), "r"(a[2]), "r"(a[3]), "r"(b[0]), "r"(b[1]));
}
__device__ __forceinline__ void mma_f16(float* d, const uint32_t* a, const uint32_t* b) {
    asm volatile(
        "mma.sync.aligned.m16n8k16.row.col.f32.f16.f16.f32 "
        "{%0,%1,%2,%3}, {%4,%5,%6,%7}, {%8,%9}, {%0,%1,%2,%3};"
        : "+f"(d[0]), "+f"(d[1]), "+f"(d[2]), "+f"(d[3])
        : "r"(a[0]), "r"(a[1]), "r"(a[2]), "r"(a[3]), "r"(b[0]), "r"(b[1]));
}
// p = 2^(cvtf16x2(s_lo,s_hi) + bias_f16x2)
__device__ __forceinline__ uint32_t bias_ex2(float lo, float hi, uint32_t bias2) {
    uint32_t t, u, r;
    asm("cvt.rn.f16x2.f32 %0, %1, %2;" : "=r"(t) : "f"(hi), "f"(lo));
    asm("add.f16x2 %0, %1, %2;" : "=r"(u) : "r"(t), "r"(bias2));
    asm("ex2.approx.f16x2 %0, %1;" : "=r"(r) : "r"(u));
    return r;
}
__device__ __forceinline__ void cp16(uint32_t dst, const void* src) {
    asm volatile("cp.async.cg.shared.global [%0], [%1], 16;" :: "r"(dst), "l"(src));
}
__device__ __forceinline__ void cp_commit() {
    asm volatile("cp.async.commit_group;" ::: "memory");
}
__device__ __forceinline__ void cp_wait_all() {
    asm volatile("cp.async.wait_group 0;" ::: "memory");
}
__device__ __forceinline__ void cp_wait_1() {
    asm volatile("cp.async.wait_group 1;" ::: "memory");
}

// ---------------------------------------------------------------------------
// Fused: x fp32 -> bf16 + LN partial sums (x read ONCE)
// ---------------------------------------------------------------------------
__global__ void cvt_x_stats(const float* __restrict__ x) {
    int tid = threadIdx.x;
    int i = blockIdx.x * 256 + tid;
    float4 v = ((const float4*)x)[i];
    __nv_bfloat162* o = (__nv_bfloat162*)(g_xbf + (size_t)i * 4);
    o[0] = __floats2bfloat162_rn(v.x, v.y);
    o[1] = __floats2bfloat162_rn(v.z, v.w);
    float s  = v.x + v.y + v.z + v.w;
    float ss = v.x * v.x + v.y * v.y + v.z * v.z + v.w * v.w;
    #pragma unroll
    for (int ofs = 16; ofs; ofs >>= 1) {
        s  += __shfl_xor_sync(0xffffffffu, s, ofs);
        ss += __shfl_xor_sync(0xffffffffu, ss, ofs);
    }
    __shared__ float sh[16];
    int w = tid >> 5, lane = tid & 31;
    if (lane == 0) { sh[w] = s; sh[8 + w] = ss; }
    __syncthreads();
    if (tid == 0) {
        float a = 0.f, b = 0.f;
        #pragma unroll
        for (int k = 0; k < 8; k++) { a += sh[k]; b += sh[8 + k]; }
        g_part[blockIdx.x] = a;
        g_part[NPART_ + blockIdx.x] = b;
    }
}

// ---------------------------------------------------------------------------
// Weight conversions (vectorized) + Wq rowsum (block r handles row r)
// ---------------------------------------------------------------------------
__global__ void cvt_w_kernel(const float* __restrict__ Wq, const float* __restrict__ Wk,
                             const float* __restrict__ Wv, const float* __restrict__ Wo) {
    int r = blockIdx.x, tid = threadIdx.x;
    int base = r * 256 + (tid & 63) * 4;
    int grp = tid >> 6;      // 0..3 selects matrix
    const float* src = (grp == 0) ? Wq : (grp == 1) ? Wk : (grp == 2) ? Wv : Wo;
    __nv_bfloat16* dst = (grp == 0) ? g_wq : (grp == 1) ? g_wk : (grp == 2) ? g_wv : g_wo;
    float4 v = *(const float4*)(src + base);
    *(__nv_bfloat162*)(dst + base)     = __floats2bfloat162_rn(v.x, v.y);
    *(__nv_bfloat162*)(dst + base + 2) = __floats2bfloat162_rn(v.z, v.w);
    float s = (grp == 0) ? (v.x + v.y) + (v.z + v.w) : 0.f;
    #pragma unroll
    for (int ofs = 16; ofs; ofs >>= 1) s += __shfl_xor_sync(0xffffffffu, s, ofs);
    __shared__ float sh[8];
    if ((tid & 31) == 0) sh[tid >> 5] = s;
    __syncthreads();
    if (tid == 0) g_wqsum[r] = sh[0] + sh[1];
}

// ---------------------------------------------------------------------------
// Bias fp32 -> fp16, scaled by log2e (log2-domain softmax, f16 add path)
// ---------------------------------------------------------------------------
__global__ void cvt_bias(const float* __restrict__ Bb) {
    size_t i = (size_t)blockIdx.x * 256 + threadIdx.x;   // group of 8
    float4 a = ((const float4*)Bb)[2 * i];
    float4 b = ((const float4*)Bb)[2 * i + 1];
    __half2* o = (__half2*)(g_bbf + i * 8);
    o[0] = __floats2half2_rn(a.x * LOG2E_, a.y * LOG2E_);
    o[1] = __floats2half2_rn(a.z * LOG2E_, a.w * LOG2E_);
    o[2] = __floats2half2_rn(b.x * LOG2E_, b.y * LOG2E_);
    o[3] = __floats2half2_rn(b.z * LOG2E_, b.w * LOG2E_);
}

// ---------------------------------------------------------------------------
// Finalize mu/rstd + folded Q bias
// ---------------------------------------------------------------------------
__global__ void stats_final(const float* __restrict__ bq) {
    int tid = threadIdx.x;
    const float4* p4  = (const float4*)g_part;
    const float4* ps4 = (const float4*)(g_part + NPART_);
    double s = 0.0, ss = 0.0;
    for (int i = tid; i < NPART_ / 4; i += 256) {
        float4 a = p4[i];
        float4 b = ps4[i];
        s  += (double)((a.x + a.y) + (a.z + a.w));
        ss += (double)((b.x + b.y) + (b.z + b.w));
    }
    __shared__ double shs[256], shss[256];
    shs[tid] = s; shss[tid] = ss;
    __syncthreads();
    for (int o = 128; o; o >>= 1) {
        if (tid < o) { shs[tid] += shs[tid + o]; shss[tid] += shss[tid + o]; }
        __syncthreads();
    }
    __shared__ float mu_s, rstd_s;
    if (tid == 0) {
        double N = (double)NTOT_;
        double mu = shs[0] / N;
        double var = shss[0] / N - mu * mu;
        float rstd = (float)(1.0 / sqrt(var + EPS_));
        g_stats[0] = (float)mu;
        g_stats[1] = rstd;
        mu_s = (float)mu; rstd_s = rstd;
    }
    __syncthreads();
    g_cq[tid] = bq[tid] - rstd_s * mu_s * g_wqsum[tid];
}

// ---------------------------------------------------------------------------
// Depthwise 3x3 stride-2 conv (K and V paths fused), bf16 output
// ---------------------------------------------------------------------------
__global__ void dwconv_kernel(const float* __restrict__ x,
                              const float* __restrict__ wk, const float* __restrict__ bkd,
                              const float* __restrict__ wv, const float* __restrict__ bvd) {
    int idx = blockIdx.x * blockDim.x + threadIdx.x;
    if (idx >= B_ * C_ * KHW_) return;
    int ox = idx % 28;
    int oy = (idx / 28) % 28;
    int c  = (idx / KHW_) % C_;
    int b  = idx / (KHW_ * C_);
    const float* xp = x + ((size_t)(b * C_ + c)) * HW_;
    float ak = 0.f, av = 0.f;
    #pragma unroll
    for (int ky = 0; ky < 3; ky++) {
        int iy = oy * 2 + ky - 1;
        if (iy < 0 || iy >= H_) continue;
        #pragma unroll
        for (int kx = 0; kx < 3; kx++) {
            int ix = ox * 2 + kx - 1;
            if (ix < 0 || ix >= W_) continue;
            float xv = xp[iy * W_ + ix];
            ak += xv * wk[c * 9 + ky * 3 + kx];
            av += xv * wv[c * 9 + ky * 3 + kx];
        }
    }
    g_ck[idx] = __float2bfloat16(ak + bkd[c]);
    g_cv[idx] = __float2bfloat16(av + bvd[c]);
}

// ---------------------------------------------------------------------------
// bf16 mma GEMM (2-stage cp.async): Q projection path (mode 1), generic.
// ---------------------------------------------------------------------------
#define WST 40
#define XST 136
__global__ void __launch_bounds__(256, 2) gemm_wx(
    const __nv_bfloat16* __restrict__ W, const __nv_bfloat16* __restrict__ X,
    const float* __restrict__ cvec, int mode, int Mt,
    void* __restrict__ outp)
{
    __shared__ __align__(16) __nv_bfloat16 Ws[2][128 * WST];
    __shared__ __align__(16) __nv_bfloat16 Xs[2][32 * XST];
    const int P0 = blockIdx.x * 128;
    const int R0 = blockIdx.y * 128;
    const int b  = blockIdx.z;
    const __nv_bfloat16* Xb = X + (size_t)b * 256 * Mt;
    const int tid = threadIdx.x, lane = tid & 31, w = tid >> 5;
    const int wR = (w >> 2) * 64, wP = (w & 3) * 32;

    float c[4][4][4];
    #pragma unroll
    for (int i = 0; i < 4; i++)
        #pragma unroll
        for (int j = 0; j < 4; j++)
            #pragma unroll
            for (int r = 0; r < 4; r++) c[i][j][r] = 0.f;

    const uint32_t wsb = smem_u32(Ws), xsb = smem_u32(Xs);

    auto load_stage = [&](int k0, int buf) {
        uint32_t wd = wsb + buf * (128 * WST * 2);
        uint32_t xd = xsb + buf * (32 * XST * 2);
        #pragma unroll
        for (int t = 0; t < 2; t++) {
            int f = tid + t * 256;
            int r = f >> 2, cc = (f & 3) * 8;
            cp16(wd + (uint32_t)((r * WST + cc) * 2),
                 W + (size_t)(R0 + r) * 256 + k0 + cc);
        }
        #pragma unroll
        for (int t = 0; t < 2; t++) {
            int f = tid + t * 256;
            int kk = f >> 4, p = (f & 15) * 8;
            int gp = P0 + p; if (gp > Mt - 8) gp = Mt - 8;
            cp16(xd + (uint32_t)((kk * XST + p) * 2),
                 Xb + (size_t)(k0 + kk) * Mt + gp);
        }
    };

    load_stage(0, 0);
    cp_commit();

    for (int s = 0; s < 8; s++) {
        cp_wait_all();
        __syncthreads();
        if (s + 1 < 8) { load_stage((s + 1) * 32, (s + 1) & 1); cp_commit(); }
        const int buf = s & 1;
        const uint32_t wb = wsb + buf * (128 * WST * 2);
        const uint32_t xb = xsb + buf * (32 * XST * 2);

        #pragma unroll
        for (int kk = 0; kk < 2; kk++) {
            uint32_t af[4][4], bf[4][2];
            {
                int rr = ((lane >> 3) & 1) * 8 + (lane & 7);
                int ch = (lane >> 4) & 1;
                #pragma unroll
                for (int rf = 0; rf < 4; rf++)
                    ldm_x4(af[rf], wb + (uint32_t)(((wR + rf * 16 + rr) * WST + kk * 16 + ch * 8) * 2));
            }
            {
                int krow = (lane & 7) + ((lane >> 3) & 1) * 8;
                int pc = ((lane >> 4) & 1) * 8;
                #pragma unroll
                for (int pf = 0; pf < 2; pf++) {
                    uint32_t r4[4];
                    ldm_x4_t(r4, xb + (uint32_t)(((kk * 16 + krow) * XST + wP + pf * 16 + pc) * 2));
                    bf[2 * pf][0] = r4[0]; bf[2 * pf][1] = r4[1];
                    bf[2 * pf + 1][0] = r4[2]; bf[2 * pf + 1][1] = r4[3];
                }
            }
            #pragma unroll
            for (int rf = 0; rf < 4; rf++)
                #pragma unroll
                for (int pg = 0; pg < 4; pg++)
                    mma_bf16(c[rf][pg], af[rf], bf[pg]);
        }
        __syncthreads();
    }

    float a1 = 1.f, a2 = 1.f;
    if (mode == 1) { a1 = g_stats[1] * SCALE_ * LOG2E_; a2 = SCALE_ * LOG2E_; }
    #pragma unroll
    for (int rf = 0; rf < 4; rf++) {
        int R = R0 + wR + rf * 16 + (lane >> 2);
        float cv1 = a2 * cvec[R], cv2 = a2 * cvec[R + 8];
        #pragma unroll
        for (int pg = 0; pg < 4; pg++) {
            int P = P0 + wP + pg * 8 + (lane & 3) * 2;
            if (P < Mt) {
                if (mode == 2) {
                    __half* ob = (__half*)outp + (size_t)b * 256 * Mt;
                    *(__half2*)(ob + (size_t)R * Mt + P) =
                        __floats2half2_rn(a1 * c[rf][pg][0] + cv1, a1 * c[rf][pg][1] + cv1);
                    *(__half2*)(ob + (size_t)(R + 8) * Mt + P) =
                        __floats2half2_rn(a1 * c[rf][pg][2] + cv2, a1 * c[rf][pg][3] + cv2);
                } else {
                    __nv_bfloat16* ob = (__nv_bfloat16*)outp + (size_t)b * 256 * Mt;
                    *(__nv_bfloat162*)(ob + (size_t)R * Mt + P) =
                        __floats2bfloat162_rn(a1 * c[rf][pg][0] + cv1, a1 * c[rf][pg][1] + cv1);
                    *(__nv_bfloat162*)(ob + (size_t)(R + 8) * Mt + P) =
                        __floats2bfloat162_rn(a1 * c[rf][pg][2] + cv2, a1 * c[rf][pg][3] + cv2);
                }
            }
        }
    }
}

// Fused K+V projection: blockIdx.z = b*2 + isV. 224 blocks in one launch.
__global__ void __launch_bounds__(256, 2) gemm_kv(
    const float* __restrict__ bk, const float* __restrict__ bv)
{
    const int z = blockIdx.z;
    const int b = z >> 1, isV = z & 1;
    const __nv_bfloat16* W = isV ? g_wv : g_wk;
    const __nv_bfloat16* X = (isV ? g_cv : g_ck) + (size_t)b * 256 * KHW_;
    const float* cvec = isV ? bv : bk;

    __shared__ __align__(16) __nv_bfloat16 Ws[2][128 * WST];
    __shared__ __align__(16) __nv_bfloat16 Xs[2][32 * XST];
    const int P0 = blockIdx.x * 128;
    const int R0 = blockIdx.y * 128;
    const int tid = threadIdx.x, lane = tid & 31, w = tid >> 5;
    const int wR = (w >> 2) * 64, wP = (w & 3) * 32;

    float c[4][4][4];
    #pragma unroll
    for (int i = 0; i < 4; i++)
        #pragma unroll
        for (int j = 0; j < 4; j++)
            #pragma unroll
            for (int r = 0; r < 4; r++) c[i][j][r] = 0.f;

    const uint32_t wsb = smem_u32(Ws), xsb = smem_u32(Xs);

    auto load_stage = [&](int k0, int buf) {
        uint32_t wd = wsb + buf * (128 * WST * 2);
        uint32_t xd = xsb + buf * (32 * XST * 2);
        #pragma unroll
        for (int t = 0; t < 2; t++) {
            int f = tid + t * 256;
            int r = f >> 2, cc = (f & 3) * 8;
            cp16(wd + (uint32_t)((r * WST + cc) * 2),
                 W + (size_t)(R0 + r) * 256 + k0 + cc);
        }
        #pragma unroll
        for (int t = 0; t < 2; t++) {
            int f = tid + t * 256;
            int kk = f >> 4, p = (f & 15) * 8;
            int gp = P0 + p; if (gp > KHW_ - 8) gp = KHW_ - 8;
            cp16(xd + (uint32_t)((kk * XST + p) * 2),
                 X + (size_t)(k0 + kk) * KHW_ + gp);
        }
    };

    load_stage(0, 0);
    cp_commit();

    for (int s = 0; s < 8; s++) {
        cp_wait_all();
        __syncthreads();
        if (s + 1 < 8) { load_stage((s + 1) * 32, (s + 1) & 1); cp_commit(); }
        const int buf = s & 1;
        const uint32_t wb = wsb + buf * (128 * WST * 2);
        const uint32_t xb = xsb + buf * (32 * XST * 2);

        #pragma unroll
        for (int kk = 0; kk < 2; kk++) {
            uint32_t af[4][4], bf[4][2];
            {
                int rr = ((lane >> 3) & 1) * 8 + (lane & 7);
                int ch = (lane >> 4) & 1;
                #pragma unroll
                for (int rf = 0; rf < 4; rf++)
                    ldm_x4(af[rf], wb + (uint32_t)(((wR + rf * 16 + rr) * WST + kk * 16 + ch * 8) * 2));
            }
            {
                int krow = (lane & 7) + ((lane >> 3) & 1) * 8;
                int pc = ((lane >> 4) & 1) * 8;
                #pragma unroll
                for (int pf = 0; pf < 2; pf++) {
                    uint32_t r4[4];
                    ldm_x4_t(r4, xb + (uint32_t)(((kk * 16 + krow) * XST + wP + pf * 16 + pc) * 2));
                    bf[2 * pf][0] = r4[0]; bf[2 * pf][1] = r4[1];
                    bf[2 * pf + 1][0] = r4[2]; bf[2 * pf + 1][1] = r4[3];
                }
            }
            #pragma unroll
            for (int rf = 0; rf < 4; rf++)
                #pragma unroll
                for (int pg = 0; pg < 4; pg++)
                    mma_bf16(c[rf][pg], af[rf], bf[pg]);
        }
        __syncthreads();
    }

    #pragma unroll
    for (int rf = 0; rf < 4; rf++) {
        int R = R0 + wR + rf * 16 + (lane >> 2);
        float cv1 = cvec[R], cv2 = cvec[R + 8];
        #pragma unroll
        for (int pg = 0; pg < 4; pg++) {
            int P = P0 + wP + pg * 8 + (lane & 3) * 2;
            if (P < KHW_) {
                if (isV) {
                    __half* ob = g_v + (size_t)b * 256 * KHW_;
                    *(__half2*)(ob + (size_t)R * KHW_ + P) =
                        __floats2half2_rn(c[rf][pg][0] + cv1, c[rf][pg][1] + cv1);
                    *(__half2*)(ob + (size_t)(R + 8) * KHW_ + P) =
                        __floats2half2_rn(c[rf][pg][2] + cv2, c[rf][pg][3] + cv2);
                } else {
                    __nv_bfloat16* ob = g_k + (size_t)b * 256 * KHW_;
                    *(__nv_bfloat162*)(ob + (size_t)R * KHW_ + P) =
                        __floats2bfloat162_rn(c[rf][pg][0] + cv1, c[rf][pg][1] + cv1);
                    *(__nv_bfloat162*)(ob + (size_t)(R + 8) * KHW_ + P) =
                        __floats2bfloat162_rn(c[rf][pg][2] + cv2, c[rf][pg][3] + cv2);
                }
            }
        }
    }
}

// ---------------------------------------------------------------------------
// O projection mma GEMM (2-stage cp.async) + fused bias + flat residual add
// ---------------------------------------------------------------------------
__global__ void __launch_bounds__(256, 2) gemm_o(
    const __nv_bfloat16* __restrict__ A, const __nv_bfloat16* __restrict__ Wo,
    const float* __restrict__ bo, const float* __restrict__ x,
    float* __restrict__ out)
{
    __shared__ __align__(16) __nv_bfloat16 As[2][128 * WST];
    __shared__ __align__(16) __nv_bfloat16 Bs[2][128 * WST];
    const int I0 = blockIdx.x * 128;
    const int N0 = blockIdx.y * 128;
    const int b  = blockIdx.z;
    const int tid = threadIdx.x, lane = tid & 31, w = tid >> 5;
    const int wI = (w >> 2) * 64, wN = (w & 3) * 32;

    float c[4][4][4];
    #pragma unroll
    for (int i = 0; i < 4; i++)
        #pragma unroll
        for (int j = 0; j < 4; j++)
            #pragma unroll
            for (int r = 0; r < 4; r++) c[i][j][r] = 0.f;

    const uint32_t asb = smem_u32(As), bsb = smem_u32(Bs);

    auto load_stage = [&](int k0, int buf) {
        uint32_t ad = asb + buf * (128 * WST * 2);
        uint32_t bd = bsb + buf * (128 * WST * 2);
        #pragma unroll
        for (int t = 0; t < 2; t++) {
            int f = tid + t * 256;
            int i = f >> 2, cc = (f & 3) * 8;
            int gi = I0 + i; if (gi > HW_ - 1) gi = HW_ - 1;
            cp16(ad + (uint32_t)((i * WST + cc) * 2),
                 A + ((size_t)(b * HW_) + gi) * 256 + k0 + cc);
        }
        #pragma unroll
        for (int t = 0; t < 2; t++) {
            int f = tid + t * 256;
            int n = f >> 2, cc = (f & 3) * 8;
            cp16(bd + (uint32_t)((n * WST + cc) * 2),
                 Wo + (size_t)(N0 + n) * 256 + k0 + cc);
        }
    };

    load_stage(0, 0);
    cp_commit();

    for (int s = 0; s < 8; s++) {
        cp_wait_all();
        __syncthreads();
        if (s + 1 < 8) { load_stage((s + 1) * 32, (s + 1) & 1); cp_commit(); }
        const int buf = s & 1;
        const uint32_t ab = asb + buf * (128 * WST * 2);
        const uint32_t bb = bsb + buf * (128 * WST * 2);

        #pragma unroll
        for (int kk = 0; kk < 2; kk++) {
            int rr = ((lane >> 3) & 1) * 8 + (lane & 7);
            int ch = (lane >> 4) & 1;
            uint32_t af[4][4], bf[4][2];
            #pragma unroll
            for (int mf = 0; mf < 4; mf++)
                ldm_x4(af[mf], ab + (uint32_t)(((wI + mf * 16 + rr) * WST + kk * 16 + ch * 8) * 2));
            #pragma unroll
            for (int ng = 0; ng < 2; ng++) {
                uint32_t r4[4];
                ldm_x4(r4, bb + (uint32_t)(((wN + ng * 16 + rr) * WST + kk * 16 + ch * 8) * 2));
                bf[2 * ng][0] = r4[0]; bf[2 * ng][1] = r4[2];
                bf[2 * ng + 1][0] = r4[1]; bf[2 * ng + 1][1] = r4[3];
            }
            #pragma unroll
            for (int mf = 0; mf < 4; mf++)
                #pragma unroll
                for (int nf = 0; nf < 4; nf++)
                    mma_bf16(c[mf][nf], af[mf], bf[nf]);
        }
        __syncthreads();
    }

    #pragma unroll
    for (int mf = 0; mf < 4; mf++) {
        int i1 = I0 + wI + mf * 16 + (lane >> 2);
        int i2 = i1 + 8;
        #pragma unroll
        for (int nf = 0; nf < 4; nf++) {
            int n = N0 + wN + nf * 8 + (lane & 3) * 2;
            float b0v = bo[n], b1v = bo[n + 1];
            if (i1 < HW_) {
                size_t flat = (size_t)b * (256 * HW_) + (size_t)i1 * 256 + n;
                float2 xv = *(const float2*)(x + flat);
                *(float2*)(out + flat) =
                    make_float2(c[mf][nf][0] + b0v + xv.x, c[mf][nf][1] + b1v + xv.y);
            }
            if (i2 < HW_) {
                size_t flat = (size_t)b * (256 * HW_) + (size_t)i2 * 256 + n;
                float2 xv = *(const float2*)(x + flat);
                *(float2*)(out + flat) =
                    make_float2(c[mf][nf][2] + b0v + xv.x, c[mf][nf][3] + b1v + xv.y);
            }
        }
    }
}

// ---------------------------------------------------------------------------
// Flash attention, log2-domain fixed-max softmax, bias via ldmatrix + f16x2
// add + ex2, denominators via ones-column mma, 3-stage cp.async pipeline.
// V fragments loaded JUST-IN-TIME per k-fragment to keep regs < 128 (no spill
// at 2 blocks/SM).
// ---------------------------------------------------------------------------
#define QST 136
#define KST 72
#define BST 72
#define KBUF  (32 * KST * 2)
#define VBUF  (32 * KST * 2)
#define BBUF  (128 * BST * 2)
#define STAGEB (KBUF + VBUF + BBUF)     // 27648
#define ATT_SMEM (8704 + 3 * STAGEB)    // 91648

__global__ void __launch_bounds__(256, 2) attn_mma_kernel(
    const __nv_bfloat16* __restrict__ qb, const __nv_bfloat16* __restrict__ kb,
    const __half* __restrict__ vb, const __half* __restrict__ bias,
    __nv_bfloat16* __restrict__ res)
{
    extern __shared__ __align__(16) char smraw[];
    __nv_bfloat16* Qs = (__nv_bfloat16*)smraw;

    const int b = blockIdx.x, h = blockIdx.y;
    const int i0 = blockIdx.z * 128;
    const int tid = threadIdx.x, lane = tid & 31, w = tid >> 5;

    const __nv_bfloat16* qsrc = qb + ((size_t)b * 256 + h * 32) * HW_;
    const __nv_bfloat16* ksrc = kb + ((size_t)b * 256 + h * 32) * KHW_;
    const __half*        vsrc = vb + ((size_t)b * 256 + h * 32) * KHW_;
    const __half*        bias_h = bias + (size_t)h * HW_ * KHW_;

    const uint32_t qbase = smem_u32(smraw);
    const uint32_t stage0 = qbase + 8704;

    // --- Q tile: [32 d][128 i] direct copy ---
    #pragma unroll
    for (int f = tid; f < 512; f += 256) {
        int d = f >> 4, ii = (f & 15) * 8;
        int gi = i0 + ii; if (gi > HW_ - 8) gi = HW_ - 8;
        *(uint4*)&Qs[d * QST + ii] = *(const uint4*)(qsrc + (size_t)d * HW_ + gi);
    }

    auto load_tile = [&](int j0, int buf) {
        uint32_t sb = stage0 + buf * STAGEB;
        {
            int d = tid >> 3, jj = (tid & 7) * 8;
            int gj = j0 + jj; if (gj > KHW_ - 8) gj = KHW_ - 8;
            cp16(sb + (uint32_t)((d * KST + jj) * 2), ksrc + (size_t)d * KHW_ + gj);
            cp16(sb + KBUF + (uint32_t)((d * KST + jj) * 2), vsrc + (size_t)d * KHW_ + gj);
        }
        #pragma unroll
        for (int t = 0; t < 4; t++) {
            int f = tid + t * 256;                 // f < 1024
            int r = f >> 3, c8 = (f & 7) * 8;
            int gr = i0 + r; if (gr > HW_ - 1) gr = HW_ - 1;
            int gc = j0 + c8; if (gc > KHW_ - 8) gc = KHW_ - 8;
            cp16(sb + KBUF + VBUF + (uint32_t)((r * BST + c8) * 2),
                 bias_h + (size_t)gr * KHW_ + gc);
        }
    };

    load_tile(0, 0);  cp_commit();
    load_tile(64, 1); cp_commit();
    __syncthreads();   // Q tile visible

    // --- Q A-fragments ---
    uint32_t qa[2][4];
    {
        int krow = (lane & 7) + ((lane >> 4) & 1) * 8;
        int mcol = w * 16 + ((lane >> 3) & 1) * 8;
        #pragma unroll
        for (int kk = 0; kk < 2; kk++)
            ldm_x4_t(qa[kk], qbase + (uint32_t)(((kk * 16 + krow) * QST + mcol) * 2));
    }

    float oacc[4][4];
    #pragma unroll
    for (int nf = 0; nf < 4; nf++)
        #pragma unroll
        for (int r = 0; r < 4; r++) oacc[nf][r] = 0.f;
    float c5[4] = {0.f, 0.f, 0.f, 0.f};            // denominator accumulator
    const uint32_t bone = (lane < 4) ? 0x3C003C00u : 0u;  // ones-column B frag
    uint32_t bones[2] = {bone, bone};

    const int rA = w * 16 + (lane >> 2);
    const int rB = rA + 8;
    // ldmatrix lane-address components (shared by V and bias loads)
    const int rr = ((lane >> 3) & 1) * 8 + (lane & 7);
    const int ch = (lane >> 4) & 1;

    #pragma unroll 1
    for (int jt = 0; jt < 13; jt++) {
        if (jt == 12) cp_wait_all(); else cp_wait_1();
        __syncthreads();
        if (jt + 2 < 13) { load_tile((jt + 2) * 64, (jt + 2) % 3); cp_commit(); }

        const uint32_t sb = stage0 + (jt % 3) * STAGEB;
        const uint32_t kbase = sb;
        const uint32_t vbase = sb + KBUF;
        const uint32_t bbase = sb + KBUF + VBUF;

        // --- S = Q @ K^T (log2-domain scores) ---
        float s[8][4];
        #pragma unroll
        for (int nf = 0; nf < 8; nf++)
            #pragma unroll
            for (int r = 0; r < 4; r++) s[nf][r] = 0.f;

        #pragma unroll
        for (int kk = 0; kk < 2; kk++) {
            uint32_t kbf[8][2];
            int krow = (lane & 7) + ((lane >> 3) & 1) * 8;
            int ncol = ((lane >> 4) & 1) * 8;
            #pragma unroll
            for (int jg = 0; jg < 4; jg++) {
                uint32_t r4[4];
                ldm_x4_t(r4, kbase + (uint32_t)(((kk * 16 + krow) * KST + jg * 16 + ncol) * 2));
                kbf[2 * jg][0] = r4[0]; kbf[2 * jg][1] = r4[1];
                kbf[2 * jg + 1][0] = r4[2]; kbf[2 * jg + 1][1] = r4[3];
            }
            #pragma unroll
            for (int nf = 0; nf < 8; nf++) mma_bf16(s[nf], qa[kk], kbf[nf]);
        }

        // --- softmax numerators: p = 2^(s + bias_l2) via ldmatrix bias + f16 ---
        uint32_t pa[4][4];
        if (jt < 12) {
            #pragma unroll
            for (int cg = 0; cg < 4; cg++) {
                uint32_t bb4[4];
                ldm_x4(bb4, bbase + (uint32_t)(((w * 16 + rr) * BST + cg * 16 + ch * 8) * 2));
                pa[cg][0] = bias_ex2(s[2 * cg][0],     s[2 * cg][1],     bb4[0]);
                pa[cg][1] = bias_ex2(s[2 * cg][2],     s[2 * cg][3],     bb4[1]);
                pa[cg][2] = bias_ex2(s[2 * cg + 1][0], s[2 * cg + 1][1], bb4[2]);
                pa[cg][3] = bias_ex2(s[2 * cg + 1][2], s[2 * cg + 1][3], bb4[3]);
            }
        } else {
            // last tile: only cols 0..15 valid (784 = 12*64 + 16) = cg 0 exactly
            uint32_t bb4[4];
            ldm_x4(bb4, bbase + (uint32_t)(((w * 16 + rr) * BST + ch * 8) * 2));
            pa[0][0] = bias_ex2(s[0][0], s[0][1], bb4[0]);
            pa[0][1] = bias_ex2(s[0][2], s[0][3], bb4[1]);
            pa[0][2] = bias_ex2(s[1][0], s[1][1], bb4[2]);
            pa[0][3] = bias_ex2(s[1][2], s[1][3], bb4[3]);
            #pragma unroll
            for (int cg = 1; cg < 4; cg++)
                #pragma unroll
                for (int r = 0; r < 4; r++) pa[cg][r] = 0u;
        }

        // --- O += P @ V, denom += P @ ones.  V fragments loaded per-kf
        // (8 live regs instead of 32 -> no spills at 2 blocks/SM). ---
        #pragma unroll
        for (int kf = 0; kf < 4; kf++) {
            uint32_t vk[4][2];
            #pragma unroll
            for (int ng = 0; ng < 2; ng++) {
                uint32_t r4[4];
                ldm_x4(r4, vbase + (uint32_t)(((ng * 16 + rr) * KST + kf * 16 + ch * 8) * 2));
                vk[2 * ng][0] = r4[0]; vk[2 * ng][1] = r4[2];
                vk[2 * ng + 1][0] = r4[1]; vk[2 * ng + 1][1] = r4[3];
            }
            #pragma unroll
            for (int nf = 0; nf < 4; nf++)
                mma_f16(oacc[nf], pa[kf], vk[nf]);
            mma_f16(c5, pa[kf], bones);
        }
    }

    // --- epilogue: broadcast denominators, normalize, store ---
    int src = (lane >> 2) << 2;
    float l0 = __shfl_sync(0xffffffffu, c5[0], src);
    float l1 = __shfl_sync(0xffffffffu, c5[2], src);
    float inv0 = 1.f / l0, inv1 = 1.f / l1;
    int giA = i0 + rA;
    int giB = i0 + rB;
    #pragma unroll
    for (int nf = 0; nf < 4; nf++) {
        int col = h * 32 + nf * 8 + (lane & 3) * 2;
        if (giA < HW_)
            *(__nv_bfloat162*)(res + ((size_t)(b * HW_ + giA)) * 256 + col) =
                __floats2bfloat162_rn(oacc[nf][0] * inv0, oacc[nf][1] * inv0);
        if (giB < HW_)
            *(__nv_bfloat162*)(res + ((size_t)(b * HW_ + giB)) * 256 + col) =
                __floats2bfloat162_rn(oacc[nf][2] * inv1, oacc[nf][3] * inv1);
    }
}

// ---------------------------------------------------------------------------
extern "C" void kernel_launch(void* const* d_in, const int* in_sizes, int n_in,
                              void* d_out, int out_size) {
    const float* x     = (const float*)d_in[0];
    const float* Wk_dw = (const float*)d_in[1];
    const float* bk_dw = (const float*)d_in[2];
    const float* Wv_dw = (const float*)d_in[3];
    const float* bv_dw = (const float*)d_in[4];
    const float* Wq    = (const float*)d_in[5];
    const float* bq    = (const float*)d_in[6];
    const float* Wk    = (const float*)d_in[7];
    const float* bk    = (const float*)d_in[8];
    const float* Wv    = (const float*)d_in[9];
    const float* bv    = (const float*)d_in[10];
    const float* Wo    = (const float*)d_in[11];
    const float* bo    = (const float*)d_in[12];
    const float* Bb    = (const float*)d_in[13];
    float* out = (float*)d_out;

    __nv_bfloat16 *qp, *kp, *resp, *xbfp;
    __half *vp, *bbfp;
    __nv_bfloat16 *wqp, *wop;
    float *cqp;
    cudaGetSymbolAddress((void**)&qp,   g_q);
    cudaGetSymbolAddress((void**)&kp,   g_k);
    cudaGetSymbolAddress((void**)&vp,   g_v);
    cudaGetSymbolAddress((void**)&resp, g_res);
    cudaGetSymbolAddress((void**)&xbfp, g_xbf);
    cudaGetSymbolAddress((void**)&bbfp, g_bbf);
    cudaGetSymbolAddress((void**)&wqp,  g_wq);
    cudaGetSymbolAddress((void**)&wop,  g_wo);
    cudaGetSymbolAddress((void**)&cqp,  g_cq);

    cudaFuncSetAttribute(attn_mma_kernel,
                         cudaFuncAttributeMaxDynamicSharedMemorySize, ATT_SMEM);

    cudaStream_t s1, s2;
    cudaStreamCreateWithFlags(&s1, cudaStreamNonBlocking);
    cudaStreamCreateWithFlags(&s2, cudaStreamNonBlocking);
    cudaEvent_t evRoot, evW, ev1, ev2;
    cudaEventCreateWithFlags(&evRoot, cudaEventDisableTiming);
    cudaEventCreateWithFlags(&evW,    cudaEventDisableTiming);
    cudaEventCreateWithFlags(&ev1,    cudaEventDisableTiming);
    cudaEventCreateWithFlags(&ev2,    cudaEventDisableTiming);

    cudaEventRecord(evRoot, 0);
    cudaStreamWaitEvent(s1, evRoot, 0);
    cudaStreamWaitEvent(s2, evRoot, 0);

    // s1: weight conversion first (unblocks everything), then bias conversion
    cvt_w_kernel<<<256, 256, 0, s1>>>(Wq, Wk, Wv, Wo);
    cudaEventRecord(evW, s1);
    cvt_bias<<<BIASN_ / 8 / 256, 256, 0, s1>>>(Bb);
    cudaEventRecord(ev1, s1);

    // s2: dwconv, then fused K+V projections (one launch, 224 blocks)
    dwconv_kernel<<<(B_ * C_ * KHW_ + 255) / 256, 256, 0, s2>>>(x, Wk_dw, bk_dw, Wv_dw, bv_dw);
    cudaStreamWaitEvent(s2, evW, 0);
    gemm_kv<<<dim3(7, 2, 16), 256, 0, s2>>>(bk, bv);
    cudaEventRecord(ev2, s2);

    // main: x conversion + stats, then Q projection
    cvt_x_stats<<<NPART_, 256>>>(x);
    cudaStreamWaitEvent(0, evW, 0);
    stats_final<<<1, 256>>>(bq);
    gemm_wx<<<dim3(25, 2, B_), 256>>>(wqp, xbfp, cqp, 1, HW_, qp);

    cudaStreamWaitEvent(0, ev1, 0);
    cudaStreamWaitEvent(0, ev2, 0);

    attn_mma_kernel<<<dim3(B_, HEADS_, 25), 256, ATT_SMEM>>>(qp, kp, vp, bbfp, resp);

    gemm_o<<<dim3(25, 2, B_), 256>>>(resp, wop, bo, x, out);

    cudaEventDestroy(evRoot);
    cudaEventDestroy(evW);
    cudaEventDestroy(ev1);
    cudaEventDestroy(ev2);
    cudaStreamDestroy(s1);
    cudaStreamDestroy(s2);
}